// round 1
// baseline (speedup 1.0000x reference)
#include <cuda_runtime.h>
#include <math.h>

#define DEPTH 4
#define DIMN  768
#define HEADS 12
#define HD    64
#define CTX   2048
#define BATCH 4
#define MTOK  (BATCH*CTX)          // 8192
#define INNER (HEADS*HD)           // 768

// ---------------- scratch (device globals; no allocation) ----------------
__device__ float g_x  [MTOK*DIMN];
__device__ float g_h  [MTOK*DIMN];
__device__ float g_q  [MTOK*INNER];
__device__ float g_k  [MTOK*INNER];
__device__ float g_v  [MTOK*INNER];
__device__ float g_o  [MTOK*INNER];
__device__ float g_f  [MTOK*DIMN];
__device__ float g_s  [(long)BATCH*HEADS*CTX*CTX];   // 805 MB scores

// ---------------- x = x + pos_emb ----------------
__global__ void add_pos_kernel(const float* __restrict__ x,
                               const float* __restrict__ pos,
                               float* __restrict__ y)
{
    long i = (long)blockIdx.x * blockDim.x + threadIdx.x;     // 6291456 total
    long posn = i % ((long)CTX * DIMN);
    y[i] = x[i] + pos[posn];
}

// ---------------- LayerNorm over last dim (768), block per row ----------------
__global__ void layernorm_kernel(const float* __restrict__ x, float* __restrict__ y,
                                 const float* __restrict__ gamma,
                                 const float* __restrict__ beta)
{
    __shared__ float ss[8], qq[8];
    int row = blockIdx.x;
    int tid = threadIdx.x;                  // 256 threads, 3 elems each
    const float* xr = x + (long)row * DIMN;
    float v0 = xr[tid], v1 = xr[tid + 256], v2 = xr[tid + 512];
    float s = v0 + v1 + v2;
    float q = v0*v0 + v1*v1 + v2*v2;
    #pragma unroll
    for (int o = 16; o > 0; o >>= 1) {
        s += __shfl_xor_sync(0xffffffffu, s, o);
        q += __shfl_xor_sync(0xffffffffu, q, o);
    }
    int wid = tid >> 5, lane = tid & 31;
    if (lane == 0) { ss[wid] = s; qq[wid] = q; }
    __syncthreads();
    if (tid == 0) {
        float ts = 0.f, tq = 0.f;
        #pragma unroll
        for (int i = 0; i < 8; i++) { ts += ss[i]; tq += qq[i]; }
        ss[0] = ts; qq[0] = tq;
    }
    __syncthreads();
    float mean = ss[0] * (1.0f / DIMN);
    float var  = qq[0] * (1.0f / DIMN) - mean * mean;
    float inv  = rsqrtf(var + 1e-5f);
    float* yr = y + (long)row * DIMN;
    yr[tid      ] = (v0 - mean) * inv * gamma[tid      ] + beta[tid      ];
    yr[tid + 256] = (v1 - mean) * inv * gamma[tid + 256] + beta[tid + 256];
    yr[tid + 512] = (v2 - mean) * inv * gamma[tid + 512] + beta[tid + 512];
}

// ---------------- row softmax over 2048, block per row ----------------
__global__ void softmax_kernel(float* __restrict__ s)
{
    __shared__ float red[8];
    long row = blockIdx.x;
    float* p = s + row * (long)CTX;
    int tid = threadIdx.x;
    float v[8];
    float m = -1e30f;
    #pragma unroll
    for (int i = 0; i < 8; i++) { v[i] = p[tid + 256*i]; m = fmaxf(m, v[i]); }
    #pragma unroll
    for (int o = 16; o > 0; o >>= 1) m = fmaxf(m, __shfl_xor_sync(0xffffffffu, m, o));
    int wid = tid >> 5, lane = tid & 31;
    if (lane == 0) red[wid] = m;
    __syncthreads();
    if (tid == 0) {
        float t = red[0];
        #pragma unroll
        for (int i = 1; i < 8; i++) t = fmaxf(t, red[i]);
        red[0] = t;
    }
    __syncthreads();
    m = red[0];
    __syncthreads();
    float sum = 0.f;
    #pragma unroll
    for (int i = 0; i < 8; i++) { v[i] = __expf(v[i] - m); sum += v[i]; }
    #pragma unroll
    for (int o = 16; o > 0; o >>= 1) sum += __shfl_xor_sync(0xffffffffu, sum, o);
    if (lane == 0) red[wid] = sum;
    __syncthreads();
    if (tid == 0) {
        float t = 0.f;
        #pragma unroll
        for (int i = 0; i < 8; i++) t += red[i];
        red[0] = t;
    }
    __syncthreads();
    float inv = 1.0f / red[0];
    #pragma unroll
    for (int i = 0; i < 8; i++) p[tid + 256*i] = v[i] * inv;
}

// ---------------- generic batched SGEMM ----------------
// C = alpha * A @ op(B) (+bias) (GELU) (+residual)
// A: [M,K] row-major stride lda. op(B): [K,N]; transB ? B[n*ldb+k] : B[k*ldb+n].
// batch index z: outer=z/batch2, inner=z%batch2; ptr += outer*s1 + inner*s2.
#define BM 128
#define BN 128
#define BK 8

__global__ void sgemm_kernel(const float* __restrict__ A, const float* __restrict__ Bm,
                             float* __restrict__ C,
                             int M, int N, int K, int lda, int ldb, int ldc,
                             long sA1, long sA2, long sB1, long sB2, long sC1, long sC2,
                             int batch2, float alpha,
                             const float* __restrict__ bias,
                             const float* __restrict__ residual,
                             int transB, int gelu)
{
    __shared__ float As[BK][BM];
    __shared__ float Bs[BK][BN];

    int z  = blockIdx.z;
    int zo = z / batch2, zi = z % batch2;
    A  += zo * sA1 + zi * sA2;
    Bm += zo * sB1 + zi * sB2;
    C  += zo * sC1 + zi * sC2;
    if (residual) residual += zo * sC1 + zi * sC2;

    int tid = threadIdx.x;
    int m0 = blockIdx.y * BM;
    int n0 = blockIdx.x * BN;
    int tx = tid & 15, ty = tid >> 4;

    float acc[8][8];
    #pragma unroll
    for (int i = 0; i < 8; i++)
        #pragma unroll
        for (int j = 0; j < 8; j++) acc[i][j] = 0.f;

    int a_m = tid >> 1;            // 0..127
    int a_k = (tid & 1) * 4;       // 0 or 4

    for (int k0 = 0; k0 < K; k0 += BK) {
        // --- load A tile (transposed into As[k][m]); K always multiple of 8 here
        {
            float4 va = make_float4(0.f,0.f,0.f,0.f);
            int gm = m0 + a_m;
            if (gm < M) va = *(const float4*)(A + (long)gm * lda + k0 + a_k);
            As[a_k+0][a_m] = va.x; As[a_k+1][a_m] = va.y;
            As[a_k+2][a_m] = va.z; As[a_k+3][a_m] = va.w;
        }
        // --- load B tile
        if (!transB) {
            int r = tid >> 5;              // 0..7
            int c = (tid & 31) * 4;        // 0..124
            int gn = n0 + c;
            float4 vb = make_float4(0.f,0.f,0.f,0.f);
            const float* p = Bm + (long)(k0 + r) * ldb + gn;
            if (gn + 3 < N) vb = *(const float4*)p;
            else {
                if (gn + 0 < N) vb.x = p[0];
                if (gn + 1 < N) vb.y = p[1];
                if (gn + 2 < N) vb.z = p[2];
                if (gn + 3 < N) vb.w = p[3];
            }
            Bs[r][c+0] = vb.x; Bs[r][c+1] = vb.y; Bs[r][c+2] = vb.z; Bs[r][c+3] = vb.w;
        } else {
            int n  = tid >> 1;             // 0..127
            int kq = (tid & 1) * 4;
            int gn = n0 + n;
            float4 vb = make_float4(0.f,0.f,0.f,0.f);
            if (gn < N) vb = *(const float4*)(Bm + (long)gn * ldb + k0 + kq);
            Bs[kq+0][n] = vb.x; Bs[kq+1][n] = vb.y; Bs[kq+2][n] = vb.z; Bs[kq+3][n] = vb.w;
        }
        __syncthreads();

        #pragma unroll
        for (int kk = 0; kk < BK; kk++) {
            float a[8], b[8];
            float4 a0 = *(const float4*)&As[kk][ty*8];
            float4 a1 = *(const float4*)&As[kk][ty*8+4];
            float4 b0 = *(const float4*)&Bs[kk][tx*8];
            float4 b1 = *(const float4*)&Bs[kk][tx*8+4];
            a[0]=a0.x;a[1]=a0.y;a[2]=a0.z;a[3]=a0.w;a[4]=a1.x;a[5]=a1.y;a[6]=a1.z;a[7]=a1.w;
            b[0]=b0.x;b[1]=b0.y;b[2]=b0.z;b[3]=b0.w;b[4]=b1.x;b[5]=b1.y;b[6]=b1.z;b[7]=b1.w;
            #pragma unroll
            for (int i = 0; i < 8; i++)
                #pragma unroll
                for (int j = 0; j < 8; j++)
                    acc[i][j] = fmaf(a[i], b[j], acc[i][j]);
        }
        __syncthreads();
    }

    // --- epilogue
    int rbase = m0 + ty * 8;
    int cbase = n0 + tx * 8;
    #pragma unroll
    for (int i = 0; i < 8; i++) {
        int r = rbase + i;
        if (r >= M) break;
        #pragma unroll
        for (int j = 0; j < 8; j++) {
            int c = cbase + j;
            if (c >= N) continue;
            float val = acc[i][j] * alpha;
            if (bias) val += bias[c];
            if (gelu) val = 0.5f * val * (1.0f + erff(val * 0.70710678118654752f));
            if (residual) val += residual[(long)r * ldc + c];
            C[(long)r * ldc + c] = val;
        }
    }
}

// ---------------- host-side launch helpers ----------------
static void launch_gemm(const float* A, const float* B, float* C,
                        int M, int N, int K, int lda, int ldb, int ldc,
                        long sA1, long sA2, long sB1, long sB2, long sC1, long sC2,
                        int batch2, int nbatch, float alpha,
                        const float* bias, const float* residual,
                        int transB, int gelu)
{
    dim3 grid((N + BN - 1) / BN, (M + BM - 1) / BM, nbatch);
    sgemm_kernel<<<grid, 256>>>(A, B, C, M, N, K, lda, ldb, ldc,
                                sA1, sA2, sB1, sB2, sC1, sC2,
                                batch2, alpha, bias, residual, transB, gelu);
}

extern "C" void kernel_launch(void* const* d_in, const int* in_sizes, int n_in,
                              void* d_out, int out_size)
{
    const float* x     = (const float*)d_in[0];
    const float* pos   = (const float*)d_in[1];
    const float* ln1_g = (const float*)d_in[2];
    const float* ln1_b = (const float*)d_in[3];
    const float* Wq    = (const float*)d_in[4];
    const float* Wk    = (const float*)d_in[5];
    const float* Wv    = (const float*)d_in[6];
    const float* Wo    = (const float*)d_in[7];
    const float* ln2_g = (const float*)d_in[8];
    const float* ln2_b = (const float*)d_in[9];
    const float* W1    = (const float*)d_in[10];
    const float* b1    = (const float*)d_in[11];
    const float* W2    = (const float*)d_in[12];
    const float* b2    = (const float*)d_in[13];

    float *gx, *gh, *gq, *gk, *gv, *go, *gf, *gs;
    cudaGetSymbolAddress((void**)&gx, g_x);
    cudaGetSymbolAddress((void**)&gh, g_h);
    cudaGetSymbolAddress((void**)&gq, g_q);
    cudaGetSymbolAddress((void**)&gk, g_k);
    cudaGetSymbolAddress((void**)&gv, g_v);
    cudaGetSymbolAddress((void**)&go, g_o);
    cudaGetSymbolAddress((void**)&gf, g_f);
    cudaGetSymbolAddress((void**)&gs, g_s);

    const long WSZ = (long)DIMN * DIMN;        // per-layer weight size (all are 768x768)
    const float scale = 0.125f;                // 1/sqrt(64)

    // x = x + pos_emb
    add_pos_kernel<<<(MTOK * DIMN) / 256, 256>>>(x, pos, gx);

    for (int l = 0; l < DEPTH; l++) {
        const float* wq = Wq + (long)l * WSZ;
        const float* wk = Wk + (long)l * WSZ;
        const float* wv = Wv + (long)l * WSZ;
        const float* wo = Wo + (long)l * WSZ;
        const float* w1 = W1 + (long)l * WSZ;
        const float* w2 = W2 + (long)l * WSZ;
        const float* l1g = ln1_g + l * DIMN, *l1b = ln1_b + l * DIMN;
        const float* l2g = ln2_g + l * DIMN, *l2b = ln2_b + l * DIMN;
        const float* bb1 = b1 + l * DIMN,   *bb2 = b2 + l * DIMN;

        // --- attention block
        layernorm_kernel<<<MTOK, 256>>>(gx, gh, l1g, l1b);

        launch_gemm(gh, wq, gq, MTOK, INNER, DIMN, DIMN, INNER, INNER,
                    0,0,0,0,0,0, 1, 1, 1.0f, nullptr, nullptr, 0, 0);
        launch_gemm(gh, wk, gk, MTOK, INNER, DIMN, DIMN, INNER, INNER,
                    0,0,0,0,0,0, 1, 1, 1.0f, nullptr, nullptr, 0, 0);
        launch_gemm(gh, wv, gv, MTOK, INNER, DIMN, DIMN, INNER, INNER,
                    0,0,0,0,0,0, 1, 1, 1.0f, nullptr, nullptr, 0, 0);

        // S[b,h] = scale * Q_bh @ K_bh^T   (48 batches of 2048x2048x64)
        launch_gemm(gq, gk, gs, CTX, CTX, HD, INNER, INNER, CTX,
                    (long)CTX*INNER, HD, (long)CTX*INNER, HD,
                    (long)HEADS*CTX*CTX, (long)CTX*CTX,
                    HEADS, BATCH*HEADS, scale, nullptr, nullptr, 1, 0);

        softmax_kernel<<<BATCH*HEADS*CTX, 256>>>(gs);

        // O[b,h] = P_bh @ V_bh   (48 batches of 2048x64x2048)
        launch_gemm(gs, gv, go, CTX, HD, CTX, CTX, INNER, INNER,
                    (long)HEADS*CTX*CTX, (long)CTX*CTX,
                    (long)CTX*INNER, HD, (long)CTX*INNER, HD,
                    HEADS, BATCH*HEADS, 1.0f, nullptr, nullptr, 0, 0);

        // x = x + O @ Wo
        launch_gemm(go, wo, gx, MTOK, DIMN, INNER, INNER, DIMN, DIMN,
                    0,0,0,0,0,0, 1, 1, 1.0f, nullptr, gx, 0, 0);

        // --- FFN block
        layernorm_kernel<<<MTOK, 256>>>(gx, gh, l2g, l2b);

        launch_gemm(gh, w1, gf, MTOK, DIMN, DIMN, DIMN, DIMN, DIMN,
                    0,0,0,0,0,0, 1, 1, 1.0f, bb1, nullptr, 0, 1);

        float* cout = (l == DEPTH - 1) ? (float*)d_out : gx;
        launch_gemm(gf, w2, cout, MTOK, DIMN, DIMN, DIMN, DIMN, DIMN,
                    0,0,0,0,0,0, 1, 1, 1.0f, bb2, gx, 0, 0);
    }
}

// round 2
// speedup vs baseline: 1.5916x; 1.5916x over previous
#include <cuda_runtime.h>
#include <math.h>

#define DEPTH 4
#define DIMN  768
#define HEADS 12
#define HD    64
#define CTX   2048
#define BATCH 4
#define MTOK  (BATCH*CTX)          // 8192
#define INNER (HEADS*HD)           // 768
#define BK 8
#define BM 128

// ---------------- scratch (device globals; no allocation) ----------------
__device__ float g_x  [MTOK*DIMN];
__device__ float g_h  [MTOK*DIMN];
__device__ float g_qkv[3L*MTOK*INNER];
__device__ float g_o  [MTOK*INNER];
__device__ float g_f  [MTOK*DIMN];
__device__ float g_s  [(long)BATCH*HEADS*CTX*CTX];   // 805 MB scores

// ---------------- x = x + pos_emb ----------------
__global__ void add_pos_kernel(const float* __restrict__ x,
                               const float* __restrict__ pos,
                               float* __restrict__ y)
{
    long i = (long)blockIdx.x * blockDim.x + threadIdx.x;
    long posn = i % ((long)CTX * DIMN);
    y[i] = x[i] + pos[posn];
}

// ---------------- LayerNorm over last dim (768), block per row ----------------
__global__ void layernorm_kernel(const float* __restrict__ x, float* __restrict__ y,
                                 const float* __restrict__ gamma,
                                 const float* __restrict__ beta)
{
    __shared__ float ss[8], qq[8];
    int row = blockIdx.x;
    int tid = threadIdx.x;                  // 256 threads, 3 elems each
    const float* xr = x + (long)row * DIMN;
    float v0 = xr[tid], v1 = xr[tid + 256], v2 = xr[tid + 512];
    float s = v0 + v1 + v2;
    float q = v0*v0 + v1*v1 + v2*v2;
    #pragma unroll
    for (int o = 16; o > 0; o >>= 1) {
        s += __shfl_xor_sync(0xffffffffu, s, o);
        q += __shfl_xor_sync(0xffffffffu, q, o);
    }
    int wid = tid >> 5, lane = tid & 31;
    if (lane == 0) { ss[wid] = s; qq[wid] = q; }
    __syncthreads();
    if (tid == 0) {
        float ts = 0.f, tq = 0.f;
        #pragma unroll
        for (int i = 0; i < 8; i++) { ts += ss[i]; tq += qq[i]; }
        ss[0] = ts; qq[0] = tq;
    }
    __syncthreads();
    float mean = ss[0] * (1.0f / DIMN);
    float var  = qq[0] * (1.0f / DIMN) - mean * mean;
    float inv  = rsqrtf(var + 1e-5f);
    float* yr = y + (long)row * DIMN;
    yr[tid      ] = (v0 - mean) * inv * gamma[tid      ] + beta[tid      ];
    yr[tid + 256] = (v1 - mean) * inv * gamma[tid + 256] + beta[tid + 256];
    yr[tid + 512] = (v2 - mean) * inv * gamma[tid + 512] + beta[tid + 512];
}

// ---------------- row softmax over 2048, block per row ----------------
__global__ void softmax_kernel(float* __restrict__ s)
{
    __shared__ float red[8];
    long row = blockIdx.x;
    float* p = s + row * (long)CTX;
    int tid = threadIdx.x;
    float v[8];
    float m = -1e30f;
    #pragma unroll
    for (int i = 0; i < 8; i++) { v[i] = p[tid + 256*i]; m = fmaxf(m, v[i]); }
    #pragma unroll
    for (int o = 16; o > 0; o >>= 1) m = fmaxf(m, __shfl_xor_sync(0xffffffffu, m, o));
    int wid = tid >> 5, lane = tid & 31;
    if (lane == 0) red[wid] = m;
    __syncthreads();
    if (tid == 0) {
        float t = red[0];
        #pragma unroll
        for (int i = 1; i < 8; i++) t = fmaxf(t, red[i]);
        red[0] = t;
    }
    __syncthreads();
    m = red[0];
    __syncthreads();
    float sum = 0.f;
    #pragma unroll
    for (int i = 0; i < 8; i++) { v[i] = __expf(v[i] - m); sum += v[i]; }
    #pragma unroll
    for (int o = 16; o > 0; o >>= 1) sum += __shfl_xor_sync(0xffffffffu, sum, o);
    if (lane == 0) red[wid] = sum;
    __syncthreads();
    if (tid == 0) {
        float t = 0.f;
        #pragma unroll
        for (int i = 0; i < 8; i++) t += red[i];
        red[0] = t;
    }
    __syncthreads();
    float inv = 1.0f / red[0];
    #pragma unroll
    for (int i = 0; i < 8; i++) p[tid + 256*i] = v[i] * inv;
}

// ---------------- templated double-buffered batched SGEMM ----------------
// C = alpha * A @ op(B) (+bias) (GELU) (+residual)
// All of M, N, K are multiples of the tile dims here -> no bounds checks.
// z batch: zo=z/batch2, zi=z%batch2; B pointer optionally selected by zo
// (B1/B2 non-null) for the fused-QKV launch.
template<int BN_, int TN_, bool TRANSB, bool GELU_, bool HASBIAS, bool HASRES>
__global__ void __launch_bounds__(256, 2)
gemm_t(const float* __restrict__ A, const float* __restrict__ B0,
       const float* __restrict__ B1, const float* __restrict__ B2,
       float* __restrict__ C,
       const float* __restrict__ bias, const float* __restrict__ residual,
       int K, int lda, int ldb, int ldc,
       long sA1, long sA2, long sB1, long sB2, long sC1, long sC2,
       int batch2, float alpha)
{
    __shared__ __align__(16) float As[2][BK][BM + 4];
    __shared__ __align__(16) float Bs[2][BK][BN_ + 4];

    const int z  = blockIdx.z;
    const int zo = z / batch2, zi = z - zo * batch2;
    const float* Bm = B0;
    if (B1 != nullptr && zo == 1) Bm = B1;
    if (B2 != nullptr && zo == 2) Bm = B2;
    A  += zo * sA1 + zi * sA2;
    Bm += zo * sB1 + zi * sB2;
    const long coff = zo * sC1 + zi * sC2;

    const int tid = threadIdx.x;
    const int m0 = blockIdx.y * BM;
    const int n0 = blockIdx.x * BN_;
    const int tx = tid & 15, ty = tid >> 4;

    // A fetch: 128x8 tile, one float4 per thread
    const int am = tid >> 1;               // 0..127
    const int ak = (tid & 1) * 4;          // 0 or 4
    const float* pA = A + (long)(m0 + am) * lda + ak;

    // B fetch
    const float* pB;
    int bn = 0, br = 0, bc = 0;
    if (TRANSB) {
        bn = tid >> 1;                     // 0..127 (BN_=128 only)
        pB = Bm + (long)(n0 + bn) * ldb + ak;
    } else {
        br = tid >> 5;                     // 0..7
        bc = (tid & 31) * (BN_ / 32);      // *4 (BN=128) or *2 (BN=64)
        pB = Bm + (long)br * ldb + n0 + bc;
    }

    float acc[8][TN_];
    #pragma unroll
    for (int i = 0; i < 8; i++)
        #pragma unroll
        for (int j = 0; j < TN_; j++) acc[i][j] = 0.f;

    float4 ra, rb;
    float2 rb2;

    // prologue: fetch + stash tile 0
    ra = *(const float4*)pA;
    if (TRANSB || BN_ == 128) rb = *(const float4*)pB;
    else                      rb2 = *(const float2*)pB;

    As[0][ak+0][am] = ra.x; As[0][ak+1][am] = ra.y;
    As[0][ak+2][am] = ra.z; As[0][ak+3][am] = ra.w;
    if (TRANSB) {
        Bs[0][ak+0][bn] = rb.x; Bs[0][ak+1][bn] = rb.y;
        Bs[0][ak+2][bn] = rb.z; Bs[0][ak+3][bn] = rb.w;
    } else if (BN_ == 128) {
        *(float4*)&Bs[0][br][bc] = rb;
    } else {
        *(float2*)&Bs[0][br][bc] = rb2;
    }
    __syncthreads();

    int buf = 0;
    for (int k0 = BK; k0 <= K; k0 += BK) {
        const bool more = (k0 < K);
        if (more) {
            ra = *(const float4*)(pA + k0);
            if (TRANSB)            rb = *(const float4*)(pB + k0);
            else if (BN_ == 128)   rb = *(const float4*)(pB + (long)k0 * ldb);
            else                   rb2 = *(const float2*)(pB + (long)k0 * ldb);
        }
        #pragma unroll
        for (int kk = 0; kk < BK; kk++) {
            float4 a0 = *(const float4*)&As[buf][kk][ty*8];
            float4 a1 = *(const float4*)&As[buf][kk][ty*8 + 4];
            float a[8] = {a0.x,a0.y,a0.z,a0.w,a1.x,a1.y,a1.z,a1.w};
            float b[TN_];
            if (TN_ == 8) {
                float4 b0 = *(const float4*)&Bs[buf][kk][tx*8];
                float4 b1 = *(const float4*)&Bs[buf][kk][tx*8 + 4];
                b[0]=b0.x;b[1]=b0.y;b[2]=b0.z;b[3]=b0.w;
                b[4]=b1.x;b[5]=b1.y;b[6]=b1.z;b[7]=b1.w;
            } else {
                float4 b0 = *(const float4*)&Bs[buf][kk][tx*4];
                b[0]=b0.x;b[1]=b0.y;b[2]=b0.z;b[3]=b0.w;
            }
            #pragma unroll
            for (int i = 0; i < 8; i++)
                #pragma unroll
                for (int j = 0; j < TN_; j++)
                    acc[i][j] = fmaf(a[i], b[j], acc[i][j]);
        }
        if (more) {
            const int nb = buf ^ 1;
            As[nb][ak+0][am] = ra.x; As[nb][ak+1][am] = ra.y;
            As[nb][ak+2][am] = ra.z; As[nb][ak+3][am] = ra.w;
            if (TRANSB) {
                Bs[nb][ak+0][bn] = rb.x; Bs[nb][ak+1][bn] = rb.y;
                Bs[nb][ak+2][bn] = rb.z; Bs[nb][ak+3][bn] = rb.w;
            } else if (BN_ == 128) {
                *(float4*)&Bs[nb][br][bc] = rb;
            } else {
                *(float2*)&Bs[nb][br][bc] = rb2;
            }
            __syncthreads();
            buf = nb;
        }
    }

    // epilogue
    float* Cp = C + coff;
    const float* Rp = HASRES ? residual + coff : nullptr;
    #pragma unroll
    for (int i = 0; i < 8; i++) {
        long r = m0 + ty*8 + i;
        #pragma unroll
        for (int j = 0; j < TN_; j++) {
            int c = n0 + tx*TN_ + j;
            float v = acc[i][j] * alpha;
            if (HASBIAS) v += bias[c];
            if (GELU_)  v = 0.5f * v * (1.0f + erff(v * 0.70710678118654752f));
            if (HASRES) v += Rp[r * ldc + c];
            Cp[r * ldc + c] = v;
        }
    }
}

template<int BN_, int TN_, bool TRANSB, bool GELU_, bool HASBIAS, bool HASRES>
static void launch(const float* A, const float* B0, const float* B1, const float* B2,
                   float* C, const float* bias, const float* res,
                   int M, int N, int K, int lda, int ldb, int ldc,
                   long sA1, long sA2, long sB1, long sB2, long sC1, long sC2,
                   int batch2, int nz, float alpha)
{
    dim3 grid(N / BN_, M / BM, nz);
    gemm_t<BN_, TN_, TRANSB, GELU_, HASBIAS, HASRES><<<grid, 256>>>(
        A, B0, B1, B2, C, bias, res, K, lda, ldb, ldc,
        sA1, sA2, sB1, sB2, sC1, sC2, batch2, alpha);
}

extern "C" void kernel_launch(void* const* d_in, const int* in_sizes, int n_in,
                              void* d_out, int out_size)
{
    const float* x     = (const float*)d_in[0];
    const float* pos   = (const float*)d_in[1];
    const float* ln1_g = (const float*)d_in[2];
    const float* ln1_b = (const float*)d_in[3];
    const float* Wq    = (const float*)d_in[4];
    const float* Wk    = (const float*)d_in[5];
    const float* Wv    = (const float*)d_in[6];
    const float* Wo    = (const float*)d_in[7];
    const float* ln2_g = (const float*)d_in[8];
    const float* ln2_b = (const float*)d_in[9];
    const float* W1    = (const float*)d_in[10];
    const float* b1    = (const float*)d_in[11];
    const float* W2    = (const float*)d_in[12];
    const float* b2    = (const float*)d_in[13];

    float *gx, *gh, *gqkv, *go, *gf, *gs;
    cudaGetSymbolAddress((void**)&gx,  g_x);
    cudaGetSymbolAddress((void**)&gh,  g_h);
    cudaGetSymbolAddress((void**)&gqkv,g_qkv);
    cudaGetSymbolAddress((void**)&go,  g_o);
    cudaGetSymbolAddress((void**)&gf,  g_f);
    cudaGetSymbolAddress((void**)&gs,  g_s);

    const long WSZ = (long)DIMN * DIMN;
    const float scale = 0.125f;              // 1/sqrt(64)
    float* gq = gqkv;
    float* gk = gqkv + (long)MTOK * INNER;
    float* gv = gqkv + 2L * MTOK * INNER;

    add_pos_kernel<<<(MTOK * DIMN) / 256, 256>>>(x, pos, gx);

    for (int l = 0; l < DEPTH; l++) {
        const float* wq = Wq + (long)l * WSZ;
        const float* wk = Wk + (long)l * WSZ;
        const float* wv = Wv + (long)l * WSZ;
        const float* wo = Wo + (long)l * WSZ;
        const float* w1 = W1 + (long)l * WSZ;
        const float* w2 = W2 + (long)l * WSZ;
        const float* l1g = ln1_g + l * DIMN, *l1b = ln1_b + l * DIMN;
        const float* l2g = ln2_g + l * DIMN, *l2b = ln2_b + l * DIMN;
        const float* bb1 = b1 + l * DIMN,   *bb2 = b2 + l * DIMN;

        // --- attention block
        layernorm_kernel<<<MTOK, 256>>>(gx, gh, l1g, l1b);

        // fused QKV: one launch, grid.z = 3 (B pointer selected by zo)
        launch<128, 8, false, false, false, false>(
            gh, wq, wk, wv, gqkv, nullptr, nullptr,
            MTOK, INNER, DIMN, DIMN, INNER, INNER,
            0, 0, 0, 0, (long)MTOK * INNER, 0, 1, 3, 1.0f);

        // S[b,h] = scale * Q_bh @ K_bh^T  (48 x [2048,2048,64])
        launch<128, 8, true, false, false, false>(
            gq, gk, nullptr, nullptr, gs, nullptr, nullptr,
            CTX, CTX, HD, INNER, INNER, CTX,
            (long)CTX * INNER, HD, (long)CTX * INNER, HD,
            (long)HEADS * CTX * CTX, (long)CTX * CTX,
            HEADS, BATCH * HEADS, scale);

        softmax_kernel<<<BATCH * HEADS * CTX, 256>>>(gs);

        // O[b,h] = P_bh @ V_bh  (48 x [2048,64,2048])
        launch<64, 4, false, false, false, false>(
            gs, gv, nullptr, nullptr, go, nullptr, nullptr,
            CTX, HD, CTX, CTX, INNER, INNER,
            (long)HEADS * CTX * CTX, (long)CTX * CTX,
            (long)CTX * INNER, HD,
            (long)CTX * INNER, HD,
            HEADS, BATCH * HEADS, 1.0f);

        // x = x + O @ Wo
        launch<64, 4, false, false, false, true>(
            go, wo, nullptr, nullptr, gx, nullptr, gx,
            MTOK, DIMN, INNER, INNER, DIMN, DIMN,
            0, 0, 0, 0, 0, 0, 1, 1, 1.0f);

        // --- FFN block
        layernorm_kernel<<<MTOK, 256>>>(gx, gh, l2g, l2b);

        launch<64, 4, false, true, true, false>(
            gh, w1, nullptr, nullptr, gf, bb1, nullptr,
            MTOK, DIMN, DIMN, DIMN, DIMN, DIMN,
            0, 0, 0, 0, 0, 0, 1, 1, 1.0f);

        float* cout = (l == DEPTH - 1) ? (float*)d_out : gx;
        launch<64, 4, false, false, true, true>(
            gf, w2, nullptr, nullptr, cout, bb2, gx,
            MTOK, DIMN, DIMN, DIMN, DIMN, DIMN,
            0, 0, 0, 0, 0, 0, 1, 1, 1.0f);
    }
}

// round 4
// speedup vs baseline: 3.0090x; 1.8906x over previous
#include <cuda_runtime.h>
#include <math.h>
#include <stdint.h>

#define DEPTH 4
#define DIMN  768
#define HEADS 12
#define HD    64
#define CTX   2048
#define BATCH 4
#define MTOK  (BATCH*CTX)          // 8192
#define INNER (HEADS*HD)           // 768
#define WSZ   ((long)DIMN*DIMN)

// ---------------- scratch (device globals; no allocation) ----------------
__device__ __align__(128) float g_x  [MTOK*DIMN];
__device__ __align__(128) float g_h  [MTOK*DIMN];
__device__ __align__(128) float g_qkv[3L*MTOK*INNER];
__device__ __align__(128) float g_o  [MTOK*INNER];
__device__ __align__(128) float g_f  [MTOK*DIMN];
__device__ __align__(128) float g_vT [(long)BATCH*HEADS*HD*CTX];
__device__ __align__(128) float g_wT [24L*DIMN*DIMN];
__device__ __align__(128) float g_s  [(long)BATCH*HEADS*CTX*CTX];

__device__ __forceinline__ uint32_t cvt_tf32(float f) {
    uint32_t u; asm("cvt.rna.tf32.f32 %0, %1;" : "=r"(u) : "f"(f)); return u;
}
__device__ __forceinline__ void mma_tf32(float* c, const uint32_t* a, const uint32_t* b) {
    asm volatile(
        "mma.sync.aligned.m16n8k8.row.col.f32.tf32.tf32.f32 "
        "{%0,%1,%2,%3}, {%4,%5,%6,%7}, {%8,%9}, {%0,%1,%2,%3};"
        : "+f"(c[0]), "+f"(c[1]), "+f"(c[2]), "+f"(c[3])
        : "r"(a[0]), "r"(a[1]), "r"(a[2]), "r"(a[3]), "r"(b[0]), "r"(b[1]));
}

// ================= elementwise kernels =================
__global__ void add_pos_kernel(const float* __restrict__ x,
                               const float* __restrict__ pos,
                               float* __restrict__ y)
{
    long i = (long)blockIdx.x * blockDim.x + threadIdx.x;
    long posn = i % ((long)CTX * DIMN);
    y[i] = x[i] + pos[posn];
}

__global__ void layernorm_kernel(const float* __restrict__ x, float* __restrict__ y,
                                 const float* __restrict__ gamma,
                                 const float* __restrict__ beta)
{
    __shared__ float ss[8], qq[8];
    int row = blockIdx.x;
    int tid = threadIdx.x;
    const float* xr = x + (long)row * DIMN;
    float v0 = xr[tid], v1 = xr[tid + 256], v2 = xr[tid + 512];
    float s = v0 + v1 + v2;
    float q = v0*v0 + v1*v1 + v2*v2;
    #pragma unroll
    for (int o = 16; o > 0; o >>= 1) {
        s += __shfl_xor_sync(0xffffffffu, s, o);
        q += __shfl_xor_sync(0xffffffffu, q, o);
    }
    int wid = tid >> 5, lane = tid & 31;
    if (lane == 0) { ss[wid] = s; qq[wid] = q; }
    __syncthreads();
    if (tid == 0) {
        float ts = 0.f, tq = 0.f;
        #pragma unroll
        for (int i = 0; i < 8; i++) { ts += ss[i]; tq += qq[i]; }
        ss[0] = ts; qq[0] = tq;
    }
    __syncthreads();
    float mean = ss[0] * (1.0f / DIMN);
    float var  = qq[0] * (1.0f / DIMN) - mean * mean;
    float inv  = rsqrtf(var + 1e-5f);
    float* yr = y + (long)row * DIMN;
    yr[tid      ] = (v0 - mean) * inv * gamma[tid      ] + beta[tid      ];
    yr[tid + 256] = (v1 - mean) * inv * gamma[tid + 256] + beta[tid + 256];
    yr[tid + 512] = (v2 - mean) * inv * gamma[tid + 512] + beta[tid + 512];
}

__global__ void softmax_kernel(float* __restrict__ s)
{
    __shared__ float red[8];
    long row = blockIdx.x;
    float* p = s + row * (long)CTX;
    int tid = threadIdx.x;
    float v[8];
    float m = -1e30f;
    #pragma unroll
    for (int i = 0; i < 8; i++) { v[i] = p[tid + 256*i]; m = fmaxf(m, v[i]); }
    #pragma unroll
    for (int o = 16; o > 0; o >>= 1) m = fmaxf(m, __shfl_xor_sync(0xffffffffu, m, o));
    int wid = tid >> 5, lane = tid & 31;
    if (lane == 0) red[wid] = m;
    __syncthreads();
    if (tid == 0) {
        float t = red[0];
        #pragma unroll
        for (int i = 1; i < 8; i++) t = fmaxf(t, red[i]);
        red[0] = t;
    }
    __syncthreads();
    m = red[0];
    __syncthreads();
    float sum = 0.f;
    #pragma unroll
    for (int i = 0; i < 8; i++) { v[i] = __expf(v[i] - m); sum += v[i]; }
    #pragma unroll
    for (int o = 16; o > 0; o >>= 1) sum += __shfl_xor_sync(0xffffffffu, sum, o);
    if (lane == 0) red[wid] = sum;
    __syncthreads();
    if (tid == 0) {
        float t = 0.f;
        #pragma unroll
        for (int i = 0; i < 8; i++) t += red[i];
        red[0] = t;
    }
    __syncthreads();
    float inv = 1.0f / red[0];
    #pragma unroll
    for (int i = 0; i < 8; i++) p[tid + 256*i] = v[i] * inv;
}

// transpose all 24 weight matrices (768x768) into g_wT; z = l*6 + w
__global__ void transpose_w(const float* __restrict__ Wq, const float* __restrict__ Wk,
                            const float* __restrict__ Wv, const float* __restrict__ Wo,
                            const float* __restrict__ W1, const float* __restrict__ W2,
                            float* __restrict__ dst)
{
    __shared__ float t[32][33];
    int z = blockIdx.z;
    int l = z / 6, w = z - l * 6;
    const float* srcs[6] = {Wq, Wk, Wv, Wo, W1, W2};
    const float* src = srcs[w] + (long)l * WSZ;
    float* d = dst + (long)z * WSZ;
    int tx = threadIdx.x, ty = threadIdx.y;
    int x = blockIdx.x * 32 + tx;
    int y = blockIdx.y * 32 + ty;
    #pragma unroll
    for (int i = 0; i < 4; i++)
        t[ty + 8*i][tx] = src[(long)(y + 8*i) * DIMN + x];
    __syncthreads();
    int x2 = blockIdx.y * 32 + tx;
    int y2 = blockIdx.x * 32 + ty;
    #pragma unroll
    for (int i = 0; i < 4; i++)
        d[(long)(y2 + 8*i) * DIMN + x2] = t[tx][ty + 8*i];
}

// vT[(b*H+h)*HD+d][t] = v[(b*CTX+t)][h*HD+d]
__global__ void transpose_v(const float* __restrict__ v, float* __restrict__ vT)
{
    __shared__ float t[32][33];
    int bh = blockIdx.z;
    int b = bh / HEADS, h = bh - b * HEADS;
    int tx = threadIdx.x, ty = threadIdx.y;
    int t0 = blockIdx.x * 32;
    int d0 = blockIdx.y * 32;
    #pragma unroll
    for (int i = 0; i < 4; i++)
        t[ty + 8*i][tx] = v[(long)(b * CTX + t0 + ty + 8*i) * INNER + h * HD + d0 + tx];
    __syncthreads();
    #pragma unroll
    for (int i = 0; i < 4; i++)
        vT[((long)bh * HD + d0 + ty + 8*i) * CTX + t0 + tx] = t[tx][ty + 8*i];
}

// ================= tf32 mma.sync batched GEMM =================
// D[128 x BN_] = alpha * A(128xK row-major) @ B(BN_ x K, K-major)^T (+bias)(GELU)(+res)
// 256 threads = 8 warps as WROWS x (8/WROWS); warp tile (MT*16) x (NT*8).
#define BK 16
#define BM 128

template<int BN_, int WROWS, bool GELU_, bool HASBIAS, bool HASRES>
__global__ void __launch_bounds__(256, 2)
mma_gemm(const float* __restrict__ A, const float* __restrict__ B,
         float* __restrict__ C, const float* __restrict__ bias,
         const float* __restrict__ residual,
         int K, int lda, int ldb, int ldc,
         long sA1, long sA2, long sB1, long sB2, long sC1, long sC2,
         int batch2, float alpha)
{
    constexpr int WCOLS = 8 / WROWS;
    constexpr int MT = (BM / WROWS) / 16;
    constexpr int NT = (BN_ / WCOLS) / 8;
    constexpr int SEGA = BM * BK / 4 / 256;   // float4 loads per thread for A
    constexpr int SEGB = BN_ * BK / 4 / 256;  // for B
    constexpr int PAD = 4;

    __shared__ uint32_t As[2][BK][BM + PAD];
    __shared__ uint32_t Bs[2][BK][BN_ + PAD];

    const int z  = blockIdx.z;
    const int zo = z / batch2, zi = z - zo * batch2;
    A += zo * sA1 + zi * sA2;
    B += zo * sB1 + zi * sB2;
    const long coff = (long)zo * sC1 + (long)zi * sC2;

    const int tid  = threadIdx.x;
    const int wid  = tid >> 5;
    const int lane = tid & 31;
    const int g    = lane >> 2;       // 0..7
    const int tg   = lane & 3;        // 0..3
    const int wm   = wid % WROWS;
    const int wn   = wid / WROWS;
    const int mwo  = wm * MT * 16;
    const int nwo  = wn * NT * 8;

    const int m0 = blockIdx.y * BM;
    const int n0 = blockIdx.x * BN_;

    // loader mapping
    const float* ap[SEGA]; int arow[SEGA], acol[SEGA];
    #pragma unroll
    for (int i = 0; i < SEGA; i++) {
        int seg = tid + 256 * i;          // 0..BM*BK/4-1
        arow[i] = seg >> 2;               // 0..127
        acol[i] = (seg & 3) * 4;          // 0,4,8,12
        ap[i] = A + (long)(m0 + arow[i]) * lda + acol[i];
    }
    const float* bp[SEGB]; int brow[SEGB], bcol[SEGB];
    #pragma unroll
    for (int i = 0; i < SEGB; i++) {
        int seg = tid + 256 * i;
        brow[i] = seg / (BK / 4);
        bcol[i] = (seg % (BK / 4)) * 4;
        bp[i] = B + (long)(n0 + brow[i]) * ldb + bcol[i];
    }

    float acc[MT][NT][4];
    #pragma unroll
    for (int i = 0; i < MT; i++)
        #pragma unroll
        for (int j = 0; j < NT; j++)
            #pragma unroll
            for (int k = 0; k < 4; k++) acc[i][j][k] = 0.f;

    float4 ra[SEGA], rb[SEGB];

#define STS_TILE(BUFV)                                                     \
    {                                                                      \
        _Pragma("unroll")                                                  \
        for (int i = 0; i < SEGA; i++) {                                   \
            As[BUFV][acol[i]+0][arow[i]] = cvt_tf32(ra[i].x);              \
            As[BUFV][acol[i]+1][arow[i]] = cvt_tf32(ra[i].y);              \
            As[BUFV][acol[i]+2][arow[i]] = cvt_tf32(ra[i].z);              \
            As[BUFV][acol[i]+3][arow[i]] = cvt_tf32(ra[i].w);              \
        }                                                                  \
        _Pragma("unroll")                                                  \
        for (int i = 0; i < SEGB; i++) {                                   \
            Bs[BUFV][bcol[i]+0][brow[i]] = cvt_tf32(rb[i].x);              \
            Bs[BUFV][bcol[i]+1][brow[i]] = cvt_tf32(rb[i].y);              \
            Bs[BUFV][bcol[i]+2][brow[i]] = cvt_tf32(rb[i].z);              \
            Bs[BUFV][bcol[i]+3][brow[i]] = cvt_tf32(rb[i].w);              \
        }                                                                  \
    }

    // prologue: tile 0
    #pragma unroll
    for (int i = 0; i < SEGA; i++) ra[i] = *(const float4*)(ap[i]);
    #pragma unroll
    for (int i = 0; i < SEGB; i++) rb[i] = *(const float4*)(bp[i]);
    STS_TILE(0);
    __syncthreads();

    const int ntiles = K / BK;
    int buf = 0;
    for (int s = 0; s < ntiles; s++) {
        if (s + 1 < ntiles) {
            const int koff = (s + 1) * BK;
            #pragma unroll
            for (int i = 0; i < SEGA; i++) ra[i] = *(const float4*)(ap[i] + koff);
            #pragma unroll
            for (int i = 0; i < SEGB; i++) rb[i] = *(const float4*)(bp[i] + koff);
        }
        #pragma unroll
        for (int kk = 0; kk < 2; kk++) {
            const int kb = kk * 8;
            uint32_t af[MT][4];
            #pragma unroll
            for (int mt = 0; mt < MT; mt++) {
                int m = mwo + mt * 16 + g;
                af[mt][0] = As[buf][kb + tg    ][m];
                af[mt][1] = As[buf][kb + tg    ][m + 8];
                af[mt][2] = As[buf][kb + tg + 4][m];
                af[mt][3] = As[buf][kb + tg + 4][m + 8];
            }
            uint32_t bf[NT][2];
            #pragma unroll
            for (int nt = 0; nt < NT; nt++) {
                int n = nwo + nt * 8 + g;
                bf[nt][0] = Bs[buf][kb + tg    ][n];
                bf[nt][1] = Bs[buf][kb + tg + 4][n];
            }
            #pragma unroll
            for (int mt = 0; mt < MT; mt++)
                #pragma unroll
                for (int nt = 0; nt < NT; nt++)
                    mma_tf32(acc[mt][nt], af[mt], bf[nt]);
        }
        if (s + 1 < ntiles) {
            __syncthreads();
            STS_TILE(buf ^ 1);
            __syncthreads();
            buf ^= 1;
        }
    }
#undef STS_TILE

    // epilogue
    float* Cp = C + coff;
    const float* Rp = HASRES ? residual + coff : nullptr;
    #pragma unroll
    for (int mt = 0; mt < MT; mt++) {
        const long r0 = m0 + mwo + mt * 16 + g;
        const long r1 = r0 + 8;
        #pragma unroll
        for (int nt = 0; nt < NT; nt++) {
            const int cb = n0 + nwo + nt * 8 + 2 * tg;
            float2 v0, v1;
            v0.x = acc[mt][nt][0] * alpha; v0.y = acc[mt][nt][1] * alpha;
            v1.x = acc[mt][nt][2] * alpha; v1.y = acc[mt][nt][3] * alpha;
            if (HASBIAS) {
                float bx = bias[cb], by = bias[cb + 1];
                v0.x += bx; v0.y += by; v1.x += bx; v1.y += by;
            }
            if (GELU_) {
                v0.x = 0.5f * v0.x * (1.0f + erff(v0.x * 0.70710678118654752f));
                v0.y = 0.5f * v0.y * (1.0f + erff(v0.y * 0.70710678118654752f));
                v1.x = 0.5f * v1.x * (1.0f + erff(v1.x * 0.70710678118654752f));
                v1.y = 0.5f * v1.y * (1.0f + erff(v1.y * 0.70710678118654752f));
            }
            if (HASRES) {
                float2 q0 = *(const float2*)(Rp + r0 * ldc + cb);
                float2 q1 = *(const float2*)(Rp + r1 * ldc + cb);
                v0.x += q0.x; v0.y += q0.y; v1.x += q1.x; v1.y += q1.y;
            }
            *(float2*)(Cp + r0 * ldc + cb) = v0;
            *(float2*)(Cp + r1 * ldc + cb) = v1;
        }
    }
}

// ================= host-side launch =================
template<int BN_, int WROWS, bool GELU_, bool HASBIAS, bool HASRES>
static void launch_mm(const float* A, const float* B, float* C,
                      const float* bias, const float* res,
                      int M, int N, int K, int lda, int ldb, int ldc,
                      long sA1, long sA2, long sB1, long sB2, long sC1, long sC2,
                      int batch2, int nz, float alpha)
{
    dim3 grid(N / BN_, M / BM, nz);
    mma_gemm<BN_, WROWS, GELU_, HASBIAS, HASRES><<<grid, 256>>>(
        A, B, C, bias, res, K, lda, ldb, ldc,
        sA1, sA2, sB1, sB2, sC1, sC2, batch2, alpha);
}

extern "C" void kernel_launch(void* const* d_in, const int* in_sizes, int n_in,
                              void* d_out, int out_size)
{
    const float* x     = (const float*)d_in[0];
    const float* pos   = (const float*)d_in[1];
    const float* ln1_g = (const float*)d_in[2];
    const float* ln1_b = (const float*)d_in[3];
    const float* Wq    = (const float*)d_in[4];
    const float* Wk    = (const float*)d_in[5];
    const float* Wv    = (const float*)d_in[6];
    const float* Wo    = (const float*)d_in[7];
    const float* ln2_g = (const float*)d_in[8];
    const float* ln2_b = (const float*)d_in[9];
    const float* W1    = (const float*)d_in[10];
    const float* b1    = (const float*)d_in[11];
    const float* W2    = (const float*)d_in[12];
    const float* b2    = (const float*)d_in[13];

    float *gx, *gh, *gqkv, *go, *gf, *gs, *gvT, *gwT;
    cudaGetSymbolAddress((void**)&gx,  g_x);
    cudaGetSymbolAddress((void**)&gh,  g_h);
    cudaGetSymbolAddress((void**)&gqkv,g_qkv);
    cudaGetSymbolAddress((void**)&go,  g_o);
    cudaGetSymbolAddress((void**)&gf,  g_f);
    cudaGetSymbolAddress((void**)&gs,  g_s);
    cudaGetSymbolAddress((void**)&gvT, g_vT);
    cudaGetSymbolAddress((void**)&gwT, g_wT);

    const float scale = 0.125f;
    float* gq = gqkv;
    float* gk = gqkv + (long)MTOK * INNER;
    float* gv = gqkv + 2L * MTOK * INNER;

    {
        dim3 grid(DIMN / 32, DIMN / 32, DEPTH * 6);
        transpose_w<<<grid, dim3(32, 8)>>>(Wq, Wk, Wv, Wo, W1, W2, gwT);
    }

    add_pos_kernel<<<(MTOK * DIMN) / 256, 256>>>(x, pos, gx);

    for (int l = 0; l < DEPTH; l++) {
        const float* wqT = gwT + (long)(l * 6 + 0) * WSZ;
        const float* woT = gwT + (long)(l * 6 + 3) * WSZ;
        const float* w1T = gwT + (long)(l * 6 + 4) * WSZ;
        const float* w2T = gwT + (long)(l * 6 + 5) * WSZ;
        const float* l1g = ln1_g + l * DIMN, *l1b = ln1_b + l * DIMN;
        const float* l2g = ln2_g + l * DIMN, *l2b = ln2_b + l * DIMN;
        const float* bb1 = b1 + l * DIMN,   *bb2 = b2 + l * DIMN;

        // --- attention
        layernorm_kernel<<<MTOK, 256>>>(gx, gh, l1g, l1b);

        // fused QKV: z selects wqT/wkT/wvT (contiguous in g_wT, stride WSZ)
        launch_mm<128, 2, false, false, false>(
            gh, wqT, gqkv, nullptr, nullptr,
            MTOK, INNER, DIMN, DIMN, DIMN, INNER,
            0, 0, WSZ, 0, (long)MTOK * INNER, 0, 1, 3, 1.0f);

        transpose_v<<<dim3(CTX / 32, HD / 32, BATCH * HEADS), dim3(32, 8)>>>(gv, gvT);

        // S = scale * Q @ K^T   (48 x [2048,2048,64])
        launch_mm<128, 2, false, false, false>(
            gq, gk, gs, nullptr, nullptr,
            CTX, CTX, HD, INNER, INNER, CTX,
            (long)CTX * INNER, HD, (long)CTX * INNER, HD,
            (long)HEADS * CTX * CTX, (long)CTX * CTX,
            HEADS, BATCH * HEADS, scale);

        softmax_kernel<<<BATCH * HEADS * CTX, 256>>>(gs);

        // O = P @ V^T   (B = vT, K-major [HD, CTX])
        launch_mm<64, 4, false, false, false>(
            gs, gvT, go, nullptr, nullptr,
            CTX, HD, CTX, CTX, CTX, INNER,
            (long)HEADS * CTX * CTX, (long)CTX * CTX,
            (long)HEADS * HD * CTX, (long)HD * CTX,
            (long)CTX * INNER, HD,
            HEADS, BATCH * HEADS, 1.0f);

        // x = x + O @ Wo
        launch_mm<128, 2, false, false, true>(
            go, woT, gx, nullptr, gx,
            MTOK, DIMN, INNER, INNER, INNER, DIMN,
            0, 0, 0, 0, 0, 0, 1, 1, 1.0f);

        // --- FFN
        layernorm_kernel<<<MTOK, 256>>>(gx, gh, l2g, l2b);

        launch_mm<128, 2, true, true, false>(
            gh, w1T, gf, bb1, nullptr,
            MTOK, DIMN, DIMN, DIMN, DIMN, DIMN,
            0, 0, 0, 0, 0, 0, 1, 1, 1.0f);

        float* cout = (l == DEPTH - 1) ? (float*)d_out : gx;
        launch_mm<128, 2, false, true, true>(
            gf, w2T, cout, bb2, gx,
            MTOK, DIMN, DIMN, DIMN, DIMN, DIMN,
            0, 0, 0, 0, 0, 0, 1, 1, 1.0f);
    }
}

// round 5
// speedup vs baseline: 3.8832x; 1.2905x over previous
#include <cuda_runtime.h>
#include <math.h>
#include <stdint.h>

#define DEPTH 4
#define DIMN  768
#define HEADS 12
#define HD    64
#define CTX   2048
#define BATCH 4
#define MTOK  (BATCH*CTX)          // 8192
#define INNER (HEADS*HD)           // 768
#define WSZ   ((long)DIMN*DIMN)

// ---------------- scratch (device globals; no allocation) ----------------
__device__ __align__(128) float g_x  [MTOK*DIMN];
__device__ __align__(128) float g_h  [MTOK*DIMN];
__device__ __align__(128) float g_qkv[3L*MTOK*INNER];
__device__ __align__(128) float g_o  [MTOK*INNER];
__device__ __align__(128) float g_f  [MTOK*DIMN];
__device__ __align__(128) float g_wT [24L*DIMN*DIMN];

__device__ __forceinline__ uint32_t cvt_tf32(float f) {
    uint32_t u; asm("cvt.rna.tf32.f32 %0, %1;" : "=r"(u) : "f"(f)); return u;
}
__device__ __forceinline__ void mma_tf32(float* c, const uint32_t* a, const uint32_t* b) {
    asm volatile(
        "mma.sync.aligned.m16n8k8.row.col.f32.tf32.tf32.f32 "
        "{%0,%1,%2,%3}, {%4,%5,%6,%7}, {%8,%9}, {%0,%1,%2,%3};"
        : "+f"(c[0]), "+f"(c[1]), "+f"(c[2]), "+f"(c[3])
        : "r"(a[0]), "r"(a[1]), "r"(a[2]), "r"(a[3]), "r"(b[0]), "r"(b[1]));
}

// ================= elementwise kernels =================
__global__ void add_pos_kernel(const float* __restrict__ x,
                               const float* __restrict__ pos,
                               float* __restrict__ y)
{
    long i = (long)blockIdx.x * blockDim.x + threadIdx.x;
    long posn = i % ((long)CTX * DIMN);
    y[i] = x[i] + pos[posn];
}

__global__ void layernorm_kernel(const float* __restrict__ x, float* __restrict__ y,
                                 const float* __restrict__ gamma,
                                 const float* __restrict__ beta)
{
    __shared__ float ss[8], qq[8];
    int row = blockIdx.x;
    int tid = threadIdx.x;
    const float* xr = x + (long)row * DIMN;
    float v0 = xr[tid], v1 = xr[tid + 256], v2 = xr[tid + 512];
    float s = v0 + v1 + v2;
    float q = v0*v0 + v1*v1 + v2*v2;
    #pragma unroll
    for (int o = 16; o > 0; o >>= 1) {
        s += __shfl_xor_sync(0xffffffffu, s, o);
        q += __shfl_xor_sync(0xffffffffu, q, o);
    }
    int wid = tid >> 5, lane = tid & 31;
    if (lane == 0) { ss[wid] = s; qq[wid] = q; }
    __syncthreads();
    if (tid == 0) {
        float ts = 0.f, tq = 0.f;
        #pragma unroll
        for (int i = 0; i < 8; i++) { ts += ss[i]; tq += qq[i]; }
        ss[0] = ts; qq[0] = tq;
    }
    __syncthreads();
    float mean = ss[0] * (1.0f / DIMN);
    float var  = qq[0] * (1.0f / DIMN) - mean * mean;
    float inv  = rsqrtf(var + 1e-5f);
    float* yr = y + (long)row * DIMN;
    yr[tid      ] = (v0 - mean) * inv * gamma[tid      ] + beta[tid      ];
    yr[tid + 256] = (v1 - mean) * inv * gamma[tid + 256] + beta[tid + 256];
    yr[tid + 512] = (v2 - mean) * inv * gamma[tid + 512] + beta[tid + 512];
}

// transpose all 24 weight matrices (768x768) into g_wT; z = l*6 + w
__global__ void transpose_w(const float* __restrict__ Wq, const float* __restrict__ Wk,
                            const float* __restrict__ Wv, const float* __restrict__ Wo,
                            const float* __restrict__ W1, const float* __restrict__ W2,
                            float* __restrict__ dst)
{
    __shared__ float t[32][33];
    int z = blockIdx.z;
    int l = z / 6, w = z - l * 6;
    const float* srcs[6] = {Wq, Wk, Wv, Wo, W1, W2};
    const float* src = srcs[w] + (long)l * WSZ;
    float* d = dst + (long)z * WSZ;
    int tx = threadIdx.x, ty = threadIdx.y;
    int x = blockIdx.x * 32 + tx;
    int y = blockIdx.y * 32 + ty;
    #pragma unroll
    for (int i = 0; i < 4; i++)
        t[ty + 8*i][tx] = src[(long)(y + 8*i) * DIMN + x];
    __syncthreads();
    int x2 = blockIdx.y * 32 + tx;
    int y2 = blockIdx.x * 32 + ty;
    #pragma unroll
    for (int i = 0; i < 4; i++)
        d[(long)(y2 + 8*i) * DIMN + x2] = t[tx][ty + 8*i];
}

// ================= fused flash attention (tf32 mma) =================
// grid: (16 q-tiles, 48 batch*head). block: 256 (8 warps x 16 q-rows).
// Q tile 128x64 (pre-scaled by 1/8, frags in regs); KV tiles 64 tokens.
// Ks/Vs: native [token][hd] pad 68 (conflict-free B-frag LDS).
// Ps: [kvcol][qrow] pad 132 (conflict-free A-frag LDS), reused for Q staging.
#define KPAD 68
#define PPAD 132

__global__ void __launch_bounds__(256, 2)
flash_attn(const float* __restrict__ Q, const float* __restrict__ Kg,
           const float* __restrict__ Vg, float* __restrict__ O)
{
    extern __shared__ uint32_t sm[];
    uint32_t* Ks = sm;                     // [64][KPAD]
    uint32_t* Vs = sm + 64 * KPAD;         // [64][KPAD]
    uint32_t* Ps = sm + 2 * 64 * KPAD;     // [64][PPAD] (also Q staging [d][m])

    const int tid  = threadIdx.x;
    const int wid  = tid >> 5;
    const int lane = tid & 31;
    const int g    = lane >> 2;
    const int tg   = lane & 3;
    const int mwo  = wid * 16;             // warp's q-row base

    const int bh = blockIdx.y;
    const int b  = bh / HEADS, h = bh - b * HEADS;
    const long qoff  = ((long)b * CTX + blockIdx.x * 128) * INNER + h * HD;
    const long kvoff = (long)b * CTX * INNER + h * HD;

    // ---- stage Q (x 1/8) into Ps as [d][m], extract A-fragments to regs ----
    {
        const int m = tid >> 1, half = tid & 1;
        const float* qp = Q + qoff + (long)m * INNER + half * 32;
        #pragma unroll
        for (int i = 0; i < 8; i++) {
            float4 v = *(const float4*)(qp + 4 * i);
            int d = half * 32 + 4 * i;
            Ps[(d + 0) * PPAD + m] = cvt_tf32(0.125f * v.x);
            Ps[(d + 1) * PPAD + m] = cvt_tf32(0.125f * v.y);
            Ps[(d + 2) * PPAD + m] = cvt_tf32(0.125f * v.z);
            Ps[(d + 3) * PPAD + m] = cvt_tf32(0.125f * v.w);
        }
    }
    __syncthreads();
    uint32_t qf[8][4];
    #pragma unroll
    for (int kk = 0; kk < 8; kk++) {
        qf[kk][0] = Ps[(kk * 8 + tg) * PPAD + mwo + g];
        qf[kk][1] = Ps[(kk * 8 + tg) * PPAD + mwo + g + 8];
        qf[kk][2] = Ps[(kk * 8 + tg + 4) * PPAD + mwo + g];
        qf[kk][3] = Ps[(kk * 8 + tg + 4) * PPAD + mwo + g + 8];
    }

    float m_r[2] = {-1e30f, -1e30f};
    float l_r[2] = {0.f, 0.f};
    float acc_o[8][4];
    #pragma unroll
    for (int nt = 0; nt < 8; nt++)
        #pragma unroll
        for (int c = 0; c < 4; c++) acc_o[nt][c] = 0.f;

    const int jrow = tid >> 2, jq = tid & 3;
    const float* kp0 = Kg + kvoff + (long)jrow * INNER + jq * 16;
    const float* vp0 = Vg + kvoff + (long)jrow * INNER + jq * 16;

    for (int it = 0; it < CTX / 64; it++) {
        __syncthreads();                    // prev-iter reads of Ks/Vs/Ps done
        const long joff = (long)it * 64 * INNER;
        #pragma unroll
        for (int i = 0; i < 4; i++) {
            float4 kv = *(const float4*)(kp0 + joff + 4 * i);
            float4 vv = *(const float4*)(vp0 + joff + 4 * i);
            int d = jq * 16 + 4 * i;
            Ks[jrow * KPAD + d + 0] = cvt_tf32(kv.x);
            Ks[jrow * KPAD + d + 1] = cvt_tf32(kv.y);
            Ks[jrow * KPAD + d + 2] = cvt_tf32(kv.z);
            Ks[jrow * KPAD + d + 3] = cvt_tf32(kv.w);
            Vs[jrow * KPAD + d + 0] = cvt_tf32(vv.x);
            Vs[jrow * KPAD + d + 1] = cvt_tf32(vv.y);
            Vs[jrow * KPAD + d + 2] = cvt_tf32(vv.z);
            Vs[jrow * KPAD + d + 3] = cvt_tf32(vv.w);
        }
        __syncthreads();

        // ---- S = Q @ K^T (rows mwo..mwo+15, cols 0..63) ----
        float acc_s[8][4];
        #pragma unroll
        for (int nt = 0; nt < 8; nt++)
            #pragma unroll
            for (int c = 0; c < 4; c++) acc_s[nt][c] = 0.f;
        #pragma unroll
        for (int kk = 0; kk < 8; kk++) {
            #pragma unroll
            for (int nt = 0; nt < 8; nt++) {
                uint32_t bf[2];
                bf[0] = Ks[(nt * 8 + g) * KPAD + kk * 8 + tg];
                bf[1] = Ks[(nt * 8 + g) * KPAD + kk * 8 + tg + 4];
                mma_tf32(acc_s[nt], qf[kk], bf);
            }
        }

        // ---- online softmax (rows g and g+8 within warp tile) ----
        #pragma unroll
        for (int r = 0; r < 2; r++) {
            float mx = -1e30f;
            #pragma unroll
            for (int nt = 0; nt < 8; nt++)
                mx = fmaxf(mx, fmaxf(acc_s[nt][2 * r], acc_s[nt][2 * r + 1]));
            mx = fmaxf(mx, __shfl_xor_sync(0xffffffffu, mx, 1));
            mx = fmaxf(mx, __shfl_xor_sync(0xffffffffu, mx, 2));
            float mn = fmaxf(m_r[r], mx);
            float alpha = __expf(m_r[r] - mn);
            m_r[r] = mn;
            float sum = 0.f;
            #pragma unroll
            for (int nt = 0; nt < 8; nt++) {
                float p0 = __expf(acc_s[nt][2 * r]     - mn);
                float p1 = __expf(acc_s[nt][2 * r + 1] - mn);
                sum += p0 + p1;
                Ps[(nt * 8 + 2 * tg)     * PPAD + mwo + g + 8 * r] = cvt_tf32(p0);
                Ps[(nt * 8 + 2 * tg + 1) * PPAD + mwo + g + 8 * r] = cvt_tf32(p1);
            }
            sum += __shfl_xor_sync(0xffffffffu, sum, 1);
            sum += __shfl_xor_sync(0xffffffffu, sum, 2);
            l_r[r] = alpha * l_r[r] + sum;
            #pragma unroll
            for (int nt = 0; nt < 8; nt++) {
                acc_o[nt][2 * r]     *= alpha;
                acc_o[nt][2 * r + 1] *= alpha;
            }
        }
        __syncthreads();

        // ---- O += P @ V ----
        #pragma unroll
        for (int kk = 0; kk < 8; kk++) {
            uint32_t af[4];
            af[0] = Ps[(kk * 8 + tg) * PPAD + mwo + g];
            af[1] = Ps[(kk * 8 + tg) * PPAD + mwo + g + 8];
            af[2] = Ps[(kk * 8 + tg + 4) * PPAD + mwo + g];
            af[3] = Ps[(kk * 8 + tg + 4) * PPAD + mwo + g + 8];
            #pragma unroll
            for (int nt = 0; nt < 8; nt++) {
                uint32_t bf[2];
                bf[0] = Vs[(kk * 8 + tg) * KPAD + nt * 8 + g];
                bf[1] = Vs[(kk * 8 + tg + 4) * KPAD + nt * 8 + g];
                mma_tf32(acc_o[nt], af, bf);
            }
        }
    }

    // ---- write O = acc / l ----
    const float inv0 = 1.0f / l_r[0];
    const float inv1 = 1.0f / l_r[1];
    #pragma unroll
    for (int nt = 0; nt < 8; nt++) {
        float2 o0, o1;
        o0.x = acc_o[nt][0] * inv0; o0.y = acc_o[nt][1] * inv0;
        o1.x = acc_o[nt][2] * inv1; o1.y = acc_o[nt][3] * inv1;
        *(float2*)(O + qoff + (long)(mwo + g) * INNER + nt * 8 + 2 * tg) = o0;
        *(float2*)(O + qoff + (long)(mwo + g + 8) * INNER + nt * 8 + 2 * tg) = o1;
    }
}

// ================= tf32 mma.sync batched GEMM (dense projections) =================
#define BK 16
#define BM 128

template<int BN_, int WROWS, bool GELU_, bool HASBIAS, bool HASRES>
__global__ void __launch_bounds__(256, 2)
mma_gemm(const float* __restrict__ A, const float* __restrict__ B,
         float* __restrict__ C, const float* __restrict__ bias,
         const float* __restrict__ residual,
         int K, int lda, int ldb, int ldc,
         long sA1, long sA2, long sB1, long sB2, long sC1, long sC2,
         int batch2, float alpha)
{
    constexpr int WCOLS = 8 / WROWS;
    constexpr int MT = (BM / WROWS) / 16;
    constexpr int NT = (BN_ / WCOLS) / 8;
    constexpr int SEGA = BM * BK / 4 / 256;
    constexpr int SEGB = BN_ * BK / 4 / 256;
    constexpr int PAD = 4;

    __shared__ uint32_t As[2][BK][BM + PAD];
    __shared__ uint32_t Bs[2][BK][BN_ + PAD];

    const int z  = blockIdx.z;
    const int zo = z / batch2, zi = z - zo * batch2;
    A += zo * sA1 + zi * sA2;
    B += zo * sB1 + zi * sB2;
    const long coff = (long)zo * sC1 + (long)zi * sC2;

    const int tid  = threadIdx.x;
    const int wid  = tid >> 5;
    const int lane = tid & 31;
    const int g    = lane >> 2;
    const int tg   = lane & 3;
    const int wm   = wid % WROWS;
    const int wn   = wid / WROWS;
    const int mwo  = wm * MT * 16;
    const int nwo  = wn * NT * 8;

    const int m0 = blockIdx.y * BM;
    const int n0 = blockIdx.x * BN_;

    const float* ap[SEGA]; int arow[SEGA], acol[SEGA];
    #pragma unroll
    for (int i = 0; i < SEGA; i++) {
        int seg = tid + 256 * i;
        arow[i] = seg >> 2;
        acol[i] = (seg & 3) * 4;
        ap[i] = A + (long)(m0 + arow[i]) * lda + acol[i];
    }
    const float* bp[SEGB]; int brow[SEGB], bcol[SEGB];
    #pragma unroll
    for (int i = 0; i < SEGB; i++) {
        int seg = tid + 256 * i;
        brow[i] = seg / (BK / 4);
        bcol[i] = (seg % (BK / 4)) * 4;
        bp[i] = B + (long)(n0 + brow[i]) * ldb + bcol[i];
    }

    float acc[MT][NT][4];
    #pragma unroll
    for (int i = 0; i < MT; i++)
        #pragma unroll
        for (int j = 0; j < NT; j++)
            #pragma unroll
            for (int k = 0; k < 4; k++) acc[i][j][k] = 0.f;

    float4 ra[SEGA], rb[SEGB];

#define STS_TILE(BUFV)                                                     \
    {                                                                      \
        _Pragma("unroll")                                                  \
        for (int i = 0; i < SEGA; i++) {                                   \
            As[BUFV][acol[i]+0][arow[i]] = cvt_tf32(ra[i].x);              \
            As[BUFV][acol[i]+1][arow[i]] = cvt_tf32(ra[i].y);              \
            As[BUFV][acol[i]+2][arow[i]] = cvt_tf32(ra[i].z);              \
            As[BUFV][acol[i]+3][arow[i]] = cvt_tf32(ra[i].w);              \
        }                                                                  \
        _Pragma("unroll")                                                  \
        for (int i = 0; i < SEGB; i++) {                                   \
            Bs[BUFV][bcol[i]+0][brow[i]] = cvt_tf32(rb[i].x);              \
            Bs[BUFV][bcol[i]+1][brow[i]] = cvt_tf32(rb[i].y);              \
            Bs[BUFV][bcol[i]+2][brow[i]] = cvt_tf32(rb[i].z);              \
            Bs[BUFV][bcol[i]+3][brow[i]] = cvt_tf32(rb[i].w);              \
        }                                                                  \
    }

    #pragma unroll
    for (int i = 0; i < SEGA; i++) ra[i] = *(const float4*)(ap[i]);
    #pragma unroll
    for (int i = 0; i < SEGB; i++) rb[i] = *(const float4*)(bp[i]);
    STS_TILE(0);
    __syncthreads();

    const int ntiles = K / BK;
    int buf = 0;
    for (int s = 0; s < ntiles; s++) {
        if (s + 1 < ntiles) {
            const int koff = (s + 1) * BK;
            #pragma unroll
            for (int i = 0; i < SEGA; i++) ra[i] = *(const float4*)(ap[i] + koff);
            #pragma unroll
            for (int i = 0; i < SEGB; i++) rb[i] = *(const float4*)(bp[i] + koff);
        }
        #pragma unroll
        for (int kk = 0; kk < 2; kk++) {
            const int kb = kk * 8;
            uint32_t af[MT][4];
            #pragma unroll
            for (int mt = 0; mt < MT; mt++) {
                int m = mwo + mt * 16 + g;
                af[mt][0] = As[buf][kb + tg    ][m];
                af[mt][1] = As[buf][kb + tg    ][m + 8];
                af[mt][2] = As[buf][kb + tg + 4][m];
                af[mt][3] = As[buf][kb + tg + 4][m + 8];
            }
            uint32_t bf[NT][2];
            #pragma unroll
            for (int nt = 0; nt < NT; nt++) {
                int n = nwo + nt * 8 + g;
                bf[nt][0] = Bs[buf][kb + tg    ][n];
                bf[nt][1] = Bs[buf][kb + tg + 4][n];
            }
            #pragma unroll
            for (int mt = 0; mt < MT; mt++)
                #pragma unroll
                for (int nt = 0; nt < NT; nt++)
                    mma_tf32(acc[mt][nt], af[mt], bf[nt]);
        }
        if (s + 1 < ntiles) {
            __syncthreads();
            STS_TILE(buf ^ 1);
            __syncthreads();
            buf ^= 1;
        }
    }
#undef STS_TILE

    float* Cp = C + coff;
    const float* Rp = HASRES ? residual + coff : nullptr;
    #pragma unroll
    for (int mt = 0; mt < MT; mt++) {
        const long r0 = m0 + mwo + mt * 16 + g;
        const long r1 = r0 + 8;
        #pragma unroll
        for (int nt = 0; nt < NT; nt++) {
            const int cb = n0 + nwo + nt * 8 + 2 * tg;
            float2 v0, v1;
            v0.x = acc[mt][nt][0] * alpha; v0.y = acc[mt][nt][1] * alpha;
            v1.x = acc[mt][nt][2] * alpha; v1.y = acc[mt][nt][3] * alpha;
            if (HASBIAS) {
                float bx = bias[cb], by = bias[cb + 1];
                v0.x += bx; v0.y += by; v1.x += bx; v1.y += by;
            }
            if (GELU_) {
                v0.x = 0.5f * v0.x * (1.0f + erff(v0.x * 0.70710678118654752f));
                v0.y = 0.5f * v0.y * (1.0f + erff(v0.y * 0.70710678118654752f));
                v1.x = 0.5f * v1.x * (1.0f + erff(v1.x * 0.70710678118654752f));
                v1.y = 0.5f * v1.y * (1.0f + erff(v1.y * 0.70710678118654752f));
            }
            if (HASRES) {
                float2 q0 = *(const float2*)(Rp + r0 * ldc + cb);
                float2 q1 = *(const float2*)(Rp + r1 * ldc + cb);
                v0.x += q0.x; v0.y += q0.y; v1.x += q1.x; v1.y += q1.y;
            }
            *(float2*)(Cp + r0 * ldc + cb) = v0;
            *(float2*)(Cp + r1 * ldc + cb) = v1;
        }
    }
}

template<int BN_, int WROWS, bool GELU_, bool HASBIAS, bool HASRES>
static void launch_mm(const float* A, const float* B, float* C,
                      const float* bias, const float* res,
                      int M, int N, int K, int lda, int ldb, int ldc,
                      long sA1, long sA2, long sB1, long sB2, long sC1, long sC2,
                      int batch2, int nz, float alpha)
{
    dim3 grid(N / BN_, M / BM, nz);
    mma_gemm<BN_, WROWS, GELU_, HASBIAS, HASRES><<<grid, 256>>>(
        A, B, C, bias, res, K, lda, ldb, ldc,
        sA1, sA2, sB1, sB2, sC1, sC2, batch2, alpha);
}

extern "C" void kernel_launch(void* const* d_in, const int* in_sizes, int n_in,
                              void* d_out, int out_size)
{
    const float* x     = (const float*)d_in[0];
    const float* pos   = (const float*)d_in[1];
    const float* ln1_g = (const float*)d_in[2];
    const float* ln1_b = (const float*)d_in[3];
    const float* Wq    = (const float*)d_in[4];
    const float* Wk    = (const float*)d_in[5];
    const float* Wv    = (const float*)d_in[6];
    const float* Wo    = (const float*)d_in[7];
    const float* ln2_g = (const float*)d_in[8];
    const float* ln2_b = (const float*)d_in[9];
    const float* W1    = (const float*)d_in[10];
    const float* b1    = (const float*)d_in[11];
    const float* W2    = (const float*)d_in[12];
    const float* b2    = (const float*)d_in[13];

    float *gx, *gh, *gqkv, *go, *gf, *gwT;
    cudaGetSymbolAddress((void**)&gx,  g_x);
    cudaGetSymbolAddress((void**)&gh,  g_h);
    cudaGetSymbolAddress((void**)&gqkv,g_qkv);
    cudaGetSymbolAddress((void**)&go,  g_o);
    cudaGetSymbolAddress((void**)&gf,  g_f);
    cudaGetSymbolAddress((void**)&gwT, g_wT);

    float* gq = gqkv;
    float* gk = gqkv + (long)MTOK * INNER;
    float* gv = gqkv + 2L * MTOK * INNER;

    const int FLASH_SMEM = (2 * 64 * KPAD + 64 * PPAD) * 4;
    cudaFuncSetAttribute((const void*)flash_attn,
                         cudaFuncAttributeMaxDynamicSharedMemorySize, FLASH_SMEM);

    {
        dim3 grid(DIMN / 32, DIMN / 32, DEPTH * 6);
        transpose_w<<<grid, dim3(32, 8)>>>(Wq, Wk, Wv, Wo, W1, W2, gwT);
    }

    add_pos_kernel<<<(MTOK * DIMN) / 256, 256>>>(x, pos, gx);

    for (int l = 0; l < DEPTH; l++) {
        const float* wqT = gwT + (long)(l * 6 + 0) * WSZ;
        const float* woT = gwT + (long)(l * 6 + 3) * WSZ;
        const float* w1T = gwT + (long)(l * 6 + 4) * WSZ;
        const float* w2T = gwT + (long)(l * 6 + 5) * WSZ;
        const float* l1g = ln1_g + l * DIMN, *l1b = ln1_b + l * DIMN;
        const float* l2g = ln2_g + l * DIMN, *l2b = ln2_b + l * DIMN;
        const float* bb1 = b1 + l * DIMN,   *bb2 = b2 + l * DIMN;

        // --- attention
        layernorm_kernel<<<MTOK, 256>>>(gx, gh, l1g, l1b);

        // fused QKV projection
        launch_mm<128, 2, false, false, false>(
            gh, wqT, gqkv, nullptr, nullptr,
            MTOK, INNER, DIMN, DIMN, DIMN, INNER,
            0, 0, WSZ, 0, (long)MTOK * INNER, 0, 1, 3, 1.0f);

        // fused flash attention (replaces QK^T, softmax, PV, transpose)
        flash_attn<<<dim3(CTX / 128, BATCH * HEADS), 256, FLASH_SMEM>>>(gq, gk, gv, go);

        // x = x + O @ Wo
        launch_mm<128, 2, false, false, true>(
            go, woT, gx, nullptr, gx,
            MTOK, DIMN, INNER, INNER, INNER, DIMN,
            0, 0, 0, 0, 0, 0, 1, 1, 1.0f);

        // --- FFN
        layernorm_kernel<<<MTOK, 256>>>(gx, gh, l2g, l2b);

        launch_mm<128, 2, true, true, false>(
            gh, w1T, gf, bb1, nullptr,
            MTOK, DIMN, DIMN, DIMN, DIMN, DIMN,
            0, 0, 0, 0, 0, 0, 1, 1, 1.0f);

        float* cout = (l == DEPTH - 1) ? (float*)d_out : gx;
        launch_mm<128, 2, false, true, true>(
            gf, w2T, cout, bb2, gx,
            MTOK, DIMN, DIMN, DIMN, DIMN, DIMN,
            0, 0, 0, 0, 0, 0, 1, 1, 1.0f);
    }
}

// round 6
// speedup vs baseline: 5.8876x; 1.5162x over previous
#include <cuda_runtime.h>
#include <cuda_fp16.h>
#include <math.h>
#include <stdint.h>

#define DEPTH 4
#define DIMN  768
#define HEADS 12
#define HD    64
#define CTX   2048
#define BATCH 4
#define MTOK  (BATCH*CTX)          // 8192
#define INNER (HEADS*HD)           // 768
#define WSZ   ((long)DIMN*DIMN)

// ---------------- scratch (device globals; no allocation) ----------------
__device__ __align__(128) float g_x  [MTOK*DIMN];
__device__ __align__(128) float g_h  [MTOK*DIMN];
__device__ __align__(128) float g_qkv[3L*MTOK*INNER];
__device__ __align__(128) float g_o  [MTOK*INNER];
__device__ __align__(128) float g_f  [MTOK*DIMN];
__device__ __align__(128) float g_wT [24L*DIMN*DIMN];

__device__ __forceinline__ uint32_t cvt_h2(float lo, float hi) {
    __half2 h = __floats2half2_rn(lo, hi);
    return *(uint32_t*)&h;
}
// D(f32) += A(f16) @ B(f16): m16n8k16
__device__ __forceinline__ void mma_f16(float* c, const uint32_t* a, const uint32_t* b) {
    asm volatile(
        "mma.sync.aligned.m16n8k16.row.col.f32.f16.f16.f32 "
        "{%0,%1,%2,%3}, {%4,%5,%6,%7}, {%8,%9}, {%0,%1,%2,%3};"
        : "+f"(c[0]), "+f"(c[1]), "+f"(c[2]), "+f"(c[3])
        : "r"(a[0]), "r"(a[1]), "r"(a[2]), "r"(a[3]), "r"(b[0]), "r"(b[1]));
}

// ================= elementwise kernels =================
__global__ void add_pos_kernel(const float* __restrict__ x,
                               const float* __restrict__ pos,
                               float* __restrict__ y)
{
    long i = (long)blockIdx.x * blockDim.x + threadIdx.x;
    long posn = i % ((long)CTX * DIMN);
    y[i] = x[i] + pos[posn];
}

__global__ void layernorm_kernel(const float* __restrict__ x, float* __restrict__ y,
                                 const float* __restrict__ gamma,
                                 const float* __restrict__ beta)
{
    __shared__ float ss[8], qq[8];
    int row = blockIdx.x;
    int tid = threadIdx.x;
    const float* xr = x + (long)row * DIMN;
    float v0 = xr[tid], v1 = xr[tid + 256], v2 = xr[tid + 512];
    float s = v0 + v1 + v2;
    float q = v0*v0 + v1*v1 + v2*v2;
    #pragma unroll
    for (int o = 16; o > 0; o >>= 1) {
        s += __shfl_xor_sync(0xffffffffu, s, o);
        q += __shfl_xor_sync(0xffffffffu, q, o);
    }
    int wid = tid >> 5, lane = tid & 31;
    if (lane == 0) { ss[wid] = s; qq[wid] = q; }
    __syncthreads();
    if (tid == 0) {
        float ts = 0.f, tq = 0.f;
        #pragma unroll
        for (int i = 0; i < 8; i++) { ts += ss[i]; tq += qq[i]; }
        ss[0] = ts; qq[0] = tq;
    }
    __syncthreads();
    float mean = ss[0] * (1.0f / DIMN);
    float var  = qq[0] * (1.0f / DIMN) - mean * mean;
    float inv  = rsqrtf(var + 1e-5f);
    float* yr = y + (long)row * DIMN;
    yr[tid      ] = (v0 - mean) * inv * gamma[tid      ] + beta[tid      ];
    yr[tid + 256] = (v1 - mean) * inv * gamma[tid + 256] + beta[tid + 256];
    yr[tid + 512] = (v2 - mean) * inv * gamma[tid + 512] + beta[tid + 512];
}

// transpose all 24 weight matrices (768x768) into g_wT; z = l*6 + w
__global__ void transpose_w(const float* __restrict__ Wq, const float* __restrict__ Wk,
                            const float* __restrict__ Wv, const float* __restrict__ Wo,
                            const float* __restrict__ W1, const float* __restrict__ W2,
                            float* __restrict__ dst)
{
    __shared__ float t[32][33];
    int z = blockIdx.z;
    int l = z / 6, w = z - l * 6;
    const float* srcs[6] = {Wq, Wk, Wv, Wo, W1, W2};
    const float* src = srcs[w] + (long)l * WSZ;
    float* d = dst + (long)z * WSZ;
    int tx = threadIdx.x, ty = threadIdx.y;
    int x = blockIdx.x * 32 + tx;
    int y = blockIdx.y * 32 + ty;
    #pragma unroll
    for (int i = 0; i < 4; i++)
        t[ty + 8*i][tx] = src[(long)(y + 8*i) * DIMN + x];
    __syncthreads();
    int x2 = blockIdx.y * 32 + tx;
    int y2 = blockIdx.x * 32 + ty;
    #pragma unroll
    for (int i = 0; i < 4; i++)
        d[(long)(y2 + 8*i) * DIMN + x2] = t[tx][ty + 8*i];
}

// ================= fused flash attention (fp16 mma) =================
// grid: (16 q-tiles, 48 batch*head). block: 256 (8 warps x 16 q-rows).
// Ks: [tok=64][KW2P] half2 packed along hd. Vs: [hd=64][KW2P] packed along token.
// Ps: [col2=32][PPAD] half2 (also Q staging [d2=32][m]).
#define KW2P 36      // 32 half2 + pad 4  -> frag reads conflict-free
#define PPAD 132

__global__ void __launch_bounds__(256, 2)
flash_attn(const float* __restrict__ Q, const float* __restrict__ Kg,
           const float* __restrict__ Vg, float* __restrict__ O)
{
    extern __shared__ uint32_t sm[];
    uint32_t* Ks = sm;                       // [64][KW2P]
    uint32_t* Vs = sm + 64 * KW2P;           // [64][KW2P]
    uint32_t* Ps = sm + 2 * 64 * KW2P;       // [32][PPAD]

    const int tid  = threadIdx.x;
    const int wid  = tid >> 5;
    const int lane = tid & 31;
    const int g    = lane >> 2;
    const int tg   = lane & 3;
    const int mwo  = wid * 16;

    const int bh = blockIdx.y;
    const int b  = bh / HEADS, h = bh - b * HEADS;
    const long qoff  = ((long)b * CTX + blockIdx.x * 128) * INNER + h * HD;
    const long kvoff = (long)b * CTX * INNER + h * HD;

    // ---- stage Q (x 1/8) into Ps as half2 [d2][m] ----
    {
        const int m = tid >> 1, half = tid & 1;
        const float* qp = Q + qoff + (long)m * INNER + half * 32;
        #pragma unroll
        for (int i = 0; i < 8; i++) {
            float4 v = *(const float4*)(qp + 4 * i);
            int d2 = half * 16 + 2 * i;
            Ps[(d2 + 0) * PPAD + m] = cvt_h2(0.125f * v.x, 0.125f * v.y);
            Ps[(d2 + 1) * PPAD + m] = cvt_h2(0.125f * v.z, 0.125f * v.w);
        }
    }
    __syncthreads();
    uint32_t qf[4][4];                       // 4 k16-steps over hd=64
    #pragma unroll
    for (int kk = 0; kk < 4; kk++) {
        qf[kk][0] = Ps[(kk * 8 + tg) * PPAD + mwo + g];
        qf[kk][1] = Ps[(kk * 8 + tg) * PPAD + mwo + g + 8];
        qf[kk][2] = Ps[(kk * 8 + tg + 4) * PPAD + mwo + g];
        qf[kk][3] = Ps[(kk * 8 + tg + 4) * PPAD + mwo + g + 8];
    }

    float m_r[2] = {-1e30f, -1e30f};
    float l_r[2] = {0.f, 0.f};
    float acc_o[8][4];
    #pragma unroll
    for (int nt = 0; nt < 8; nt++)
        #pragma unroll
        for (int c = 0; c < 4; c++) acc_o[nt][c] = 0.f;

    // K loader: tok = tid>>2 (0..63), dq = tid&3 -> hd [dq*16, +16)
    const int ktok = tid >> 2, kdq = tid & 3;
    const float* kp0 = Kg + kvoff + (long)ktok * INNER + kdq * 16;
    // V loader: token pair tp = tid&31, dq8 = tid>>5 -> hd [dq8*8, +8)
    const int vtp = tid & 31, vdq = tid >> 5;
    const float* vp0 = Vg + kvoff + (long)(2 * vtp) * INNER + vdq * 8;

    for (int it = 0; it < CTX / 64; it++) {
        __syncthreads();
        const long joff = (long)it * 64 * INNER;
        // K: pack along hd -> Ks[tok][d2]
        #pragma unroll
        for (int i = 0; i < 4; i++) {
            float4 kv = *(const float4*)(kp0 + joff + 4 * i);
            int d2 = kdq * 8 + 2 * i;
            Ks[ktok * KW2P + d2 + 0] = cvt_h2(kv.x, kv.y);
            Ks[ktok * KW2P + d2 + 1] = cvt_h2(kv.z, kv.w);
        }
        // V: pack along token -> Vs[hd][tok2]
        {
            float4 v0a = *(const float4*)(vp0 + joff);
            float4 v0b = *(const float4*)(vp0 + joff + 4);
            float4 v1a = *(const float4*)(vp0 + joff + INNER);
            float4 v1b = *(const float4*)(vp0 + joff + INNER + 4);
            Vs[(vdq * 8 + 0) * KW2P + vtp] = cvt_h2(v0a.x, v1a.x);
            Vs[(vdq * 8 + 1) * KW2P + vtp] = cvt_h2(v0a.y, v1a.y);
            Vs[(vdq * 8 + 2) * KW2P + vtp] = cvt_h2(v0a.z, v1a.z);
            Vs[(vdq * 8 + 3) * KW2P + vtp] = cvt_h2(v0a.w, v1a.w);
            Vs[(vdq * 8 + 4) * KW2P + vtp] = cvt_h2(v0b.x, v1b.x);
            Vs[(vdq * 8 + 5) * KW2P + vtp] = cvt_h2(v0b.y, v1b.y);
            Vs[(vdq * 8 + 6) * KW2P + vtp] = cvt_h2(v0b.z, v1b.z);
            Vs[(vdq * 8 + 7) * KW2P + vtp] = cvt_h2(v0b.w, v1b.w);
        }
        __syncthreads();

        // ---- S = Q @ K^T ----
        float acc_s[8][4];
        #pragma unroll
        for (int nt = 0; nt < 8; nt++)
            #pragma unroll
            for (int c = 0; c < 4; c++) acc_s[nt][c] = 0.f;
        #pragma unroll
        for (int kk = 0; kk < 4; kk++) {
            #pragma unroll
            for (int nt = 0; nt < 8; nt++) {
                uint32_t bf[2];
                bf[0] = Ks[(nt * 8 + g) * KW2P + kk * 8 + tg];
                bf[1] = Ks[(nt * 8 + g) * KW2P + kk * 8 + tg + 4];
                mma_f16(acc_s[nt], qf[kk], bf);
            }
        }

        // ---- online softmax ----
        #pragma unroll
        for (int r = 0; r < 2; r++) {
            float mx = -1e30f;
            #pragma unroll
            for (int nt = 0; nt < 8; nt++)
                mx = fmaxf(mx, fmaxf(acc_s[nt][2 * r], acc_s[nt][2 * r + 1]));
            mx = fmaxf(mx, __shfl_xor_sync(0xffffffffu, mx, 1));
            mx = fmaxf(mx, __shfl_xor_sync(0xffffffffu, mx, 2));
            float mn = fmaxf(m_r[r], mx);
            float alpha = __expf(m_r[r] - mn);
            m_r[r] = mn;
            float sum = 0.f;
            #pragma unroll
            for (int nt = 0; nt < 8; nt++) {
                float p0 = __expf(acc_s[nt][2 * r]     - mn);
                float p1 = __expf(acc_s[nt][2 * r + 1] - mn);
                sum += p0 + p1;
                Ps[(nt * 4 + tg) * PPAD + mwo + g + 8 * r] = cvt_h2(p0, p1);
            }
            sum += __shfl_xor_sync(0xffffffffu, sum, 1);
            sum += __shfl_xor_sync(0xffffffffu, sum, 2);
            l_r[r] = alpha * l_r[r] + sum;
            #pragma unroll
            for (int nt = 0; nt < 8; nt++) {
                acc_o[nt][2 * r]     *= alpha;
                acc_o[nt][2 * r + 1] *= alpha;
            }
        }
        __syncthreads();

        // ---- O += P @ V ----
        #pragma unroll
        for (int kk = 0; kk < 4; kk++) {
            uint32_t af[4];
            af[0] = Ps[(kk * 8 + tg) * PPAD + mwo + g];
            af[1] = Ps[(kk * 8 + tg) * PPAD + mwo + g + 8];
            af[2] = Ps[(kk * 8 + tg + 4) * PPAD + mwo + g];
            af[3] = Ps[(kk * 8 + tg + 4) * PPAD + mwo + g + 8];
            #pragma unroll
            for (int nt = 0; nt < 8; nt++) {
                uint32_t bf[2];
                bf[0] = Vs[(nt * 8 + g) * KW2P + kk * 8 + tg];
                bf[1] = Vs[(nt * 8 + g) * KW2P + kk * 8 + tg + 4];
                mma_f16(acc_o[nt], af, bf);
            }
        }
    }

    // ---- write O = acc / l ----
    const float inv0 = 1.0f / l_r[0];
    const float inv1 = 1.0f / l_r[1];
    #pragma unroll
    for (int nt = 0; nt < 8; nt++) {
        float2 o0, o1;
        o0.x = acc_o[nt][0] * inv0; o0.y = acc_o[nt][1] * inv0;
        o1.x = acc_o[nt][2] * inv1; o1.y = acc_o[nt][3] * inv1;
        *(float2*)(O + qoff + (long)(mwo + g) * INNER + nt * 8 + 2 * tg) = o0;
        *(float2*)(O + qoff + (long)(mwo + g + 8) * INNER + nt * 8 + 2 * tg) = o1;
    }
}

// ================= fp16 mma.sync batched GEMM (dense projections) =================
// Smem tiles as half2 packed along k: As[k2][m], Bs[k2][n]; BK=16 -> k2 = 8.
#define BK 16
#define BM 128

template<int BN_, int WROWS, bool GELU_, bool HASBIAS, bool HASRES>
__global__ void __launch_bounds__(256, 2)
mma_gemm(const float* __restrict__ A, const float* __restrict__ B,
         float* __restrict__ C, const float* __restrict__ bias,
         const float* __restrict__ residual,
         int K, int lda, int ldb, int ldc,
         long sA1, long sA2, long sB1, long sB2, long sC1, long sC2,
         int batch2, float alpha)
{
    constexpr int WCOLS = 8 / WROWS;
    constexpr int MT = (BM / WROWS) / 16;
    constexpr int NT = (BN_ / WCOLS) / 8;
    constexpr int SEGA = BM * BK / 4 / 256;
    constexpr int SEGB = BN_ * BK / 4 / 256;
    constexpr int PAD = 4;

    __shared__ uint32_t As[2][BK / 2][BM + PAD];
    __shared__ uint32_t Bs[2][BK / 2][BN_ + PAD];

    const int z  = blockIdx.z;
    const int zo = z / batch2, zi = z - zo * batch2;
    A += zo * sA1 + zi * sA2;
    B += zo * sB1 + zi * sB2;
    const long coff = (long)zo * sC1 + (long)zi * sC2;

    const int tid  = threadIdx.x;
    const int wid  = tid >> 5;
    const int lane = tid & 31;
    const int g    = lane >> 2;
    const int tg   = lane & 3;
    const int wm   = wid % WROWS;
    const int wn   = wid / WROWS;
    const int mwo  = wm * MT * 16;
    const int nwo  = wn * NT * 8;

    const int m0 = blockIdx.y * BM;
    const int n0 = blockIdx.x * BN_;

    const float* ap[SEGA]; int arow[SEGA], acol2[SEGA];
    #pragma unroll
    for (int i = 0; i < SEGA; i++) {
        int seg = tid + 256 * i;
        arow[i]  = seg >> 2;
        acol2[i] = (seg & 3) * 2;           // half2 col index (k2)
        ap[i] = A + (long)(m0 + arow[i]) * lda + (seg & 3) * 4;
    }
    const float* bp[SEGB]; int brow[SEGB], bcol2[SEGB];
    #pragma unroll
    for (int i = 0; i < SEGB; i++) {
        int seg = tid + 256 * i;
        brow[i]  = seg / (BK / 4);
        bcol2[i] = (seg % (BK / 4)) * 2;
        bp[i] = B + (long)(n0 + brow[i]) * ldb + (seg % (BK / 4)) * 4;
    }

    float acc[MT][NT][4];
    #pragma unroll
    for (int i = 0; i < MT; i++)
        #pragma unroll
        for (int j = 0; j < NT; j++)
            #pragma unroll
            for (int k = 0; k < 4; k++) acc[i][j][k] = 0.f;

    float4 ra[SEGA], rb[SEGB];

#define STS_TILE(BUFV)                                                     \
    {                                                                      \
        _Pragma("unroll")                                                  \
        for (int i = 0; i < SEGA; i++) {                                   \
            As[BUFV][acol2[i]+0][arow[i]] = cvt_h2(ra[i].x, ra[i].y);      \
            As[BUFV][acol2[i]+1][arow[i]] = cvt_h2(ra[i].z, ra[i].w);      \
        }                                                                  \
        _Pragma("unroll")                                                  \
        for (int i = 0; i < SEGB; i++) {                                   \
            Bs[BUFV][bcol2[i]+0][brow[i]] = cvt_h2(rb[i].x, rb[i].y);      \
            Bs[BUFV][bcol2[i]+1][brow[i]] = cvt_h2(rb[i].z, rb[i].w);      \
        }                                                                  \
    }

    #pragma unroll
    for (int i = 0; i < SEGA; i++) ra[i] = *(const float4*)(ap[i]);
    #pragma unroll
    for (int i = 0; i < SEGB; i++) rb[i] = *(const float4*)(bp[i]);
    STS_TILE(0);
    __syncthreads();

    const int ntiles = K / BK;
    int buf = 0;
    for (int s = 0; s < ntiles; s++) {
        if (s + 1 < ntiles) {
            const int koff = (s + 1) * BK;
            #pragma unroll
            for (int i = 0; i < SEGA; i++) ra[i] = *(const float4*)(ap[i] + koff);
            #pragma unroll
            for (int i = 0; i < SEGB; i++) rb[i] = *(const float4*)(bp[i] + koff);
        }
        // one k16 mma round per BK tile
        {
            uint32_t af[MT][4];
            #pragma unroll
            for (int mt = 0; mt < MT; mt++) {
                int m = mwo + mt * 16 + g;
                af[mt][0] = As[buf][tg    ][m];
                af[mt][1] = As[buf][tg    ][m + 8];
                af[mt][2] = As[buf][tg + 4][m];
                af[mt][3] = As[buf][tg + 4][m + 8];
            }
            uint32_t bf[NT][2];
            #pragma unroll
            for (int nt = 0; nt < NT; nt++) {
                int n = nwo + nt * 8 + g;
                bf[nt][0] = Bs[buf][tg    ][n];
                bf[nt][1] = Bs[buf][tg + 4][n];
            }
            #pragma unroll
            for (int mt = 0; mt < MT; mt++)
                #pragma unroll
                for (int nt = 0; nt < NT; nt++)
                    mma_f16(acc[mt][nt], af[mt], bf[nt]);
        }
        if (s + 1 < ntiles) {
            __syncthreads();
            STS_TILE(buf ^ 1);
            __syncthreads();
            buf ^= 1;
        }
    }
#undef STS_TILE

    float* Cp = C + coff;
    const float* Rp = HASRES ? residual + coff : nullptr;
    #pragma unroll
    for (int mt = 0; mt < MT; mt++) {
        const long r0 = m0 + mwo + mt * 16 + g;
        const long r1 = r0 + 8;
        #pragma unroll
        for (int nt = 0; nt < NT; nt++) {
            const int cb = n0 + nwo + nt * 8 + 2 * tg;
            float2 v0, v1;
            v0.x = acc[mt][nt][0] * alpha; v0.y = acc[mt][nt][1] * alpha;
            v1.x = acc[mt][nt][2] * alpha; v1.y = acc[mt][nt][3] * alpha;
            if (HASBIAS) {
                float bx = bias[cb], by = bias[cb + 1];
                v0.x += bx; v0.y += by; v1.x += bx; v1.y += by;
            }
            if (GELU_) {
                v0.x = 0.5f * v0.x * (1.0f + erff(v0.x * 0.70710678118654752f));
                v0.y = 0.5f * v0.y * (1.0f + erff(v0.y * 0.70710678118654752f));
                v1.x = 0.5f * v1.x * (1.0f + erff(v1.x * 0.70710678118654752f));
                v1.y = 0.5f * v1.y * (1.0f + erff(v1.y * 0.70710678118654752f));
            }
            if (HASRES) {
                float2 q0 = *(const float2*)(Rp + r0 * ldc + cb);
                float2 q1 = *(const float2*)(Rp + r1 * ldc + cb);
                v0.x += q0.x; v0.y += q0.y; v1.x += q1.x; v1.y += q1.y;
            }
            *(float2*)(Cp + r0 * ldc + cb) = v0;
            *(float2*)(Cp + r1 * ldc + cb) = v1;
        }
    }
}

template<int BN_, int WROWS, bool GELU_, bool HASBIAS, bool HASRES>
static void launch_mm(const float* A, const float* B, float* C,
                      const float* bias, const float* res,
                      int M, int N, int K, int lda, int ldb, int ldc,
                      long sA1, long sA2, long sB1, long sB2, long sC1, long sC2,
                      int batch2, int nz, float alpha)
{
    dim3 grid(N / BN_, M / BM, nz);
    mma_gemm<BN_, WROWS, GELU_, HASBIAS, HASRES><<<grid, 256>>>(
        A, B, C, bias, res, K, lda, ldb, ldc,
        sA1, sA2, sB1, sB2, sC1, sC2, batch2, alpha);
}

extern "C" void kernel_launch(void* const* d_in, const int* in_sizes, int n_in,
                              void* d_out, int out_size)
{
    const float* x     = (const float*)d_in[0];
    const float* pos   = (const float*)d_in[1];
    const float* ln1_g = (const float*)d_in[2];
    const float* ln1_b = (const float*)d_in[3];
    const float* Wq    = (const float*)d_in[4];
    const float* Wk    = (const float*)d_in[5];
    const float* Wv    = (const float*)d_in[6];
    const float* Wo    = (const float*)d_in[7];
    const float* ln2_g = (const float*)d_in[8];
    const float* ln2_b = (const float*)d_in[9];
    const float* W1    = (const float*)d_in[10];
    const float* b1    = (const float*)d_in[11];
    const float* W2    = (const float*)d_in[12];
    const float* b2    = (const float*)d_in[13];

    float *gx, *gh, *gqkv, *go, *gf, *gwT;
    cudaGetSymbolAddress((void**)&gx,  g_x);
    cudaGetSymbolAddress((void**)&gh,  g_h);
    cudaGetSymbolAddress((void**)&gqkv,g_qkv);
    cudaGetSymbolAddress((void**)&go,  g_o);
    cudaGetSymbolAddress((void**)&gf,  g_f);
    cudaGetSymbolAddress((void**)&gwT, g_wT);

    float* gq = gqkv;
    float* gk = gqkv + (long)MTOK * INNER;
    float* gv = gqkv + 2L * MTOK * INNER;

    const int FLASH_SMEM = (2 * 64 * KW2P + 32 * PPAD) * 4;
    cudaFuncSetAttribute((const void*)flash_attn,
                         cudaFuncAttributeMaxDynamicSharedMemorySize, FLASH_SMEM);

    {
        dim3 grid(DIMN / 32, DIMN / 32, DEPTH * 6);
        transpose_w<<<grid, dim3(32, 8)>>>(Wq, Wk, Wv, Wo, W1, W2, gwT);
    }

    add_pos_kernel<<<(MTOK * DIMN) / 256, 256>>>(x, pos, gx);

    for (int l = 0; l < DEPTH; l++) {
        const float* wqT = gwT + (long)(l * 6 + 0) * WSZ;
        const float* woT = gwT + (long)(l * 6 + 3) * WSZ;
        const float* w1T = gwT + (long)(l * 6 + 4) * WSZ;
        const float* w2T = gwT + (long)(l * 6 + 5) * WSZ;
        const float* l1g = ln1_g + l * DIMN, *l1b = ln1_b + l * DIMN;
        const float* l2g = ln2_g + l * DIMN, *l2b = ln2_b + l * DIMN;
        const float* bb1 = b1 + l * DIMN,   *bb2 = b2 + l * DIMN;

        // --- attention
        layernorm_kernel<<<MTOK, 256>>>(gx, gh, l1g, l1b);

        // fused QKV projection
        launch_mm<128, 2, false, false, false>(
            gh, wqT, gqkv, nullptr, nullptr,
            MTOK, INNER, DIMN, DIMN, DIMN, INNER,
            0, 0, WSZ, 0, (long)MTOK * INNER, 0, 1, 3, 1.0f);

        // fused flash attention
        flash_attn<<<dim3(CTX / 128, BATCH * HEADS), 256, FLASH_SMEM>>>(gq, gk, gv, go);

        // x = x + O @ Wo
        launch_mm<128, 2, false, false, true>(
            go, woT, gx, nullptr, gx,
            MTOK, DIMN, INNER, INNER, INNER, DIMN,
            0, 0, 0, 0, 0, 0, 1, 1, 1.0f);

        // --- FFN
        layernorm_kernel<<<MTOK, 256>>>(gx, gh, l2g, l2b);

        launch_mm<128, 2, true, true, false>(
            gh, w1T, gf, bb1, nullptr,
            MTOK, DIMN, DIMN, DIMN, DIMN, DIMN,
            0, 0, 0, 0, 0, 0, 1, 1, 1.0f);

        float* cout = (l == DEPTH - 1) ? (float*)d_out : gx;
        launch_mm<128, 2, false, true, true>(
            gf, w2T, cout, bb2, gx,
            MTOK, DIMN, DIMN, DIMN, DIMN, DIMN,
            0, 0, 0, 0, 0, 0, 1, 1, 1.0f);
    }
}

// round 7
// speedup vs baseline: 6.0233x; 1.0230x over previous
#include <cuda_runtime.h>
#include <cuda_fp16.h>
#include <math.h>
#include <stdint.h>

#define DEPTH 4
#define DIMN  768
#define HEADS 12
#define HD    64
#define CTX   2048
#define BATCH 4
#define MTOK  (BATCH*CTX)          // 8192
#define INNER (HEADS*HD)           // 768
#define WSZ   ((long)DIMN*DIMN)

// ---------------- scratch (device globals; no allocation) ----------------
__device__ __align__(128) float g_x  [MTOK*DIMN];
__device__ __align__(128) float g_h  [MTOK*DIMN];
__device__ __align__(128) float g_qkv[3L*MTOK*INNER];
__device__ __align__(128) float g_o  [MTOK*INNER];
__device__ __align__(128) float g_f  [MTOK*DIMN];
__device__ __align__(128) float g_wT [24L*DIMN*DIMN];

__device__ __forceinline__ uint32_t cvt_h2(float lo, float hi) {
    __half2 h = __floats2half2_rn(lo, hi);
    return *(uint32_t*)&h;
}
// D(f32) += A(f16) @ B(f16): m16n8k16
__device__ __forceinline__ void mma_f16(float* c, const uint32_t* a, const uint32_t* b) {
    asm volatile(
        "mma.sync.aligned.m16n8k16.row.col.f32.f16.f16.f32 "
        "{%0,%1,%2,%3}, {%4,%5,%6,%7}, {%8,%9}, {%0,%1,%2,%3};"
        : "+f"(c[0]), "+f"(c[1]), "+f"(c[2]), "+f"(c[3])
        : "r"(a[0]), "r"(a[1]), "r"(a[2]), "r"(a[3]), "r"(b[0]), "r"(b[1]));
}

// ================= elementwise kernels =================
__global__ void add_pos_kernel(const float* __restrict__ x,
                               const float* __restrict__ pos,
                               float* __restrict__ y)
{
    long i = (long)blockIdx.x * blockDim.x + threadIdx.x;
    long posn = i % ((long)CTX * DIMN);
    y[i] = x[i] + pos[posn];
}

__global__ void layernorm_kernel(const float* __restrict__ x, float* __restrict__ y,
                                 const float* __restrict__ gamma,
                                 const float* __restrict__ beta)
{
    __shared__ float ss[8], qq[8];
    int row = blockIdx.x;
    int tid = threadIdx.x;
    const float* xr = x + (long)row * DIMN;
    float v0 = xr[tid], v1 = xr[tid + 256], v2 = xr[tid + 512];
    float s = v0 + v1 + v2;
    float q = v0*v0 + v1*v1 + v2*v2;
    #pragma unroll
    for (int o = 16; o > 0; o >>= 1) {
        s += __shfl_xor_sync(0xffffffffu, s, o);
        q += __shfl_xor_sync(0xffffffffu, q, o);
    }
    int wid = tid >> 5, lane = tid & 31;
    if (lane == 0) { ss[wid] = s; qq[wid] = q; }
    __syncthreads();
    if (tid == 0) {
        float ts = 0.f, tq = 0.f;
        #pragma unroll
        for (int i = 0; i < 8; i++) { ts += ss[i]; tq += qq[i]; }
        ss[0] = ts; qq[0] = tq;
    }
    __syncthreads();
    float mean = ss[0] * (1.0f / DIMN);
    float var  = qq[0] * (1.0f / DIMN) - mean * mean;
    float inv  = rsqrtf(var + 1e-5f);
    float* yr = y + (long)row * DIMN;
    yr[tid      ] = (v0 - mean) * inv * gamma[tid      ] + beta[tid      ];
    yr[tid + 256] = (v1 - mean) * inv * gamma[tid + 256] + beta[tid + 256];
    yr[tid + 512] = (v2 - mean) * inv * gamma[tid + 512] + beta[tid + 512];
}

// transpose all 24 weight matrices (768x768) into g_wT; z = l*6 + w
__global__ void transpose_w(const float* __restrict__ Wq, const float* __restrict__ Wk,
                            const float* __restrict__ Wv, const float* __restrict__ Wo,
                            const float* __restrict__ W1, const float* __restrict__ W2,
                            float* __restrict__ dst)
{
    __shared__ float t[32][33];
    int z = blockIdx.z;
    int l = z / 6, w = z - l * 6;
    const float* srcs[6] = {Wq, Wk, Wv, Wo, W1, W2};
    const float* src = srcs[w] + (long)l * WSZ;
    float* d = dst + (long)z * WSZ;
    int tx = threadIdx.x, ty = threadIdx.y;
    int x = blockIdx.x * 32 + tx;
    int y = blockIdx.y * 32 + ty;
    #pragma unroll
    for (int i = 0; i < 4; i++)
        t[ty + 8*i][tx] = src[(long)(y + 8*i) * DIMN + x];
    __syncthreads();
    int x2 = blockIdx.y * 32 + tx;
    int y2 = blockIdx.x * 32 + ty;
    #pragma unroll
    for (int i = 0; i < 4; i++)
        d[(long)(y2 + 8*i) * DIMN + x2] = t[tx][ty + 8*i];
}

// ================= fused flash attention v2 (fp16 mma, P in registers) =================
// grid: (16 q-tiles, 48 batch*head). block: 256 (8 warps x 16 q-rows).
// Double-buffered K/V smem: [K0 V0 K1 V1], each [64][KW2P] half2.
// Q staging area Ps after the buffers (only used at init).
#define KW2P 36      // 32 half2 + pad 4
#define PPAD 132
#define KVBUF (2 * 64 * KW2P)     // one buffer (K+V) in uint32
#define FLASH_SMEM ((2 * KVBUF + 32 * PPAD) * 4)
#define NIT (CTX / 64)

__global__ void __launch_bounds__(256, 2)
flash_attn(const float* __restrict__ Q, const float* __restrict__ Kg,
           const float* __restrict__ Vg, float* __restrict__ O)
{
    extern __shared__ uint32_t sm[];
    uint32_t* Ps = sm + 2 * KVBUF;          // [32][PPAD]

    const int tid  = threadIdx.x;
    const int wid  = tid >> 5;
    const int lane = tid & 31;
    const int g    = lane >> 2;
    const int tg   = lane & 3;
    const int mwo  = wid * 16;

    const int bh = blockIdx.y;
    const int b  = bh / HEADS, h = bh - b * HEADS;
    const long qoff  = ((long)b * CTX + blockIdx.x * 128) * INNER + h * HD;
    const long kvoff = (long)b * CTX * INNER + h * HD;

    // ---- stage Q (x 1/8) into Ps as half2 [d2][m], extract frags ----
    {
        const int m = tid >> 1, half = tid & 1;
        const float* qp = Q + qoff + (long)m * INNER + half * 32;
        #pragma unroll
        for (int i = 0; i < 8; i++) {
            float4 v = *(const float4*)(qp + 4 * i);
            int d2 = half * 16 + 2 * i;
            Ps[(d2 + 0) * PPAD + m] = cvt_h2(0.125f * v.x, 0.125f * v.y);
            Ps[(d2 + 1) * PPAD + m] = cvt_h2(0.125f * v.z, 0.125f * v.w);
        }
    }
    __syncthreads();
    uint32_t qf[4][4];
    #pragma unroll
    for (int kk = 0; kk < 4; kk++) {
        qf[kk][0] = Ps[(kk * 8 + tg) * PPAD + mwo + g];
        qf[kk][1] = Ps[(kk * 8 + tg) * PPAD + mwo + g + 8];
        qf[kk][2] = Ps[(kk * 8 + tg + 4) * PPAD + mwo + g];
        qf[kk][3] = Ps[(kk * 8 + tg + 4) * PPAD + mwo + g + 8];
    }

    float m_r[2] = {-1e30f, -1e30f};
    float l_r[2] = {0.f, 0.f};
    float acc_o[8][4];
    #pragma unroll
    for (int nt = 0; nt < 8; nt++)
        #pragma unroll
        for (int c = 0; c < 4; c++) acc_o[nt][c] = 0.f;

    // K loader: tok = tid>>2 (0..63), dq = tid&3 -> hd [dq*16, +16)
    const int ktok = tid >> 2, kdq = tid & 3;
    const float* kp0 = Kg + kvoff + (long)ktok * INNER + kdq * 16;
    // V loader: token pair tp = tid&31, dq8 = tid>>5 -> hd [dq8*8, +8)
    const int vtp = tid & 31, vdq = tid >> 5;
    const float* vp0 = Vg + kvoff + (long)(2 * vtp) * INNER + vdq * 8;

#define STS_KV(KSP, VSP, KA, V0A, V0B, V1A, V1B)                             \
    {                                                                        \
        _Pragma("unroll")                                                    \
        for (int i = 0; i < 4; i++) {                                        \
            int d2 = kdq * 8 + 2 * i;                                        \
            (KSP)[ktok * KW2P + d2 + 0] = cvt_h2((KA)[i].x, (KA)[i].y);      \
            (KSP)[ktok * KW2P + d2 + 1] = cvt_h2((KA)[i].z, (KA)[i].w);      \
        }                                                                    \
        (VSP)[(vdq * 8 + 0) * KW2P + vtp] = cvt_h2((V0A).x, (V1A).x);        \
        (VSP)[(vdq * 8 + 1) * KW2P + vtp] = cvt_h2((V0A).y, (V1A).y);        \
        (VSP)[(vdq * 8 + 2) * KW2P + vtp] = cvt_h2((V0A).z, (V1A).z);        \
        (VSP)[(vdq * 8 + 3) * KW2P + vtp] = cvt_h2((V0A).w, (V1A).w);        \
        (VSP)[(vdq * 8 + 4) * KW2P + vtp] = cvt_h2((V0B).x, (V1B).x);        \
        (VSP)[(vdq * 8 + 5) * KW2P + vtp] = cvt_h2((V0B).y, (V1B).y);        \
        (VSP)[(vdq * 8 + 6) * KW2P + vtp] = cvt_h2((V0B).z, (V1B).z);        \
        (VSP)[(vdq * 8 + 7) * KW2P + vtp] = cvt_h2((V0B).w, (V1B).w);        \
    }

    // prologue: tile 0 into buf0
    {
        float4 ka[4];
        #pragma unroll
        for (int i = 0; i < 4; i++) ka[i] = *(const float4*)(kp0 + 4 * i);
        float4 v0a = *(const float4*)(vp0);
        float4 v0b = *(const float4*)(vp0 + 4);
        float4 v1a = *(const float4*)(vp0 + INNER);
        float4 v1b = *(const float4*)(vp0 + INNER + 4);
        STS_KV(sm, sm + 64 * KW2P, ka, v0a, v0b, v1a, v1b);
    }
    __syncthreads();

    for (int it = 0; it < NIT; it++) {
        const int cur = it & 1;
        const uint32_t* Ks = sm + cur * KVBUF;
        const uint32_t* Vs = Ks + 64 * KW2P;
        const bool more = (it + 1 < NIT);
        const long joff = (long)(it + 1) * 64 * INNER;

        // prefetch next K
        float4 kpre[4];
        if (more) {
            #pragma unroll
            for (int i = 0; i < 4; i++) kpre[i] = *(const float4*)(kp0 + joff + 4 * i);
        }

        // ---- S = Q @ K^T ----
        float acc_s[8][4];
        #pragma unroll
        for (int nt = 0; nt < 8; nt++)
            #pragma unroll
            for (int c = 0; c < 4; c++) acc_s[nt][c] = 0.f;
        #pragma unroll
        for (int kk = 0; kk < 4; kk++) {
            #pragma unroll
            for (int nt = 0; nt < 8; nt++) {
                uint32_t bf[2];
                bf[0] = Ks[(nt * 8 + g) * KW2P + kk * 8 + tg];
                bf[1] = Ks[(nt * 8 + g) * KW2P + kk * 8 + tg + 4];
                mma_f16(acc_s[nt], qf[kk], bf);
            }
        }

        // prefetch next V (latency hidden under softmax)
        float4 vpre0a, vpre0b, vpre1a, vpre1b;
        if (more) {
            vpre0a = *(const float4*)(vp0 + joff);
            vpre0b = *(const float4*)(vp0 + joff + 4);
            vpre1a = *(const float4*)(vp0 + joff + INNER);
            vpre1b = *(const float4*)(vp0 + joff + INNER + 4);
        }

        // ---- online softmax; P packed directly into mma A-fragments ----
        uint32_t pf[4][4];
        #pragma unroll
        for (int r = 0; r < 2; r++) {
            float mx = -1e30f;
            #pragma unroll
            for (int nt = 0; nt < 8; nt++)
                mx = fmaxf(mx, fmaxf(acc_s[nt][2 * r], acc_s[nt][2 * r + 1]));
            mx = fmaxf(mx, __shfl_xor_sync(0xffffffffu, mx, 1));
            mx = fmaxf(mx, __shfl_xor_sync(0xffffffffu, mx, 2));
            float mn = fmaxf(m_r[r], mx);
            float alpha = __expf(m_r[r] - mn);
            m_r[r] = mn;
            float sum = 0.f;
            #pragma unroll
            for (int nt = 0; nt < 8; nt++) {
                float p0 = __expf(acc_s[nt][2 * r]     - mn);
                float p1 = __expf(acc_s[nt][2 * r + 1] - mn);
                sum += p0 + p1;
                // acc_s[2kk] r=0 -> pf[kk][0]; r=1 -> pf[kk][1]
                // acc_s[2kk+1] r=0 -> pf[kk][2]; r=1 -> pf[kk][3]
                pf[nt >> 1][(nt & 1) * 2 + r] = cvt_h2(p0, p1);
            }
            sum += __shfl_xor_sync(0xffffffffu, sum, 1);
            sum += __shfl_xor_sync(0xffffffffu, sum, 2);
            l_r[r] = alpha * l_r[r] + sum;
            #pragma unroll
            for (int nt = 0; nt < 8; nt++) {
                acc_o[nt][2 * r]     *= alpha;
                acc_o[nt][2 * r + 1] *= alpha;
            }
        }

        // ---- O += P @ V ----
        #pragma unroll
        for (int kk = 0; kk < 4; kk++) {
            #pragma unroll
            for (int nt = 0; nt < 8; nt++) {
                uint32_t bf[2];
                bf[0] = Vs[(nt * 8 + g) * KW2P + kk * 8 + tg];
                bf[1] = Vs[(nt * 8 + g) * KW2P + kk * 8 + tg + 4];
                mma_f16(acc_o[nt], pf[kk], bf);
            }
        }

        if (more) {
            uint32_t* Kn = sm + (cur ^ 1) * KVBUF;
            uint32_t* Vn = Kn + 64 * KW2P;
            STS_KV(Kn, Vn, kpre, vpre0a, vpre0b, vpre1a, vpre1b);
            __syncthreads();
        }
    }
#undef STS_KV

    // ---- write O = acc / l ----
    const float inv0 = 1.0f / l_r[0];
    const float inv1 = 1.0f / l_r[1];
    #pragma unroll
    for (int nt = 0; nt < 8; nt++) {
        float2 o0, o1;
        o0.x = acc_o[nt][0] * inv0; o0.y = acc_o[nt][1] * inv0;
        o1.x = acc_o[nt][2] * inv1; o1.y = acc_o[nt][3] * inv1;
        *(float2*)(O + qoff + (long)(mwo + g) * INNER + nt * 8 + 2 * tg) = o0;
        *(float2*)(O + qoff + (long)(mwo + g + 8) * INNER + nt * 8 + 2 * tg) = o1;
    }
}

// ================= fp16 mma.sync batched GEMM, BK=32 =================
// Smem half2 packed along k: As[k2][m], Bs[k2][n]; BK=32 -> 16 k2-rows, 2 mma rounds/stage.
#define BK 32
#define BM 128
#define SPAD 8

template<int BN_, int WROWS, bool GELU_, bool HASBIAS, bool HASRES>
__global__ void __launch_bounds__(256, 2)
mma_gemm(const float* __restrict__ A, const float* __restrict__ B,
         float* __restrict__ C, const float* __restrict__ bias,
         const float* __restrict__ residual,
         int K, int lda, int ldb, int ldc,
         long sA1, long sA2, long sB1, long sB2, long sC1, long sC2,
         int batch2, float alpha)
{
    constexpr int WCOLS = 8 / WROWS;
    constexpr int MT = (BM / WROWS) / 16;
    constexpr int NT = (BN_ / WCOLS) / 8;
    constexpr int SEGA = BM * BK / 4 / 256;   // float4 loads per thread (4)
    constexpr int SEGB = BN_ * BK / 4 / 256;

    __shared__ uint32_t As[2][BK / 2][BM + SPAD];
    __shared__ uint32_t Bs[2][BK / 2][BN_ + SPAD];

    const int z  = blockIdx.z;
    const int zo = z / batch2, zi = z - zo * batch2;
    A += zo * sA1 + zi * sA2;
    B += zo * sB1 + zi * sB2;
    const long coff = (long)zo * sC1 + (long)zi * sC2;

    const int tid  = threadIdx.x;
    const int wid  = tid >> 5;
    const int lane = tid & 31;
    const int g    = lane >> 2;
    const int tg   = lane & 3;
    const int wm   = wid % WROWS;
    const int wn   = wid / WROWS;
    const int mwo  = wm * MT * 16;
    const int nwo  = wn * NT * 8;

    const int m0 = blockIdx.y * BM;
    const int n0 = blockIdx.x * BN_;

    // loader: 8 float4 per row of 32 floats
    const float* ap[SEGA]; int arow[SEGA], acol2[SEGA];
    #pragma unroll
    for (int i = 0; i < SEGA; i++) {
        int seg = tid + 256 * i;
        arow[i]  = seg >> 3;
        acol2[i] = (seg & 7) * 2;
        ap[i] = A + (long)(m0 + arow[i]) * lda + (seg & 7) * 4;
    }
    const float* bp[SEGB]; int brow[SEGB], bcol2[SEGB];
    #pragma unroll
    for (int i = 0; i < SEGB; i++) {
        int seg = tid + 256 * i;
        brow[i]  = seg >> 3;
        bcol2[i] = (seg & 7) * 2;
        bp[i] = B + (long)(n0 + brow[i]) * ldb + (seg & 7) * 4;
    }

    float acc[MT][NT][4];
    #pragma unroll
    for (int i = 0; i < MT; i++)
        #pragma unroll
        for (int j = 0; j < NT; j++)
            #pragma unroll
            for (int k = 0; k < 4; k++) acc[i][j][k] = 0.f;

    float4 ra[SEGA], rb[SEGB];

#define STS_TILE(BUFV)                                                     \
    {                                                                      \
        _Pragma("unroll")                                                  \
        for (int i = 0; i < SEGA; i++) {                                   \
            As[BUFV][acol2[i]+0][arow[i]] = cvt_h2(ra[i].x, ra[i].y);      \
            As[BUFV][acol2[i]+1][arow[i]] = cvt_h2(ra[i].z, ra[i].w);      \
        }                                                                  \
        _Pragma("unroll")                                                  \
        for (int i = 0; i < SEGB; i++) {                                   \
            Bs[BUFV][bcol2[i]+0][brow[i]] = cvt_h2(rb[i].x, rb[i].y);      \
            Bs[BUFV][bcol2[i]+1][brow[i]] = cvt_h2(rb[i].z, rb[i].w);      \
        }                                                                  \
    }

    #pragma unroll
    for (int i = 0; i < SEGA; i++) ra[i] = *(const float4*)(ap[i]);
    #pragma unroll
    for (int i = 0; i < SEGB; i++) rb[i] = *(const float4*)(bp[i]);
    STS_TILE(0);
    __syncthreads();

    const int ntiles = K / BK;
    int buf = 0;
    for (int s = 0; s < ntiles; s++) {
        if (s + 1 < ntiles) {
            const int koff = (s + 1) * BK;
            #pragma unroll
            for (int i = 0; i < SEGA; i++) ra[i] = *(const float4*)(ap[i] + koff);
            #pragma unroll
            for (int i = 0; i < SEGB; i++) rb[i] = *(const float4*)(bp[i] + koff);
        }
        #pragma unroll
        for (int half = 0; half < 2; half++) {
            const int kb = half * 8;
            uint32_t af[MT][4];
            #pragma unroll
            for (int mt = 0; mt < MT; mt++) {
                int m = mwo + mt * 16 + g;
                af[mt][0] = As[buf][kb + tg    ][m];
                af[mt][1] = As[buf][kb + tg    ][m + 8];
                af[mt][2] = As[buf][kb + tg + 4][m];
                af[mt][3] = As[buf][kb + tg + 4][m + 8];
            }
            uint32_t bf[NT][2];
            #pragma unroll
            for (int nt = 0; nt < NT; nt++) {
                int n = nwo + nt * 8 + g;
                bf[nt][0] = Bs[buf][kb + tg    ][n];
                bf[nt][1] = Bs[buf][kb + tg + 4][n];
            }
            #pragma unroll
            for (int mt = 0; mt < MT; mt++)
                #pragma unroll
                for (int nt = 0; nt < NT; nt++)
                    mma_f16(acc[mt][nt], af[mt], bf[nt]);
        }
        if (s + 1 < ntiles) {
            __syncthreads();
            STS_TILE(buf ^ 1);
            __syncthreads();
            buf ^= 1;
        }
    }
#undef STS_TILE

    float* Cp = C + coff;
    const float* Rp = HASRES ? residual + coff : nullptr;
    #pragma unroll
    for (int mt = 0; mt < MT; mt++) {
        const long r0 = m0 + mwo + mt * 16 + g;
        const long r1 = r0 + 8;
        #pragma unroll
        for (int nt = 0; nt < NT; nt++) {
            const int cb = n0 + nwo + nt * 8 + 2 * tg;
            float2 v0, v1;
            v0.x = acc[mt][nt][0] * alpha; v0.y = acc[mt][nt][1] * alpha;
            v1.x = acc[mt][nt][2] * alpha; v1.y = acc[mt][nt][3] * alpha;
            if (HASBIAS) {
                float bx = bias[cb], by = bias[cb + 1];
                v0.x += bx; v0.y += by; v1.x += bx; v1.y += by;
            }
            if (GELU_) {
                v0.x = 0.5f * v0.x * (1.0f + erff(v0.x * 0.70710678118654752f));
                v0.y = 0.5f * v0.y * (1.0f + erff(v0.y * 0.70710678118654752f));
                v1.x = 0.5f * v1.x * (1.0f + erff(v1.x * 0.70710678118654752f));
                v1.y = 0.5f * v1.y * (1.0f + erff(v1.y * 0.70710678118654752f));
            }
            if (HASRES) {
                float2 q0 = *(const float2*)(Rp + r0 * ldc + cb);
                float2 q1 = *(const float2*)(Rp + r1 * ldc + cb);
                v0.x += q0.x; v0.y += q0.y; v1.x += q1.x; v1.y += q1.y;
            }
            *(float2*)(Cp + r0 * ldc + cb) = v0;
            *(float2*)(Cp + r1 * ldc + cb) = v1;
        }
    }
}

template<int BN_, int WROWS, bool GELU_, bool HASBIAS, bool HASRES>
static void launch_mm(const float* A, const float* B, float* C,
                      const float* bias, const float* res,
                      int M, int N, int K, int lda, int ldb, int ldc,
                      long sA1, long sA2, long sB1, long sB2, long sC1, long sC2,
                      int batch2, int nz, float alpha)
{
    dim3 grid(N / BN_, M / BM, nz);
    mma_gemm<BN_, WROWS, GELU_, HASBIAS, HASRES><<<grid, 256>>>(
        A, B, C, bias, res, K, lda, ldb, ldc,
        sA1, sA2, sB1, sB2, sC1, sC2, batch2, alpha);
}

extern "C" void kernel_launch(void* const* d_in, const int* in_sizes, int n_in,
                              void* d_out, int out_size)
{
    const float* x     = (const float*)d_in[0];
    const float* pos   = (const float*)d_in[1];
    const float* ln1_g = (const float*)d_in[2];
    const float* ln1_b = (const float*)d_in[3];
    const float* Wq    = (const float*)d_in[4];
    const float* Wk    = (const float*)d_in[5];
    const float* Wv    = (const float*)d_in[6];
    const float* Wo    = (const float*)d_in[7];
    const float* ln2_g = (const float*)d_in[8];
    const float* ln2_b = (const float*)d_in[9];
    const float* W1    = (const float*)d_in[10];
    const float* b1    = (const float*)d_in[11];
    const float* W2    = (const float*)d_in[12];
    const float* b2    = (const float*)d_in[13];

    float *gx, *gh, *gqkv, *go, *gf, *gwT;
    cudaGetSymbolAddress((void**)&gx,  g_x);
    cudaGetSymbolAddress((void**)&gh,  g_h);
    cudaGetSymbolAddress((void**)&gqkv,g_qkv);
    cudaGetSymbolAddress((void**)&go,  g_o);
    cudaGetSymbolAddress((void**)&gf,  g_f);
    cudaGetSymbolAddress((void**)&gwT, g_wT);

    float* gq = gqkv;
    float* gk = gqkv + (long)MTOK * INNER;
    float* gv = gqkv + 2L * MTOK * INNER;

    cudaFuncSetAttribute((const void*)flash_attn,
                         cudaFuncAttributeMaxDynamicSharedMemorySize, FLASH_SMEM);

    {
        dim3 grid(DIMN / 32, DIMN / 32, DEPTH * 6);
        transpose_w<<<grid, dim3(32, 8)>>>(Wq, Wk, Wv, Wo, W1, W2, gwT);
    }

    add_pos_kernel<<<(MTOK * DIMN) / 256, 256>>>(x, pos, gx);

    for (int l = 0; l < DEPTH; l++) {
        const float* wqT = gwT + (long)(l * 6 + 0) * WSZ;
        const float* woT = gwT + (long)(l * 6 + 3) * WSZ;
        const float* w1T = gwT + (long)(l * 6 + 4) * WSZ;
        const float* w2T = gwT + (long)(l * 6 + 5) * WSZ;
        const float* l1g = ln1_g + l * DIMN, *l1b = ln1_b + l * DIMN;
        const float* l2g = ln2_g + l * DIMN, *l2b = ln2_b + l * DIMN;
        const float* bb1 = b1 + l * DIMN,   *bb2 = b2 + l * DIMN;

        // --- attention
        layernorm_kernel<<<MTOK, 256>>>(gx, gh, l1g, l1b);

        // fused QKV projection
        launch_mm<128, 2, false, false, false>(
            gh, wqT, gqkv, nullptr, nullptr,
            MTOK, INNER, DIMN, DIMN, DIMN, INNER,
            0, 0, WSZ, 0, (long)MTOK * INNER, 0, 1, 3, 1.0f);

        // fused flash attention
        flash_attn<<<dim3(CTX / 128, BATCH * HEADS), 256, FLASH_SMEM>>>(gq, gk, gv, go);

        // x = x + O @ Wo
        launch_mm<128, 2, false, false, true>(
            go, woT, gx, nullptr, gx,
            MTOK, DIMN, INNER, INNER, INNER, DIMN,
            0, 0, 0, 0, 0, 0, 1, 1, 1.0f);

        // --- FFN
        layernorm_kernel<<<MTOK, 256>>>(gx, gh, l2g, l2b);

        launch_mm<128, 2, true, true, false>(
            gh, w1T, gf, bb1, nullptr,
            MTOK, DIMN, DIMN, DIMN, DIMN, DIMN,
            0, 0, 0, 0, 0, 0, 1, 1, 1.0f);

        float* cout = (l == DEPTH - 1) ? (float*)d_out : gx;
        launch_mm<128, 2, false, true, true>(
            gf, w2T, cout, bb2, gx,
            MTOK, DIMN, DIMN, DIMN, DIMN, DIMN,
            0, 0, 0, 0, 0, 0, 1, 1, 1.0f);
    }
}

// round 8
// speedup vs baseline: 10.4869x; 1.7411x over previous
#include <cuda_runtime.h>
#include <cuda_fp16.h>
#include <math.h>
#include <stdint.h>

#define DEPTH 4
#define DIMN  768
#define HEADS 12
#define HD    64
#define CTX   2048
#define BATCH 4
#define MTOK  (BATCH*CTX)          // 8192
#define INNER (HEADS*HD)           // 768
#define WSZ   ((long)DIMN*DIMN)

// ---------------- scratch (device globals; no allocation) ----------------
__device__ __align__(128) float  g_x  [MTOK*DIMN];             // residual (fp32)
__device__ __align__(128) __half g_h  [MTOK*DIMN];             // LN out
__device__ __align__(128) __half g_qkv[3L*MTOK*INNER];
__device__ __align__(128) __half g_o  [MTOK*INNER];
__device__ __align__(128) __half g_f  [MTOK*DIMN];
__device__ __align__(128) __half g_wT [24L*DIMN*DIMN];         // K-major weights, fp16

__device__ __forceinline__ uint32_t cvt_h2(float lo, float hi) {
    __half2 h = __floats2half2_rn(lo, hi);
    return *(uint32_t*)&h;
}
__device__ __forceinline__ uint32_t smem_u32(const void* p) {
    uint32_t a;
    asm("{ .reg .u64 t; cvta.to.shared.u64 t, %1; cvt.u32.u64 %0, t; }" : "=r"(a) : "l"(p));
    return a;
}
__device__ __forceinline__ void mma_f16(float* c, const uint32_t* a, const uint32_t* b) {
    asm volatile(
        "mma.sync.aligned.m16n8k16.row.col.f32.f16.f16.f32 "
        "{%0,%1,%2,%3}, {%4,%5,%6,%7}, {%8,%9}, {%0,%1,%2,%3};"
        : "+f"(c[0]), "+f"(c[1]), "+f"(c[2]), "+f"(c[3])
        : "r"(a[0]), "r"(a[1]), "r"(a[2]), "r"(a[3]), "r"(b[0]), "r"(b[1]));
}
__device__ __forceinline__ void ldm_x4(uint32_t* r, uint32_t addr) {
    asm volatile("ldmatrix.sync.aligned.m8n8.x4.shared.b16 {%0,%1,%2,%3}, [%4];"
                 : "=r"(r[0]), "=r"(r[1]), "=r"(r[2]), "=r"(r[3]) : "r"(addr));
}
__device__ __forceinline__ void ldm_x4_t(uint32_t* r, uint32_t addr) {
    asm volatile("ldmatrix.sync.aligned.m8n8.x4.trans.shared.b16 {%0,%1,%2,%3}, [%4];"
                 : "=r"(r[0]), "=r"(r[1]), "=r"(r[2]), "=r"(r[3]) : "r"(addr));
}

// ================= elementwise kernels =================
__global__ void add_pos_kernel(const float* __restrict__ x,
                               const float* __restrict__ pos,
                               float* __restrict__ y)
{
    long i = (long)blockIdx.x * blockDim.x + threadIdx.x;
    long posn = i % ((long)CTX * DIMN);
    y[i] = x[i] + pos[posn];
}

__global__ void layernorm_kernel(const float* __restrict__ x, __half* __restrict__ y,
                                 const float* __restrict__ gamma,
                                 const float* __restrict__ beta)
{
    __shared__ float ss[8], qq[8];
    int row = blockIdx.x;
    int tid = threadIdx.x;
    const float* xr = x + (long)row * DIMN;
    float v0 = xr[tid], v1 = xr[tid + 256], v2 = xr[tid + 512];
    float s = v0 + v1 + v2;
    float q = v0*v0 + v1*v1 + v2*v2;
    #pragma unroll
    for (int o = 16; o > 0; o >>= 1) {
        s += __shfl_xor_sync(0xffffffffu, s, o);
        q += __shfl_xor_sync(0xffffffffu, q, o);
    }
    int wid = tid >> 5, lane = tid & 31;
    if (lane == 0) { ss[wid] = s; qq[wid] = q; }
    __syncthreads();
    if (tid == 0) {
        float ts = 0.f, tq = 0.f;
        #pragma unroll
        for (int i = 0; i < 8; i++) { ts += ss[i]; tq += qq[i]; }
        ss[0] = ts; qq[0] = tq;
    }
    __syncthreads();
    float mean = ss[0] * (1.0f / DIMN);
    float var  = qq[0] * (1.0f / DIMN) - mean * mean;
    float inv  = rsqrtf(var + 1e-5f);
    __half* yr = y + (long)row * DIMN;
    yr[tid      ] = __float2half((v0 - mean) * inv * gamma[tid      ] + beta[tid      ]);
    yr[tid + 256] = __float2half((v1 - mean) * inv * gamma[tid + 256] + beta[tid + 256]);
    yr[tid + 512] = __float2half((v2 - mean) * inv * gamma[tid + 512] + beta[tid + 512]);
}

// transpose all 24 weight matrices (768x768) into g_wT (half); z = l*6 + w
__global__ void transpose_w(const float* __restrict__ Wq, const float* __restrict__ Wk,
                            const float* __restrict__ Wv, const float* __restrict__ Wo,
                            const float* __restrict__ W1, const float* __restrict__ W2,
                            __half* __restrict__ dst)
{
    __shared__ float t[32][33];
    int z = blockIdx.z;
    int l = z / 6, w = z - l * 6;
    const float* srcs[6] = {Wq, Wk, Wv, Wo, W1, W2};
    const float* src = srcs[w] + (long)l * WSZ;
    __half* d = dst + (long)z * WSZ;
    int tx = threadIdx.x, ty = threadIdx.y;
    int x = blockIdx.x * 32 + tx;
    int y = blockIdx.y * 32 + ty;
    #pragma unroll
    for (int i = 0; i < 4; i++)
        t[ty + 8*i][tx] = src[(long)(y + 8*i) * DIMN + x];
    __syncthreads();
    int x2 = blockIdx.y * 32 + tx;
    int y2 = blockIdx.x * 32 + ty;
    #pragma unroll
    for (int i = 0; i < 4; i++)
        d[(long)(y2 + 8*i) * DIMN + x2] = __float2half(t[tx][ty + 8*i]);
}

// ================= fused flash attention v3 (fp16 gmem + ldmatrix) =================
// grid: (16 q-tiles, 48 batch*head). block: 256 (8 warps x 16 q-rows).
// K/V tiles [64 tok][72 halfs] (pad 72: (row+chunk)%8 distinct -> conflict-free).
// Double buffered; Q staged once over buffer 0 region as [128][72].
#define FROW 72
#define NIT (CTX / 64)

__global__ void __launch_bounds__(256, 2)
flash_attn(const __half* __restrict__ Q, const __half* __restrict__ Kg,
           const __half* __restrict__ Vg, __half* __restrict__ O)
{
    __shared__ __align__(16) __half KV[2][2][64][FROW];   // [buf][K/V][tok][d]

    const int tid  = threadIdx.x;
    const int wid  = tid >> 5;
    const int lane = tid & 31;
    const int g    = lane >> 2;
    const int tg   = lane & 3;
    const int mwo  = wid * 16;

    const int grp  = lane >> 3;            // ldmatrix address group 0..3
    const int l7   = lane & 7;
    const int rowo = (grp & 1) * 8 + l7;   // row offset within 16-row block
    const int colo = (grp >> 1);           // 16B-chunk offset within k16

    const int bh = blockIdx.y;
    const int b  = bh / HEADS, h = bh - b * HEADS;
    const long qoff  = ((long)b * CTX + blockIdx.x * 128) * INNER + h * HD;
    const long kvoff = (long)b * CTX * INNER + h * HD;

    const uint32_t smbase = smem_u32(&KV[0][0][0][0]);
    // per-lane ldmatrix base offset (bytes): rowo*FROW + colo*8 halfs
    const uint32_t lmoff = (uint32_t)(rowo * FROW + colo * 8) * 2;

    // ---- stage Q over buffer-0 region as [m 0..127][FROW], extract frags ----
    {
        __half* Qst = &KV[0][0][0][0];
        #pragma unroll
        for (int i = 0; i < 4; i++) {
            int idx = tid + 256 * i;
            int r = idx >> 3, c = idx & 7;
            *(uint4*)(Qst + r * FROW + c * 8) =
                *(const uint4*)(Q + qoff + (long)r * INNER + c * 8);
        }
    }
    __syncthreads();
    uint32_t qf[4][4];
    {
        const uint32_t qb = smbase + lmoff + (uint32_t)(mwo * FROW) * 2;
        #pragma unroll
        for (int kk = 0; kk < 4; kk++)
            ldm_x4(qf[kk], qb + kk * 32);        // chunk kk*2 (+colo) -> +kk*16 halfs
    }
    __syncthreads();

    float m_r[2] = {-1e30f, -1e30f};
    float l_r[2] = {0.f, 0.f};
    float acc_o[8][4];
    #pragma unroll
    for (int nt = 0; nt < 8; nt++)
        #pragma unroll
        for (int c = 0; c < 4; c++) acc_o[nt][c] = 0.f;

    // loader mapping: idx -> row=idx>>3 (0..63), c=idx&7; two chunks each for K and V
    const int lr0 = tid >> 3, lc0 = (tid & 7) * 8;
    const int lr1 = lr0 + 32;
    const __half* kp0 = Kg + kvoff + (long)lr0 * INNER + lc0;
    const __half* kp1 = Kg + kvoff + (long)lr1 * INNER + lc0;
    const __half* vp0 = Vg + kvoff + (long)lr0 * INNER + lc0;
    const __half* vp1 = Vg + kvoff + (long)lr1 * INNER + lc0;

    // prologue: tile 0 -> buf 0
    {
        uint4 k0 = *(const uint4*)kp0, k1 = *(const uint4*)kp1;
        uint4 v0 = *(const uint4*)vp0, v1 = *(const uint4*)vp1;
        *(uint4*)(&KV[0][0][lr0][lc0]) = k0;
        *(uint4*)(&KV[0][0][lr1][lc0]) = k1;
        *(uint4*)(&KV[0][1][lr0][lc0]) = v0;
        *(uint4*)(&KV[0][1][lr1][lc0]) = v1;
    }
    __syncthreads();

    const uint32_t KBUF = 64 * FROW * 2;       // bytes per K (or V) tile

    for (int it = 0; it < NIT; it++) {
        const int cur = it & 1;
        const uint32_t kb = smbase + cur * 2 * KBUF + lmoff;
        const uint32_t vb = kb + KBUF;
        const bool more = (it + 1 < NIT);
        const long joff = (long)(it + 1) * 64 * INNER;

        uint4 kpre0, kpre1;
        if (more) { kpre0 = *(const uint4*)(kp0 + joff); kpre1 = *(const uint4*)(kp1 + joff); }

        // ---- S = Q @ K^T ----
        float acc_s[8][4];
        #pragma unroll
        for (int nt = 0; nt < 8; nt++)
            #pragma unroll
            for (int c = 0; c < 4; c++) acc_s[nt][c] = 0.f;
        #pragma unroll
        for (int kk = 0; kk < 4; kk++) {
            #pragma unroll
            for (int j = 0; j < 4; j++) {
                uint32_t r[4];
                // rows tok j*16+rowo, chunk kk*2+colo
                ldm_x4(r, kb + (uint32_t)(j * 16 * FROW) * 2 + kk * 32);
                uint32_t b0[2] = {r[0], r[2]};   // nt = 2j
                uint32_t b1[2] = {r[1], r[3]};   // nt = 2j+1
                mma_f16(acc_s[2*j],     qf[kk], b0);
                mma_f16(acc_s[2*j + 1], qf[kk], b1);
            }
        }

        uint4 vpre0, vpre1;
        if (more) { vpre0 = *(const uint4*)(vp0 + joff); vpre1 = *(const uint4*)(vp1 + joff); }

        // ---- online softmax (scale 1/8 folded into exp args) ----
        uint32_t pf[4][4];
        #pragma unroll
        for (int r = 0; r < 2; r++) {
            float mx = -1e30f;
            #pragma unroll
            for (int nt = 0; nt < 8; nt++)
                mx = fmaxf(mx, fmaxf(acc_s[nt][2 * r], acc_s[nt][2 * r + 1]));
            mx = fmaxf(mx, __shfl_xor_sync(0xffffffffu, mx, 1));
            mx = fmaxf(mx, __shfl_xor_sync(0xffffffffu, mx, 2));
            float mn = fmaxf(m_r[r], mx);
            float alpha = __expf((m_r[r] - mn) * 0.125f);
            m_r[r] = mn;
            float sum = 0.f;
            #pragma unroll
            for (int nt = 0; nt < 8; nt++) {
                float p0 = __expf((acc_s[nt][2 * r]     - mn) * 0.125f);
                float p1 = __expf((acc_s[nt][2 * r + 1] - mn) * 0.125f);
                sum += p0 + p1;
                pf[nt >> 1][(nt & 1) * 2 + r] = cvt_h2(p0, p1);
            }
            sum += __shfl_xor_sync(0xffffffffu, sum, 1);
            sum += __shfl_xor_sync(0xffffffffu, sum, 2);
            l_r[r] = alpha * l_r[r] + sum;
            #pragma unroll
            for (int nt = 0; nt < 8; nt++) {
                acc_o[nt][2 * r]     *= alpha;
                acc_o[nt][2 * r + 1] *= alpha;
            }
        }

        // ---- O += P @ V  (V frags via ldmatrix.trans on [tok][d]) ----
        #pragma unroll
        for (int kk = 0; kk < 4; kk++) {
            uint32_t bf[8][2];
            #pragma unroll
            for (int j = 0; j < 4; j++) {
                uint32_t r[4];
                // rows tok kk*16+rowo, chunk j*2+colo
                ldm_x4_t(r, vb + (uint32_t)(kk * 16 * FROW) * 2 + j * 32);
                bf[2*j][0]     = r[0]; bf[2*j][1]     = r[1];
                bf[2*j + 1][0] = r[2]; bf[2*j + 1][1] = r[3];
            }
            #pragma unroll
            for (int nt = 0; nt < 8; nt++)
                mma_f16(acc_o[nt], pf[kk], bf[nt]);
        }

        if (more) {
            const int nb = cur ^ 1;
            *(uint4*)(&KV[nb][0][lr0][lc0]) = kpre0;
            *(uint4*)(&KV[nb][0][lr1][lc0]) = kpre1;
            *(uint4*)(&KV[nb][1][lr0][lc0]) = vpre0;
            *(uint4*)(&KV[nb][1][lr1][lc0]) = vpre1;
            __syncthreads();
        }
    }

    // ---- write O = acc / l (fp16) ----
    const float inv0 = 1.0f / l_r[0];
    const float inv1 = 1.0f / l_r[1];
    #pragma unroll
    for (int nt = 0; nt < 8; nt++) {
        uint32_t o0 = cvt_h2(acc_o[nt][0] * inv0, acc_o[nt][1] * inv0);
        uint32_t o1 = cvt_h2(acc_o[nt][2] * inv1, acc_o[nt][3] * inv1);
        *(uint32_t*)(O + qoff + (long)(mwo + g) * INNER + nt * 8 + 2 * tg) = o0;
        *(uint32_t*)(O + qoff + (long)(mwo + g + 8) * INNER + nt * 8 + 2 * tg) = o1;
    }
}

// ================= fp16 GEMM with ldmatrix (dense projections) =================
// C[M,768] = A[M,768](half) @ B[768,768]^T(half,K-major) ; epilogue flags.
// Block 128x128, 8 warps 2x4, warp tile 64x32 (MT=4, NT=4), BK=32.
// Smem rows padded to 40 halfs (5 chunks, coprime 8 -> ldmatrix conflict-free).
#define BKD 32
#define AROW 40

template<bool GELU_, bool HASBIAS, bool HASRES, bool OUTHALF>
__global__ void __launch_bounds__(256, 2)
mma_gemm(const __half* __restrict__ A, const __half* __restrict__ B,
         void* __restrict__ Cv, const float* __restrict__ bias,
         const float* __restrict__ residual,
         int K, long sB1, long sC1, float alpha)
{
    __shared__ __align__(16) __half As[2][128][AROW];
    __shared__ __align__(16) __half Bs[2][128][AROW];

    const int zo = blockIdx.z;
    B += zo * sB1;
    const long coff = (long)zo * sC1;

    const int tid  = threadIdx.x;
    const int wid  = tid >> 5;
    const int lane = tid & 31;
    const int g    = lane >> 2;
    const int tg   = lane & 3;
    const int wm   = wid & 1;
    const int wn   = wid >> 1;
    const int mwo  = wm * 64;
    const int nwo  = wn * 32;

    const int grp  = lane >> 3;
    const int l7   = lane & 7;
    const int rowo = (grp & 1) * 8 + l7;
    const int colo = (grp >> 1);

    const int m0 = blockIdx.y * 128;
    const int n0 = blockIdx.x * 128;

    const uint32_t abase = smem_u32(&As[0][0][0]);
    const uint32_t bbase = smem_u32(&Bs[0][0][0]);
    const uint32_t lma = (uint32_t)((mwo + rowo) * AROW + colo * 8) * 2;
    const uint32_t lmb = (uint32_t)((nwo + rowo) * AROW + colo * 8) * 2;
    const uint32_t BUFB = 128 * AROW * 2;     // bytes per buffer

    // loader: idx -> row=idx>>2 (0..127), chunk=idx&3 (16B = 8 halfs)
    const int lrow = tid >> 1;                 // 2 chunks/thread: (tid,0/1),(tid+256 ...)
    // simpler: idx0 = tid, idx1 = tid+256
    const int r0_ = tid >> 2, c0_ = (tid & 3) * 8;
    const int r1_ = r0_ + 64;
    (void)lrow;
    const __half* ap0 = A + (long)(m0 + r0_) * DIMN + c0_;
    const __half* ap1 = A + (long)(m0 + r1_) * DIMN + c0_;
    const __half* bp0 = B + (long)(n0 + r0_) * DIMN + c0_;
    const __half* bp1 = B + (long)(n0 + r1_) * DIMN + c0_;

    float acc[4][4][4];
    #pragma unroll
    for (int i = 0; i < 4; i++)
        #pragma unroll
        for (int j = 0; j < 4; j++)
            #pragma unroll
            for (int k = 0; k < 4; k++) acc[i][j][k] = 0.f;

    uint4 ra0, ra1, rb0, rb1;

#define STS_TILE(BUFV)                                                  \
    {                                                                   \
        *(uint4*)(&As[BUFV][r0_][c0_]) = ra0;                           \
        *(uint4*)(&As[BUFV][r1_][c0_]) = ra1;                           \
        *(uint4*)(&Bs[BUFV][r0_][c0_]) = rb0;                           \
        *(uint4*)(&Bs[BUFV][r1_][c0_]) = rb1;                           \
    }

    ra0 = *(const uint4*)ap0; ra1 = *(const uint4*)ap1;
    rb0 = *(const uint4*)bp0; rb1 = *(const uint4*)bp1;
    STS_TILE(0);
    __syncthreads();

    const int ntiles = K / BKD;
    int buf = 0;
    for (int s = 0; s < ntiles; s++) {
        if (s + 1 < ntiles) {
            const int koff = (s + 1) * BKD;
            ra0 = *(const uint4*)(ap0 + koff); ra1 = *(const uint4*)(ap1 + koff);
            rb0 = *(const uint4*)(bp0 + koff); rb1 = *(const uint4*)(bp1 + koff);
        }
        #pragma unroll
        for (int half = 0; half < 2; half++) {
            const uint32_t koffb = half * 32;          // 16 halfs = 32 bytes
            uint32_t af[4][4];
            #pragma unroll
            for (int mt = 0; mt < 4; mt++)
                ldm_x4(af[mt], abase + buf * BUFB + lma +
                               (uint32_t)(mt * 16 * AROW) * 2 + koffb);
            uint32_t bf[4][2];
            #pragma unroll
            for (int j = 0; j < 2; j++) {
                uint32_t r[4];
                ldm_x4(r, bbase + buf * BUFB + lmb +
                          (uint32_t)(j * 16 * AROW) * 2 + koffb);
                bf[2*j][0]     = r[0]; bf[2*j][1]     = r[2];
                bf[2*j + 1][0] = r[1]; bf[2*j + 1][1] = r[3];
            }
            #pragma unroll
            for (int mt = 0; mt < 4; mt++)
                #pragma unroll
                for (int nt = 0; nt < 4; nt++)
                    mma_f16(acc[mt][nt], af[mt], bf[nt]);
        }
        if (s + 1 < ntiles) {
            __syncthreads();
            STS_TILE(buf ^ 1);
            __syncthreads();
            buf ^= 1;
        }
    }
#undef STS_TILE

    // ---- epilogue ----
    #pragma unroll
    for (int mt = 0; mt < 4; mt++) {
        const long r0 = m0 + mwo + mt * 16 + g;
        const long r1 = r0 + 8;
        #pragma unroll
        for (int nt = 0; nt < 4; nt++) {
            const int cb = n0 + nwo + nt * 8 + 2 * tg;
            float2 v0, v1;
            v0.x = acc[mt][nt][0] * alpha; v0.y = acc[mt][nt][1] * alpha;
            v1.x = acc[mt][nt][2] * alpha; v1.y = acc[mt][nt][3] * alpha;
            if (HASBIAS) {
                float bx = bias[cb], by = bias[cb + 1];
                v0.x += bx; v0.y += by; v1.x += bx; v1.y += by;
            }
            if (GELU_) {
                v0.x = 0.5f * v0.x * (1.0f + erff(v0.x * 0.70710678118654752f));
                v0.y = 0.5f * v0.y * (1.0f + erff(v0.y * 0.70710678118654752f));
                v1.x = 0.5f * v1.x * (1.0f + erff(v1.x * 0.70710678118654752f));
                v1.y = 0.5f * v1.y * (1.0f + erff(v1.y * 0.70710678118654752f));
            }
            if (OUTHALF) {
                __half* Cp = (__half*)Cv + coff;
                *(uint32_t*)(Cp + r0 * DIMN + cb) = cvt_h2(v0.x, v0.y);
                *(uint32_t*)(Cp + r1 * DIMN + cb) = cvt_h2(v1.x, v1.y);
            } else {
                float* Cp = (float*)Cv + coff;
                if (HASRES) {
                    const float* Rp = residual + coff;
                    float2 q0 = *(const float2*)(Rp + r0 * DIMN + cb);
                    float2 q1 = *(const float2*)(Rp + r1 * DIMN + cb);
                    v0.x += q0.x; v0.y += q0.y; v1.x += q1.x; v1.y += q1.y;
                }
                *(float2*)(Cp + r0 * DIMN + cb) = v0;
                *(float2*)(Cp + r1 * DIMN + cb) = v1;
            }
        }
    }
}

template<bool GELU_, bool HASBIAS, bool HASRES, bool OUTHALF>
static void launch_mm(const __half* A, const __half* B, void* C,
                      const float* bias, const float* res,
                      long sB1, long sC1, int nz, float alpha)
{
    dim3 grid(DIMN / 128, MTOK / 128, nz);
    mma_gemm<GELU_, HASBIAS, HASRES, OUTHALF><<<grid, 256>>>(
        A, B, C, bias, res, DIMN, sB1, sC1, alpha);
}

extern "C" void kernel_launch(void* const* d_in, const int* in_sizes, int n_in,
                              void* d_out, int out_size)
{
    const float* x     = (const float*)d_in[0];
    const float* pos   = (const float*)d_in[1];
    const float* ln1_g = (const float*)d_in[2];
    const float* ln1_b = (const float*)d_in[3];
    const float* Wq    = (const float*)d_in[4];
    const float* Wk    = (const float*)d_in[5];
    const float* Wv    = (const float*)d_in[6];
    const float* Wo    = (const float*)d_in[7];
    const float* ln2_g = (const float*)d_in[8];
    const float* ln2_b = (const float*)d_in[9];
    const float* W1    = (const float*)d_in[10];
    const float* b1    = (const float*)d_in[11];
    const float* W2    = (const float*)d_in[12];
    const float* b2    = (const float*)d_in[13];

    float  *gx;
    __half *gh, *gqkv, *go, *gf, *gwT;
    cudaGetSymbolAddress((void**)&gx,   g_x);
    cudaGetSymbolAddress((void**)&gh,   g_h);
    cudaGetSymbolAddress((void**)&gqkv, g_qkv);
    cudaGetSymbolAddress((void**)&go,   g_o);
    cudaGetSymbolAddress((void**)&gf,   g_f);
    cudaGetSymbolAddress((void**)&gwT,  g_wT);

    __half* gq = gqkv;
    __half* gk = gqkv + (long)MTOK * INNER;
    __half* gv = gqkv + 2L * MTOK * INNER;

    {
        dim3 grid(DIMN / 32, DIMN / 32, DEPTH * 6);
        transpose_w<<<grid, dim3(32, 8)>>>(Wq, Wk, Wv, Wo, W1, W2, gwT);
    }

    add_pos_kernel<<<(MTOK * DIMN) / 256, 256>>>(x, pos, gx);

    for (int l = 0; l < DEPTH; l++) {
        const __half* wqT = gwT + (long)(l * 6 + 0) * WSZ;
        const __half* woT = gwT + (long)(l * 6 + 3) * WSZ;
        const __half* w1T = gwT + (long)(l * 6 + 4) * WSZ;
        const __half* w2T = gwT + (long)(l * 6 + 5) * WSZ;
        const float* l1g = ln1_g + l * DIMN, *l1b = ln1_b + l * DIMN;
        const float* l2g = ln2_g + l * DIMN, *l2b = ln2_b + l * DIMN;
        const float* bb1 = b1 + l * DIMN,   *bb2 = b2 + l * DIMN;

        // --- attention
        layernorm_kernel<<<MTOK, 256>>>(gx, gh, l1g, l1b);

        // fused QKV projection -> half (z selects wq/wk/wv)
        launch_mm<false, false, false, true>(
            gh, wqT, gqkv, nullptr, nullptr,
            WSZ, (long)MTOK * INNER, 3, 1.0f);

        // fused flash attention -> half O
        flash_attn<<<dim3(CTX / 128, BATCH * HEADS), 256>>>(gq, gk, gv, go);

        // x = x + O @ Wo (fp32 out + residual)
        launch_mm<false, false, true, false>(
            go, woT, gx, nullptr, gx, 0, 0, 1, 1.0f);

        // --- FFN
        layernorm_kernel<<<MTOK, 256>>>(gx, gh, l2g, l2b);

        launch_mm<true, true, false, true>(
            gh, w1T, gf, bb1, nullptr, 0, 0, 1, 1.0f);

        float* cout = (l == DEPTH - 1) ? (float*)d_out : gx;
        launch_mm<false, true, true, false>(
            gf, w2T, cout, bb2, gx, 0, 0, 1, 1.0f);
    }
}

// round 9
// speedup vs baseline: 11.2674x; 1.0744x over previous
#include <cuda_runtime.h>
#include <cuda_fp16.h>
#include <math.h>
#include <stdint.h>

#define DEPTH 4
#define DIMN  768
#define HEADS 12
#define HD    64
#define CTX   2048
#define BATCH 4
#define MTOK  (BATCH*CTX)          // 8192
#define INNER (HEADS*HD)           // 768
#define WSZ   ((long)DIMN*DIMN)

// ---------------- scratch (device globals; no allocation) ----------------
__device__ __align__(128) float  g_x  [MTOK*DIMN];             // residual (fp32)
__device__ __align__(128) __half g_h  [MTOK*DIMN];             // LN out
__device__ __align__(128) __half g_qkv[3L*MTOK*INNER];
__device__ __align__(128) __half g_o  [MTOK*INNER];
__device__ __align__(128) __half g_f  [MTOK*DIMN];
__device__ __align__(128) __half g_wT [24L*DIMN*DIMN];         // K-major weights, fp16

__device__ __forceinline__ uint32_t cvt_h2(float lo, float hi) {
    __half2 h = __floats2half2_rn(lo, hi);
    return *(uint32_t*)&h;
}
__device__ __forceinline__ uint32_t smem_u32(const void* p) {
    uint32_t a;
    asm("{ .reg .u64 t; cvta.to.shared.u64 t, %1; cvt.u32.u64 %0, t; }" : "=r"(a) : "l"(p));
    return a;
}
__device__ __forceinline__ void mma_f16(float* c, const uint32_t* a, const uint32_t* b) {
    asm volatile(
        "mma.sync.aligned.m16n8k16.row.col.f32.f16.f16.f32 "
        "{%0,%1,%2,%3}, {%4,%5,%6,%7}, {%8,%9}, {%0,%1,%2,%3};"
        : "+f"(c[0]), "+f"(c[1]), "+f"(c[2]), "+f"(c[3])
        : "r"(a[0]), "r"(a[1]), "r"(a[2]), "r"(a[3]), "r"(b[0]), "r"(b[1]));
}
__device__ __forceinline__ void ldm_x4(uint32_t* r, uint32_t addr) {
    asm volatile("ldmatrix.sync.aligned.m8n8.x4.shared.b16 {%0,%1,%2,%3}, [%4];"
                 : "=r"(r[0]), "=r"(r[1]), "=r"(r[2]), "=r"(r[3]) : "r"(addr));
}
__device__ __forceinline__ void ldm_x4_t(uint32_t* r, uint32_t addr) {
    asm volatile("ldmatrix.sync.aligned.m8n8.x4.trans.shared.b16 {%0,%1,%2,%3}, [%4];"
                 : "=r"(r[0]), "=r"(r[1]), "=r"(r[2]), "=r"(r[3]) : "r"(addr));
}
__device__ __forceinline__ void cp16(uint32_t s, const void* g) {
    asm volatile("cp.async.cg.shared.global [%0], [%1], 16;" :: "r"(s), "l"(g));
}
#define CP_COMMIT() asm volatile("cp.async.commit_group;" ::: "memory")
#define CP_WAIT1()  asm volatile("cp.async.wait_group 1;" ::: "memory")

// ================= elementwise kernels =================
__global__ void add_pos_kernel(const float* __restrict__ x,
                               const float* __restrict__ pos,
                               float* __restrict__ y)
{
    long i = (long)blockIdx.x * blockDim.x + threadIdx.x;
    long posn = i % ((long)CTX * DIMN);
    y[i] = x[i] + pos[posn];
}

__global__ void layernorm_kernel(const float* __restrict__ x, __half* __restrict__ y,
                                 const float* __restrict__ gamma,
                                 const float* __restrict__ beta)
{
    __shared__ float ss[8], qq[8];
    int row = blockIdx.x;
    int tid = threadIdx.x;
    const float* xr = x + (long)row * DIMN;
    float v0 = xr[tid], v1 = xr[tid + 256], v2 = xr[tid + 512];
    float s = v0 + v1 + v2;
    float q = v0*v0 + v1*v1 + v2*v2;
    #pragma unroll
    for (int o = 16; o > 0; o >>= 1) {
        s += __shfl_xor_sync(0xffffffffu, s, o);
        q += __shfl_xor_sync(0xffffffffu, q, o);
    }
    int wid = tid >> 5, lane = tid & 31;
    if (lane == 0) { ss[wid] = s; qq[wid] = q; }
    __syncthreads();
    if (tid == 0) {
        float ts = 0.f, tq = 0.f;
        #pragma unroll
        for (int i = 0; i < 8; i++) { ts += ss[i]; tq += qq[i]; }
        ss[0] = ts; qq[0] = tq;
    }
    __syncthreads();
    float mean = ss[0] * (1.0f / DIMN);
    float var  = qq[0] * (1.0f / DIMN) - mean * mean;
    float inv  = rsqrtf(var + 1e-5f);
    __half* yr = y + (long)row * DIMN;
    yr[tid      ] = __float2half((v0 - mean) * inv * gamma[tid      ] + beta[tid      ]);
    yr[tid + 256] = __float2half((v1 - mean) * inv * gamma[tid + 256] + beta[tid + 256]);
    yr[tid + 512] = __float2half((v2 - mean) * inv * gamma[tid + 512] + beta[tid + 512]);
}

// transpose all 24 weight matrices (768x768) into g_wT (half); z = l*6 + w
__global__ void transpose_w(const float* __restrict__ Wq, const float* __restrict__ Wk,
                            const float* __restrict__ Wv, const float* __restrict__ Wo,
                            const float* __restrict__ W1, const float* __restrict__ W2,
                            __half* __restrict__ dst)
{
    __shared__ float t[32][33];
    int z = blockIdx.z;
    int l = z / 6, w = z - l * 6;
    const float* srcs[6] = {Wq, Wk, Wv, Wo, W1, W2};
    const float* src = srcs[w] + (long)l * WSZ;
    __half* d = dst + (long)z * WSZ;
    int tx = threadIdx.x, ty = threadIdx.y;
    int x = blockIdx.x * 32 + tx;
    int y = blockIdx.y * 32 + ty;
    #pragma unroll
    for (int i = 0; i < 4; i++)
        t[ty + 8*i][tx] = src[(long)(y + 8*i) * DIMN + x];
    __syncthreads();
    int x2 = blockIdx.y * 32 + tx;
    int y2 = blockIdx.x * 32 + ty;
    #pragma unroll
    for (int i = 0; i < 4; i++)
        d[(long)(y2 + 8*i) * DIMN + x2] = __float2half(t[tx][ty + 8*i]);
}

// ================= fused flash attention v4 =================
// grid (16, 48), block 128 = 4 warps x 32 q-rows. Q frags direct from gmem.
// K/V smem: 3-stage cp.async pipeline, [tok 64][FROW] per tile.
#define FROW 72
#define NIT (CTX / 64)
#define FSTAGE (2 * 64 * FROW)                 // halfs per stage (K then V)
#define FLASH_SMEM (3 * FSTAGE * 2)            // bytes

__global__ void __launch_bounds__(128, 2)
flash_attn(const __half* __restrict__ Q, const __half* __restrict__ Kg,
           const __half* __restrict__ Vg, __half* __restrict__ O)
{
    extern __shared__ __half fsm[];

    const int tid  = threadIdx.x;
    const int wid  = tid >> 5;
    const int lane = tid & 31;
    const int g    = lane >> 2;
    const int tg   = lane & 3;
    const int mwo  = wid * 32;

    const int grp  = lane >> 3;
    const int l7   = lane & 7;
    const int rowo = (grp & 1) * 8 + l7;
    const int colo = (grp >> 1);

    const int bh = blockIdx.y;
    const int b  = bh / HEADS, h = bh - b * HEADS;
    const long qoff  = ((long)b * CTX + blockIdx.x * 128) * INNER + h * HD;
    const long kvoff = (long)b * CTX * INNER + h * HD;

    const uint32_t smbase = smem_u32(fsm);
    const uint32_t lmoff  = (uint32_t)(rowo * FROW + colo * 8) * 2;
    const uint32_t VOFF   = 64 * FROW * 2;     // V offset within stage, bytes

    // ---- Q fragments direct from gmem (m16n8k16 A layout) ----
    uint32_t qf[2][4][4];
    #pragma unroll
    for (int mg = 0; mg < 2; mg++) {
        const __half* q0 = Q + qoff + (long)(mwo + mg * 16 + g) * INNER + 2 * tg;
        const __half* q8 = q0 + 8 * INNER;
        #pragma unroll
        for (int kk = 0; kk < 4; kk++) {
            qf[mg][kk][0] = *(const uint32_t*)(q0 + 16 * kk);
            qf[mg][kk][1] = *(const uint32_t*)(q8 + 16 * kk);
            qf[mg][kk][2] = *(const uint32_t*)(q0 + 16 * kk + 8);
            qf[mg][kk][3] = *(const uint32_t*)(q8 + 16 * kk + 8);
        }
    }

    float m_r[2][2], l_r[2][2], acc_o[2][8][4];
    #pragma unroll
    for (int mg = 0; mg < 2; mg++) {
        m_r[mg][0] = m_r[mg][1] = -1e30f;
        l_r[mg][0] = l_r[mg][1] = 0.f;
        #pragma unroll
        for (int nt = 0; nt < 8; nt++)
            #pragma unroll
            for (int c = 0; c < 4; c++) acc_o[mg][nt][c] = 0.f;
    }

    // loader: 4 chunks each for K and V per thread; idx -> row=idx>>3, c=idx&7
    const __half* kp[4]; const __half* vp[4]; uint32_t soff[4];
    #pragma unroll
    for (int i = 0; i < 4; i++) {
        int idx = tid + 128 * i;
        int row = idx >> 3, c = idx & 7;
        kp[i] = Kg + kvoff + (long)row * INNER + c * 8;
        vp[i] = Vg + kvoff + (long)row * INNER + c * 8;
        soff[i] = (uint32_t)(row * FROW + c * 8) * 2;
    }

#define FCOPY(ST, IT)                                                       \
    {                                                                       \
        const uint32_t sb = smbase + (uint32_t)(ST) * (FSTAGE * 2);         \
        const long go = (long)(IT) * 64 * INNER;                            \
        _Pragma("unroll")                                                   \
        for (int i = 0; i < 4; i++) {                                       \
            cp16(sb + soff[i], kp[i] + go);                                 \
            cp16(sb + VOFF + soff[i], vp[i] + go);                          \
        }                                                                   \
    }

    FCOPY(0, 0); CP_COMMIT();
    FCOPY(1, 1); CP_COMMIT();

    for (int it = 0; it < NIT; it++) {
        CP_WAIT1();
        __syncthreads();
        const int st = it % 3;
        const uint32_t kb = smbase + (uint32_t)st * (FSTAGE * 2) + lmoff;
        const uint32_t vb = kb + VOFF;

        // ---- S = Q @ K^T, both 16-row groups share K frags ----
        float acc_s[2][8][4];
        #pragma unroll
        for (int mg = 0; mg < 2; mg++)
            #pragma unroll
            for (int nt = 0; nt < 8; nt++)
                #pragma unroll
                for (int c = 0; c < 4; c++) acc_s[mg][nt][c] = 0.f;
        #pragma unroll
        for (int kk = 0; kk < 4; kk++) {
            #pragma unroll
            for (int j = 0; j < 4; j++) {
                uint32_t r[4];
                ldm_x4(r, kb + (uint32_t)(j * 16 * FROW) * 2 + kk * 32);
                uint32_t b0[2] = {r[0], r[2]};
                uint32_t b1[2] = {r[1], r[3]};
                mma_f16(acc_s[0][2*j],     qf[0][kk], b0);
                mma_f16(acc_s[0][2*j + 1], qf[0][kk], b1);
                mma_f16(acc_s[1][2*j],     qf[1][kk], b0);
                mma_f16(acc_s[1][2*j + 1], qf[1][kk], b1);
            }
        }

        // ---- online softmax per group (1/8 scale folded into exp) ----
        uint32_t pf[2][4][4];
        #pragma unroll
        for (int mg = 0; mg < 2; mg++) {
            #pragma unroll
            for (int r = 0; r < 2; r++) {
                float mx = -1e30f;
                #pragma unroll
                for (int nt = 0; nt < 8; nt++)
                    mx = fmaxf(mx, fmaxf(acc_s[mg][nt][2 * r], acc_s[mg][nt][2 * r + 1]));
                mx = fmaxf(mx, __shfl_xor_sync(0xffffffffu, mx, 1));
                mx = fmaxf(mx, __shfl_xor_sync(0xffffffffu, mx, 2));
                float mn = fmaxf(m_r[mg][r], mx);
                float alpha = __expf((m_r[mg][r] - mn) * 0.125f);
                m_r[mg][r] = mn;
                float sum = 0.f;
                #pragma unroll
                for (int nt = 0; nt < 8; nt++) {
                    float p0 = __expf((acc_s[mg][nt][2 * r]     - mn) * 0.125f);
                    float p1 = __expf((acc_s[mg][nt][2 * r + 1] - mn) * 0.125f);
                    sum += p0 + p1;
                    pf[mg][nt >> 1][(nt & 1) * 2 + r] = cvt_h2(p0, p1);
                }
                sum += __shfl_xor_sync(0xffffffffu, sum, 1);
                sum += __shfl_xor_sync(0xffffffffu, sum, 2);
                l_r[mg][r] = alpha * l_r[mg][r] + sum;
                #pragma unroll
                for (int nt = 0; nt < 8; nt++) {
                    acc_o[mg][nt][2 * r]     *= alpha;
                    acc_o[mg][nt][2 * r + 1] *= alpha;
                }
            }
        }

        // ---- O += P @ V, both groups share V frags ----
        #pragma unroll
        for (int kk = 0; kk < 4; kk++) {
            uint32_t bf[8][2];
            #pragma unroll
            for (int j = 0; j < 4; j++) {
                uint32_t r[4];
                ldm_x4_t(r, vb + (uint32_t)(kk * 16 * FROW) * 2 + j * 32);
                bf[2*j][0]     = r[0]; bf[2*j][1]     = r[1];
                bf[2*j + 1][0] = r[2]; bf[2*j + 1][1] = r[3];
            }
            #pragma unroll
            for (int mg = 0; mg < 2; mg++)
                #pragma unroll
                for (int nt = 0; nt < 8; nt++)
                    mma_f16(acc_o[mg][nt], pf[mg][kk], bf[nt]);
        }

        // issue next-next stage copy (barrier at top of it+1 protects the overwrite)
        if (it + 2 < NIT) FCOPY((it + 2) % 3, it + 2);
        CP_COMMIT();
    }
#undef FCOPY

    // ---- write O = acc / l (fp16) ----
    #pragma unroll
    for (int mg = 0; mg < 2; mg++) {
        const float inv0 = 1.0f / l_r[mg][0];
        const float inv1 = 1.0f / l_r[mg][1];
        const long r0 = mwo + mg * 16 + g;
        #pragma unroll
        for (int nt = 0; nt < 8; nt++) {
            uint32_t o0 = cvt_h2(acc_o[mg][nt][0] * inv0, acc_o[mg][nt][1] * inv0);
            uint32_t o1 = cvt_h2(acc_o[mg][nt][2] * inv1, acc_o[mg][nt][3] * inv1);
            *(uint32_t*)(O + qoff + r0 * INNER + nt * 8 + 2 * tg) = o0;
            *(uint32_t*)(O + qoff + (r0 + 8) * INNER + nt * 8 + 2 * tg) = o1;
        }
    }
}

// ================= fp16 GEMM, ldmatrix + cp.async 3-stage =================
// C[M,768] = A[M,768] @ B[768,768]^T ; block 128x128, 8 warps 2x4 (64x32), BK=32.
#define BKD 32
#define AROW 40
#define DSTAGE (2 * 128 * AROW)                // halfs per stage (A then B)
#define DENSE_SMEM (3 * DSTAGE * 2)            // bytes

template<bool GELU_, bool HASBIAS, bool HASRES, bool OUTHALF>
__global__ void __launch_bounds__(256, 2)
mma_gemm(const __half* __restrict__ A, const __half* __restrict__ B,
         void* __restrict__ Cv, const float* __restrict__ bias,
         const float* __restrict__ residual,
         long sB1, long sC1, float alpha)
{
    extern __shared__ __half dsm[];

    const int zo = blockIdx.z;
    B += zo * sB1;
    const long coff = (long)zo * sC1;

    const int tid  = threadIdx.x;
    const int wid  = tid >> 5;
    const int lane = tid & 31;
    const int g    = lane >> 2;
    const int tg   = lane & 3;
    const int wm   = wid & 1;
    const int wn   = wid >> 1;
    const int mwo  = wm * 64;
    const int nwo  = wn * 32;

    const int grp  = lane >> 3;
    const int l7   = lane & 7;
    const int rowo = (grp & 1) * 8 + l7;
    const int colo = (grp >> 1);

    const int m0 = blockIdx.y * 128;
    const int n0 = blockIdx.x * 128;

    const uint32_t smbase = smem_u32(dsm);
    const uint32_t BOFF = 128 * AROW * 2;      // B offset within stage, bytes
    const uint32_t lma = (uint32_t)((mwo + rowo) * AROW + colo * 8) * 2;
    const uint32_t lmb = (uint32_t)((nwo + rowo) * AROW + colo * 8) * 2;

    // loader: 2 A-chunks + 2 B-chunks per thread; idx -> row=idx>>2, c=idx&3
    const __half* ap[2]; const __half* bp[2]; uint32_t soff[2];
    #pragma unroll
    for (int i = 0; i < 2; i++) {
        int idx = tid + 256 * i;
        int row = idx >> 2, c = idx & 3;
        ap[i] = A + (long)(m0 + row) * DIMN + c * 8;
        bp[i] = B + (long)(n0 + row) * DIMN + c * 8;
        soff[i] = (uint32_t)(row * AROW + c * 8) * 2;
    }

#define DCOPY(ST, S)                                                        \
    {                                                                       \
        const uint32_t sb = smbase + (uint32_t)(ST) * (DSTAGE * 2);         \
        const int ko = (S) * BKD;                                           \
        _Pragma("unroll")                                                   \
        for (int i = 0; i < 2; i++) {                                       \
            cp16(sb + soff[i], ap[i] + ko);                                 \
            cp16(sb + BOFF + soff[i], bp[i] + ko);                          \
        }                                                                   \
    }

    float acc[4][4][4];
    #pragma unroll
    for (int i = 0; i < 4; i++)
        #pragma unroll
        for (int j = 0; j < 4; j++)
            #pragma unroll
            for (int k = 0; k < 4; k++) acc[i][j][k] = 0.f;

    DCOPY(0, 0); CP_COMMIT();
    DCOPY(1, 1); CP_COMMIT();

    const int ntiles = DIMN / BKD;             // 24
    for (int s = 0; s < ntiles; s++) {
        CP_WAIT1();
        __syncthreads();
        const int st = s % 3;
        const uint32_t ab = smbase + (uint32_t)st * (DSTAGE * 2) + lma;
        const uint32_t bb = smbase + (uint32_t)st * (DSTAGE * 2) + BOFF + lmb;

        #pragma unroll
        for (int half = 0; half < 2; half++) {
            const uint32_t koffb = half * 32;
            uint32_t af[4][4];
            #pragma unroll
            for (int mt = 0; mt < 4; mt++)
                ldm_x4(af[mt], ab + (uint32_t)(mt * 16 * AROW) * 2 + koffb);
            uint32_t bf[4][2];
            #pragma unroll
            for (int j = 0; j < 2; j++) {
                uint32_t r[4];
                ldm_x4(r, bb + (uint32_t)(j * 16 * AROW) * 2 + koffb);
                bf[2*j][0]     = r[0]; bf[2*j][1]     = r[2];
                bf[2*j + 1][0] = r[1]; bf[2*j + 1][1] = r[3];
            }
            #pragma unroll
            for (int mt = 0; mt < 4; mt++)
                #pragma unroll
                for (int nt = 0; nt < 4; nt++)
                    mma_f16(acc[mt][nt], af[mt], bf[nt]);
        }

        if (s + 2 < ntiles) DCOPY((s + 2) % 3, s + 2);
        CP_COMMIT();
    }
#undef DCOPY

    // ---- epilogue ----
    #pragma unroll
    for (int mt = 0; mt < 4; mt++) {
        const long r0 = m0 + mwo + mt * 16 + g;
        const long r1 = r0 + 8;
        #pragma unroll
        for (int nt = 0; nt < 4; nt++) {
            const int cb = n0 + nwo + nt * 8 + 2 * tg;
            float2 v0, v1;
            v0.x = acc[mt][nt][0] * alpha; v0.y = acc[mt][nt][1] * alpha;
            v1.x = acc[mt][nt][2] * alpha; v1.y = acc[mt][nt][3] * alpha;
            if (HASBIAS) {
                float bx = bias[cb], by = bias[cb + 1];
                v0.x += bx; v0.y += by; v1.x += bx; v1.y += by;
            }
            if (GELU_) {
                v0.x = 0.5f * v0.x * (1.0f + erff(v0.x * 0.70710678118654752f));
                v0.y = 0.5f * v0.y * (1.0f + erff(v0.y * 0.70710678118654752f));
                v1.x = 0.5f * v1.x * (1.0f + erff(v1.x * 0.70710678118654752f));
                v1.y = 0.5f * v1.y * (1.0f + erff(v1.y * 0.70710678118654752f));
            }
            if (OUTHALF) {
                __half* Cp = (__half*)Cv + coff;
                *(uint32_t*)(Cp + r0 * DIMN + cb) = cvt_h2(v0.x, v0.y);
                *(uint32_t*)(Cp + r1 * DIMN + cb) = cvt_h2(v1.x, v1.y);
            } else {
                float* Cp = (float*)Cv + coff;
                if (HASRES) {
                    const float* Rp = residual + coff;
                    float2 q0 = *(const float2*)(Rp + r0 * DIMN + cb);
                    float2 q1 = *(const float2*)(Rp + r1 * DIMN + cb);
                    v0.x += q0.x; v0.y += q0.y; v1.x += q1.x; v1.y += q1.y;
                }
                *(float2*)(Cp + r0 * DIMN + cb) = v0;
                *(float2*)(Cp + r1 * DIMN + cb) = v1;
            }
        }
    }
}

template<bool GELU_, bool HASBIAS, bool HASRES, bool OUTHALF>
static void launch_mm(const __half* A, const __half* B, void* C,
                      const float* bias, const float* res,
                      long sB1, long sC1, int nz, float alpha)
{
    cudaFuncSetAttribute((const void*)mma_gemm<GELU_, HASBIAS, HASRES, OUTHALF>,
                         cudaFuncAttributeMaxDynamicSharedMemorySize, DENSE_SMEM);
    dim3 grid(DIMN / 128, MTOK / 128, nz);
    mma_gemm<GELU_, HASBIAS, HASRES, OUTHALF><<<grid, 256, DENSE_SMEM>>>(
        A, B, C, bias, res, sB1, sC1, alpha);
}

extern "C" void kernel_launch(void* const* d_in, const int* in_sizes, int n_in,
                              void* d_out, int out_size)
{
    const float* x     = (const float*)d_in[0];
    const float* pos   = (const float*)d_in[1];
    const float* ln1_g = (const float*)d_in[2];
    const float* ln1_b = (const float*)d_in[3];
    const float* Wq    = (const float*)d_in[4];
    const float* Wk    = (const float*)d_in[5];
    const float* Wv    = (const float*)d_in[6];
    const float* Wo    = (const float*)d_in[7];
    const float* ln2_g = (const float*)d_in[8];
    const float* ln2_b = (const float*)d_in[9];
    const float* W1    = (const float*)d_in[10];
    const float* b1    = (const float*)d_in[11];
    const float* W2    = (const float*)d_in[12];
    const float* b2    = (const float*)d_in[13];

    float  *gx;
    __half *gh, *gqkv, *go, *gf, *gwT;
    cudaGetSymbolAddress((void**)&gx,   g_x);
    cudaGetSymbolAddress((void**)&gh,   g_h);
    cudaGetSymbolAddress((void**)&gqkv, g_qkv);
    cudaGetSymbolAddress((void**)&go,   g_o);
    cudaGetSymbolAddress((void**)&gf,   g_f);
    cudaGetSymbolAddress((void**)&gwT,  g_wT);

    __half* gq = gqkv;
    __half* gk = gqkv + (long)MTOK * INNER;
    __half* gv = gqkv + 2L * MTOK * INNER;

    cudaFuncSetAttribute((const void*)flash_attn,
                         cudaFuncAttributeMaxDynamicSharedMemorySize, FLASH_SMEM);

    {
        dim3 grid(DIMN / 32, DIMN / 32, DEPTH * 6);
        transpose_w<<<grid, dim3(32, 8)>>>(Wq, Wk, Wv, Wo, W1, W2, gwT);
    }

    add_pos_kernel<<<(MTOK * DIMN) / 256, 256>>>(x, pos, gx);

    for (int l = 0; l < DEPTH; l++) {
        const __half* wqT = gwT + (long)(l * 6 + 0) * WSZ;
        const __half* woT = gwT + (long)(l * 6 + 3) * WSZ;
        const __half* w1T = gwT + (long)(l * 6 + 4) * WSZ;
        const __half* w2T = gwT + (long)(l * 6 + 5) * WSZ;
        const float* l1g = ln1_g + l * DIMN, *l1b = ln1_b + l * DIMN;
        const float* l2g = ln2_g + l * DIMN, *l2b = ln2_b + l * DIMN;
        const float* bb1 = b1 + l * DIMN,   *bb2 = b2 + l * DIMN;

        // --- attention
        layernorm_kernel<<<MTOK, 256>>>(gx, gh, l1g, l1b);

        launch_mm<false, false, false, true>(
            gh, wqT, gqkv, nullptr, nullptr,
            WSZ, (long)MTOK * INNER, 3, 1.0f);

        flash_attn<<<dim3(CTX / 128, BATCH * HEADS), 128, FLASH_SMEM>>>(gq, gk, gv, go);

        launch_mm<false, false, true, false>(
            go, woT, gx, nullptr, gx, 0, 0, 1, 1.0f);

        // --- FFN
        layernorm_kernel<<<MTOK, 256>>>(gx, gh, l2g, l2b);

        launch_mm<true, true, false, true>(
            gh, w1T, gf, bb1, nullptr, 0, 0, 1, 1.0f);

        float* cout = (l == DEPTH - 1) ? (float*)d_out : gx;
        launch_mm<false, true, true, false>(
            gf, w2T, cout, bb2, gx, 0, 0, 1, 1.0f);
    }
}

// round 10
// speedup vs baseline: 11.4125x; 1.0129x over previous
#include <cuda_runtime.h>
#include <cuda_fp16.h>
#include <math.h>
#include <stdint.h>

#define DEPTH 4
#define DIMN  768
#define HEADS 12
#define HD    64
#define CTX   2048
#define BATCH 4
#define MTOK  (BATCH*CTX)          // 8192
#define INNER (HEADS*HD)           // 768
#define WSZ   ((long)DIMN*DIMN)

// ---------------- scratch (device globals; no allocation) ----------------
__device__ __align__(128) float  g_x  [MTOK*DIMN];             // residual (fp32)
__device__ __align__(128) __half g_h  [MTOK*DIMN];             // LN out
__device__ __align__(128) __half g_qkv[3L*MTOK*INNER];
__device__ __align__(128) __half g_o  [MTOK*INNER];
__device__ __align__(128) __half g_f  [MTOK*DIMN];
__device__ __align__(128) __half g_wT [24L*DIMN*DIMN];         // K-major weights, fp16

__device__ __forceinline__ uint32_t cvt_h2(float lo, float hi) {
    __half2 h = __floats2half2_rn(lo, hi);
    return *(uint32_t*)&h;
}
__device__ __forceinline__ uint32_t smem_u32(const void* p) {
    uint32_t a;
    asm("{ .reg .u64 t; cvta.to.shared.u64 t, %1; cvt.u32.u64 %0, t; }" : "=r"(a) : "l"(p));
    return a;
}
__device__ __forceinline__ void mma_f16(float* c, const uint32_t* a, const uint32_t* b) {
    asm volatile(
        "mma.sync.aligned.m16n8k16.row.col.f32.f16.f16.f32 "
        "{%0,%1,%2,%3}, {%4,%5,%6,%7}, {%8,%9}, {%0,%1,%2,%3};"
        : "+f"(c[0]), "+f"(c[1]), "+f"(c[2]), "+f"(c[3])
        : "r"(a[0]), "r"(a[1]), "r"(a[2]), "r"(a[3]), "r"(b[0]), "r"(b[1]));
}
__device__ __forceinline__ void ldm_x4(uint32_t* r, uint32_t addr) {
    asm volatile("ldmatrix.sync.aligned.m8n8.x4.shared.b16 {%0,%1,%2,%3}, [%4];"
                 : "=r"(r[0]), "=r"(r[1]), "=r"(r[2]), "=r"(r[3]) : "r"(addr));
}
__device__ __forceinline__ void ldm_x4_t(uint32_t* r, uint32_t addr) {
    asm volatile("ldmatrix.sync.aligned.m8n8.x4.trans.shared.b16 {%0,%1,%2,%3}, [%4];"
                 : "=r"(r[0]), "=r"(r[1]), "=r"(r[2]), "=r"(r[3]) : "r"(addr));
}
__device__ __forceinline__ void cp16(uint32_t s, const void* g) {
    asm volatile("cp.async.cg.shared.global [%0], [%1], 16;" :: "r"(s), "l"(g));
}
#define CP_COMMIT() asm volatile("cp.async.commit_group;" ::: "memory")
#define CP_WAIT1()  asm volatile("cp.async.wait_group 1;" ::: "memory")

// ================= elementwise kernels =================
// LayerNorm; optionally adds pos_emb first and writes the fp32 residual base.
__global__ void layernorm_kernel(const float* __restrict__ x, __half* __restrict__ y,
                                 const float* __restrict__ gamma,
                                 const float* __restrict__ beta,
                                 const float* __restrict__ pos,   // nullptr -> plain LN
                                 float* __restrict__ xout)        // fp32 residual out
{
    __shared__ float ss[8], qq[8];
    int row = blockIdx.x;
    int tid = threadIdx.x;
    const float* xr = x + (long)row * DIMN;
    float v0 = xr[tid], v1 = xr[tid + 256], v2 = xr[tid + 512];
    if (pos) {
        const float* pr = pos + (long)(row % CTX) * DIMN;
        v0 += pr[tid]; v1 += pr[tid + 256]; v2 += pr[tid + 512];
        float* xo = xout + (long)row * DIMN;
        xo[tid] = v0; xo[tid + 256] = v1; xo[tid + 512] = v2;
    }
    float s = v0 + v1 + v2;
    float q = v0*v0 + v1*v1 + v2*v2;
    #pragma unroll
    for (int o = 16; o > 0; o >>= 1) {
        s += __shfl_xor_sync(0xffffffffu, s, o);
        q += __shfl_xor_sync(0xffffffffu, q, o);
    }
    int wid = tid >> 5, lane = tid & 31;
    if (lane == 0) { ss[wid] = s; qq[wid] = q; }
    __syncthreads();
    if (tid == 0) {
        float ts = 0.f, tq = 0.f;
        #pragma unroll
        for (int i = 0; i < 8; i++) { ts += ss[i]; tq += qq[i]; }
        ss[0] = ts; qq[0] = tq;
    }
    __syncthreads();
    float mean = ss[0] * (1.0f / DIMN);
    float var  = qq[0] * (1.0f / DIMN) - mean * mean;
    float inv  = rsqrtf(var + 1e-5f);
    __half* yr = y + (long)row * DIMN;
    yr[tid      ] = __float2half((v0 - mean) * inv * gamma[tid      ] + beta[tid      ]);
    yr[tid + 256] = __float2half((v1 - mean) * inv * gamma[tid + 256] + beta[tid + 256]);
    yr[tid + 512] = __float2half((v2 - mean) * inv * gamma[tid + 512] + beta[tid + 512]);
}

// transpose all 24 weight matrices (768x768) into g_wT (half); z = l*6 + w
__global__ void transpose_w(const float* __restrict__ Wq, const float* __restrict__ Wk,
                            const float* __restrict__ Wv, const float* __restrict__ Wo,
                            const float* __restrict__ W1, const float* __restrict__ W2,
                            __half* __restrict__ dst)
{
    __shared__ float t[32][33];
    int z = blockIdx.z;
    int l = z / 6, w = z - l * 6;
    const float* srcs[6] = {Wq, Wk, Wv, Wo, W1, W2};
    const float* src = srcs[w] + (long)l * WSZ;
    __half* d = dst + (long)z * WSZ;
    int tx = threadIdx.x, ty = threadIdx.y;
    int x = blockIdx.x * 32 + tx;
    int y = blockIdx.y * 32 + ty;
    #pragma unroll
    for (int i = 0; i < 4; i++)
        t[ty + 8*i][tx] = src[(long)(y + 8*i) * DIMN + x];
    __syncthreads();
    int x2 = blockIdx.y * 32 + tx;
    int y2 = blockIdx.x * 32 + ty;
    #pragma unroll
    for (int i = 0; i < 4; i++)
        d[(long)(y2 + 8*i) * DIMN + x2] = __float2half(t[tx][ty + 8*i]);
}

// ================= fused flash attention v4 =================
#define FROW 72
#define NIT (CTX / 64)
#define FSTAGE (2 * 64 * FROW)                 // halfs per stage (K then V)
#define FLASH_SMEM (3 * FSTAGE * 2)            // bytes
#define SCL 0.18033688f                        // 0.125 * log2(e)

__global__ void __launch_bounds__(128, 2)
flash_attn(const __half* __restrict__ Q, const __half* __restrict__ Kg,
           const __half* __restrict__ Vg, __half* __restrict__ O)
{
    extern __shared__ __half fsm[];

    const int tid  = threadIdx.x;
    const int wid  = tid >> 5;
    const int lane = tid & 31;
    const int g    = lane >> 2;
    const int tg   = lane & 3;
    const int mwo  = wid * 32;

    const int grp  = lane >> 3;
    const int l7   = lane & 7;
    const int rowo = (grp & 1) * 8 + l7;
    const int colo = (grp >> 1);

    const int bh = blockIdx.y;
    const int b  = bh / HEADS, h = bh - b * HEADS;
    const long qoff  = ((long)b * CTX + blockIdx.x * 128) * INNER + h * HD;
    const long kvoff = (long)b * CTX * INNER + h * HD;

    const uint32_t smbase = smem_u32(fsm);
    const uint32_t lmoff  = (uint32_t)(rowo * FROW + colo * 8) * 2;
    const uint32_t VOFF   = 64 * FROW * 2;

    // ---- Q fragments direct from gmem ----
    uint32_t qf[2][4][4];
    #pragma unroll
    for (int mg = 0; mg < 2; mg++) {
        const __half* q0 = Q + qoff + (long)(mwo + mg * 16 + g) * INNER + 2 * tg;
        const __half* q8 = q0 + 8 * INNER;
        #pragma unroll
        for (int kk = 0; kk < 4; kk++) {
            qf[mg][kk][0] = *(const uint32_t*)(q0 + 16 * kk);
            qf[mg][kk][1] = *(const uint32_t*)(q8 + 16 * kk);
            qf[mg][kk][2] = *(const uint32_t*)(q0 + 16 * kk + 8);
            qf[mg][kk][3] = *(const uint32_t*)(q8 + 16 * kk + 8);
        }
    }

    float m_r[2][2], l_r[2][2], acc_o[2][8][4];
    #pragma unroll
    for (int mg = 0; mg < 2; mg++) {
        m_r[mg][0] = m_r[mg][1] = -1e30f;
        l_r[mg][0] = l_r[mg][1] = 0.f;
        #pragma unroll
        for (int nt = 0; nt < 8; nt++)
            #pragma unroll
            for (int c = 0; c < 4; c++) acc_o[mg][nt][c] = 0.f;
    }

    const __half* kp[4]; const __half* vp[4]; uint32_t soff[4];
    #pragma unroll
    for (int i = 0; i < 4; i++) {
        int idx = tid + 128 * i;
        int row = idx >> 3, c = idx & 7;
        kp[i] = Kg + kvoff + (long)row * INNER + c * 8;
        vp[i] = Vg + kvoff + (long)row * INNER + c * 8;
        soff[i] = (uint32_t)(row * FROW + c * 8) * 2;
    }

#define FCOPY(ST, IT)                                                       \
    {                                                                       \
        const uint32_t sb = smbase + (uint32_t)(ST) * (FSTAGE * 2);         \
        const long go = (long)(IT) * 64 * INNER;                            \
        _Pragma("unroll")                                                   \
        for (int i = 0; i < 4; i++) {                                       \
            cp16(sb + soff[i], kp[i] + go);                                 \
            cp16(sb + VOFF + soff[i], vp[i] + go);                          \
        }                                                                   \
    }

    FCOPY(0, 0); CP_COMMIT();
    FCOPY(1, 1); CP_COMMIT();

    for (int it = 0; it < NIT; it++) {
        CP_WAIT1();
        __syncthreads();
        const int st = it % 3;
        const uint32_t kb = smbase + (uint32_t)st * (FSTAGE * 2) + lmoff;
        const uint32_t vb = kb + VOFF;

        // ---- S = Q @ K^T ----
        float acc_s[2][8][4];
        #pragma unroll
        for (int mg = 0; mg < 2; mg++)
            #pragma unroll
            for (int nt = 0; nt < 8; nt++)
                #pragma unroll
                for (int c = 0; c < 4; c++) acc_s[mg][nt][c] = 0.f;
        #pragma unroll
        for (int kk = 0; kk < 4; kk++) {
            #pragma unroll
            for (int j = 0; j < 4; j++) {
                uint32_t r[4];
                ldm_x4(r, kb + (uint32_t)(j * 16 * FROW) * 2 + kk * 32);
                uint32_t b0[2] = {r[0], r[2]};
                uint32_t b1[2] = {r[1], r[3]};
                mma_f16(acc_s[0][2*j],     qf[0][kk], b0);
                mma_f16(acc_s[0][2*j + 1], qf[0][kk], b1);
                mma_f16(acc_s[1][2*j],     qf[1][kk], b0);
                mma_f16(acc_s[1][2*j + 1], qf[1][kk], b1);
            }
        }

        // ---- online softmax (exp2, 1/8*log2e folded) ----
        uint32_t pf[2][4][4];
        #pragma unroll
        for (int mg = 0; mg < 2; mg++) {
            #pragma unroll
            for (int r = 0; r < 2; r++) {
                float mx = -1e30f;
                #pragma unroll
                for (int nt = 0; nt < 8; nt++)
                    mx = fmaxf(mx, fmaxf(acc_s[mg][nt][2 * r], acc_s[mg][nt][2 * r + 1]));
                mx = fmaxf(mx, __shfl_xor_sync(0xffffffffu, mx, 1));
                mx = fmaxf(mx, __shfl_xor_sync(0xffffffffu, mx, 2));
                float mn = fmaxf(m_r[mg][r], mx);
                float alpha = exp2f((m_r[mg][r] - mn) * SCL);
                m_r[mg][r] = mn;
                float sum = 0.f;
                #pragma unroll
                for (int nt = 0; nt < 8; nt++) {
                    float p0 = exp2f((acc_s[mg][nt][2 * r]     - mn) * SCL);
                    float p1 = exp2f((acc_s[mg][nt][2 * r + 1] - mn) * SCL);
                    sum += p0 + p1;
                    pf[mg][nt >> 1][(nt & 1) * 2 + r] = cvt_h2(p0, p1);
                }
                sum += __shfl_xor_sync(0xffffffffu, sum, 1);
                sum += __shfl_xor_sync(0xffffffffu, sum, 2);
                l_r[mg][r] = alpha * l_r[mg][r] + sum;
                #pragma unroll
                for (int nt = 0; nt < 8; nt++) {
                    acc_o[mg][nt][2 * r]     *= alpha;
                    acc_o[mg][nt][2 * r + 1] *= alpha;
                }
            }
        }

        // ---- O += P @ V ----
        #pragma unroll
        for (int kk = 0; kk < 4; kk++) {
            uint32_t bf[8][2];
            #pragma unroll
            for (int j = 0; j < 4; j++) {
                uint32_t r[4];
                ldm_x4_t(r, vb + (uint32_t)(kk * 16 * FROW) * 2 + j * 32);
                bf[2*j][0]     = r[0]; bf[2*j][1]     = r[1];
                bf[2*j + 1][0] = r[2]; bf[2*j + 1][1] = r[3];
            }
            #pragma unroll
            for (int mg = 0; mg < 2; mg++)
                #pragma unroll
                for (int nt = 0; nt < 8; nt++)
                    mma_f16(acc_o[mg][nt], pf[mg][kk], bf[nt]);
        }

        if (it + 2 < NIT) FCOPY((it + 2) % 3, it + 2);
        CP_COMMIT();
    }
#undef FCOPY

    // ---- write O = acc / l (fp16) ----
    #pragma unroll
    for (int mg = 0; mg < 2; mg++) {
        const float inv0 = 1.0f / l_r[mg][0];
        const float inv1 = 1.0f / l_r[mg][1];
        const long r0 = mwo + mg * 16 + g;
        #pragma unroll
        for (int nt = 0; nt < 8; nt++) {
            uint32_t o0 = cvt_h2(acc_o[mg][nt][0] * inv0, acc_o[mg][nt][1] * inv0);
            uint32_t o1 = cvt_h2(acc_o[mg][nt][2] * inv1, acc_o[mg][nt][3] * inv1);
            *(uint32_t*)(O + qoff + r0 * INNER + nt * 8 + 2 * tg) = o0;
            *(uint32_t*)(O + qoff + (r0 + 8) * INNER + nt * 8 + 2 * tg) = o1;
        }
    }
}

// ================= fp16 GEMM, ldmatrix + cp.async 3-stage, BM templated =================
// C[M,768] = A[M,768] @ B[768,768]^T ; BM x 128 tile, 8 warps 2x4.
// BMT=128: warp 64x32 (MT=4); BMT=64: warp 32x32 (MT=2), 768 CTAs for M=8192.
#define BKD 32
#define AROW 40

template<int BMT, bool GELU_, bool HASBIAS, bool HASRES, bool OUTHALF>
__global__ void __launch_bounds__(256, 2)
mma_gemm(const __half* __restrict__ A, const __half* __restrict__ B,
         void* __restrict__ Cv, const float* __restrict__ bias,
         const float* __restrict__ residual,
         long sB1, long sC1, float alpha)
{
    constexpr int MT  = BMT / 32;                       // 4 or 2
    constexpr int ACH = (BMT * 4) / 256;                // A chunks/thread: 2 or 1
    constexpr uint32_t DSTG = (uint32_t)(BMT + 128) * AROW * 2;  // stage bytes
    constexpr uint32_t BOFF = (uint32_t)BMT * AROW * 2;

    extern __shared__ __half dsm[];

    const int zo = blockIdx.z;
    B += zo * sB1;
    const long coff = (long)zo * sC1;

    const int tid  = threadIdx.x;
    const int wid  = tid >> 5;
    const int lane = tid & 31;
    const int g    = lane >> 2;
    const int tg   = lane & 3;
    const int wm   = wid & 1;
    const int wn   = wid >> 1;
    const int mwo  = wm * (BMT / 2);
    const int nwo  = wn * 32;

    const int grp  = lane >> 3;
    const int l7   = lane & 7;
    const int rowo = (grp & 1) * 8 + l7;
    const int colo = (grp >> 1);

    const int m0 = blockIdx.y * BMT;
    const int n0 = blockIdx.x * 128;

    const uint32_t smbase = smem_u32(dsm);
    const uint32_t lma = (uint32_t)((mwo + rowo) * AROW + colo * 8) * 2;
    const uint32_t lmb = (uint32_t)((nwo + rowo) * AROW + colo * 8) * 2;

    // loaders: A = BMT rows x 4 chunks; B = 128 rows x 4 chunks (2/thread)
    const __half* ap[ACH]; uint32_t soffa[ACH];
    #pragma unroll
    for (int i = 0; i < ACH; i++) {
        int idx = tid + 256 * i;
        int row = idx >> 2, c = idx & 3;
        ap[i] = A + (long)(m0 + row) * DIMN + c * 8;
        soffa[i] = (uint32_t)(row * AROW + c * 8) * 2;
    }
    const __half* bp[2]; uint32_t soffb[2];
    #pragma unroll
    for (int i = 0; i < 2; i++) {
        int idx = tid + 256 * i;
        int row = idx >> 2, c = idx & 3;
        bp[i] = B + (long)(n0 + row) * DIMN + c * 8;
        soffb[i] = (uint32_t)(row * AROW + c * 8) * 2;
    }

#define DCOPY(ST, S)                                                        \
    {                                                                       \
        const uint32_t sb = smbase + (uint32_t)(ST) * DSTG;                 \
        const int ko = (S) * BKD;                                           \
        _Pragma("unroll")                                                   \
        for (int i = 0; i < ACH; i++) cp16(sb + soffa[i], ap[i] + ko);      \
        _Pragma("unroll")                                                   \
        for (int i = 0; i < 2; i++) cp16(sb + BOFF + soffb[i], bp[i] + ko); \
    }

    float acc[MT][4][4];
    #pragma unroll
    for (int i = 0; i < MT; i++)
        #pragma unroll
        for (int j = 0; j < 4; j++)
            #pragma unroll
            for (int k = 0; k < 4; k++) acc[i][j][k] = 0.f;

    DCOPY(0, 0); CP_COMMIT();
    DCOPY(1, 1); CP_COMMIT();

    const int ntiles = DIMN / BKD;             // 24
    for (int s = 0; s < ntiles; s++) {
        CP_WAIT1();
        __syncthreads();
        const int st = s % 3;
        const uint32_t ab = smbase + (uint32_t)st * DSTG + lma;
        const uint32_t bb = smbase + (uint32_t)st * DSTG + BOFF + lmb;

        #pragma unroll
        for (int half = 0; half < 2; half++) {
            const uint32_t koffb = half * 32;
            uint32_t af[MT][4];
            #pragma unroll
            for (int mt = 0; mt < MT; mt++)
                ldm_x4(af[mt], ab + (uint32_t)(mt * 16 * AROW) * 2 + koffb);
            uint32_t bf[4][2];
            #pragma unroll
            for (int j = 0; j < 2; j++) {
                uint32_t r[4];
                ldm_x4(r, bb + (uint32_t)(j * 16 * AROW) * 2 + koffb);
                bf[2*j][0]     = r[0]; bf[2*j][1]     = r[2];
                bf[2*j + 1][0] = r[1]; bf[2*j + 1][1] = r[3];
            }
            #pragma unroll
            for (int mt = 0; mt < MT; mt++)
                #pragma unroll
                for (int nt = 0; nt < 4; nt++)
                    mma_f16(acc[mt][nt], af[mt], bf[nt]);
        }

        if (s + 2 < ntiles) DCOPY((s + 2) % 3, s + 2);
        CP_COMMIT();
    }
#undef DCOPY

    // ---- epilogue ----
    #pragma unroll
    for (int mt = 0; mt < MT; mt++) {
        const long r0 = m0 + mwo + mt * 16 + g;
        const long r1 = r0 + 8;
        #pragma unroll
        for (int nt = 0; nt < 4; nt++) {
            const int cb = n0 + nwo + nt * 8 + 2 * tg;
            float2 v0, v1;
            v0.x = acc[mt][nt][0] * alpha; v0.y = acc[mt][nt][1] * alpha;
            v1.x = acc[mt][nt][2] * alpha; v1.y = acc[mt][nt][3] * alpha;
            if (HASBIAS) {
                float bx = bias[cb], by = bias[cb + 1];
                v0.x += bx; v0.y += by; v1.x += bx; v1.y += by;
            }
            if (GELU_) {
                v0.x = 0.5f * v0.x * (1.0f + erff(v0.x * 0.70710678118654752f));
                v0.y = 0.5f * v0.y * (1.0f + erff(v0.y * 0.70710678118654752f));
                v1.x = 0.5f * v1.x * (1.0f + erff(v1.x * 0.70710678118654752f));
                v1.y = 0.5f * v1.y * (1.0f + erff(v1.y * 0.70710678118654752f));
            }
            if (OUTHALF) {
                __half* Cp = (__half*)Cv + coff;
                *(uint32_t*)(Cp + r0 * DIMN + cb) = cvt_h2(v0.x, v0.y);
                *(uint32_t*)(Cp + r1 * DIMN + cb) = cvt_h2(v1.x, v1.y);
            } else {
                float* Cp = (float*)Cv + coff;
                if (HASRES) {
                    const float* Rp = residual + coff;
                    float2 q0 = *(const float2*)(Rp + r0 * DIMN + cb);
                    float2 q1 = *(const float2*)(Rp + r1 * DIMN + cb);
                    v0.x += q0.x; v0.y += q0.y; v1.x += q1.x; v1.y += q1.y;
                }
                *(float2*)(Cp + r0 * DIMN + cb) = v0;
                *(float2*)(Cp + r1 * DIMN + cb) = v1;
            }
        }
    }
}

template<int BMT, bool GELU_, bool HASBIAS, bool HASRES, bool OUTHALF>
static void launch_mm(const __half* A, const __half* B, void* C,
                      const float* bias, const float* res,
                      long sB1, long sC1, int nz, float alpha)
{
    constexpr int SMEM = 3 * (BMT + 128) * AROW * 2;
    cudaFuncSetAttribute((const void*)mma_gemm<BMT, GELU_, HASBIAS, HASRES, OUTHALF>,
                         cudaFuncAttributeMaxDynamicSharedMemorySize, SMEM);
    dim3 grid(DIMN / 128, MTOK / BMT, nz);
    mma_gemm<BMT, GELU_, HASBIAS, HASRES, OUTHALF><<<grid, 256, SMEM>>>(
        A, B, C, bias, res, sB1, sC1, alpha);
}

extern "C" void kernel_launch(void* const* d_in, const int* in_sizes, int n_in,
                              void* d_out, int out_size)
{
    const float* x     = (const float*)d_in[0];
    const float* pos   = (const float*)d_in[1];
    const float* ln1_g = (const float*)d_in[2];
    const float* ln1_b = (const float*)d_in[3];
    const float* Wq    = (const float*)d_in[4];
    const float* Wk    = (const float*)d_in[5];
    const float* Wv    = (const float*)d_in[6];
    const float* Wo    = (const float*)d_in[7];
    const float* ln2_g = (const float*)d_in[8];
    const float* ln2_b = (const float*)d_in[9];
    const float* W1    = (const float*)d_in[10];
    const float* b1    = (const float*)d_in[11];
    const float* W2    = (const float*)d_in[12];
    const float* b2    = (const float*)d_in[13];

    float  *gx;
    __half *gh, *gqkv, *go, *gf, *gwT;
    cudaGetSymbolAddress((void**)&gx,   g_x);
    cudaGetSymbolAddress((void**)&gh,   g_h);
    cudaGetSymbolAddress((void**)&gqkv, g_qkv);
    cudaGetSymbolAddress((void**)&go,   g_o);
    cudaGetSymbolAddress((void**)&gf,   g_f);
    cudaGetSymbolAddress((void**)&gwT,  g_wT);

    __half* gq = gqkv;
    __half* gk = gqkv + (long)MTOK * INNER;
    __half* gv = gqkv + 2L * MTOK * INNER;

    cudaFuncSetAttribute((const void*)flash_attn,
                         cudaFuncAttributeMaxDynamicSharedMemorySize, FLASH_SMEM);

    {
        dim3 grid(DIMN / 32, DIMN / 32, DEPTH * 6);
        transpose_w<<<grid, dim3(32, 8)>>>(Wq, Wk, Wv, Wo, W1, W2, gwT);
    }

    for (int l = 0; l < DEPTH; l++) {
        const __half* wqT = gwT + (long)(l * 6 + 0) * WSZ;
        const __half* woT = gwT + (long)(l * 6 + 3) * WSZ;
        const __half* w1T = gwT + (long)(l * 6 + 4) * WSZ;
        const __half* w2T = gwT + (long)(l * 6 + 5) * WSZ;
        const float* l1g = ln1_g + l * DIMN, *l1b = ln1_b + l * DIMN;
        const float* l2g = ln2_g + l * DIMN, *l2b = ln2_b + l * DIMN;
        const float* bb1 = b1 + l * DIMN,   *bb2 = b2 + l * DIMN;

        // --- attention
        if (l == 0) {
            // fused (x + pos) -> residual base gx AND LN -> gh
            layernorm_kernel<<<MTOK, 256>>>(x, gh, l1g, l1b, pos, gx);
        } else {
            layernorm_kernel<<<MTOK, 256>>>(gx, gh, l1g, l1b, nullptr, nullptr);
        }

        launch_mm<128, false, false, false, true>(
            gh, wqT, gqkv, nullptr, nullptr,
            WSZ, (long)MTOK * INNER, 3, 1.0f);

        flash_attn<<<dim3(CTX / 128, BATCH * HEADS), 128, FLASH_SMEM>>>(gq, gk, gv, go);

        // x = x + O @ Wo (fp32 out + residual), 64x128 tiles -> 768 CTAs
        launch_mm<64, false, false, true, false>(
            go, woT, gx, nullptr, gx, 0, 0, 1, 1.0f);

        // --- FFN
        layernorm_kernel<<<MTOK, 256>>>(gx, gh, l2g, l2b, nullptr, nullptr);

        launch_mm<64, true, true, false, true>(
            gh, w1T, gf, bb1, nullptr, 0, 0, 1, 1.0f);

        float* cout = (l == DEPTH - 1) ? (float*)d_out : gx;
        launch_mm<64, false, true, true, false>(
            gf, w2T, cout, bb2, gx, 0, 0, 1, 1.0f);
    }
}

// round 11
// speedup vs baseline: 11.6818x; 1.0236x over previous
#include <cuda_runtime.h>
#include <cuda_fp16.h>
#include <math.h>
#include <stdint.h>

#define DEPTH 4
#define DIMN  768
#define HEADS 12
#define HD    64
#define CTX   2048
#define BATCH 4
#define MTOK  (BATCH*CTX)          // 8192
#define INNER (HEADS*HD)           // 768
#define WSZ   ((long)DIMN*DIMN)

// ---------------- scratch (device globals; no allocation) ----------------
__device__ __align__(128) float  g_x  [MTOK*DIMN];             // residual (fp32)
__device__ __align__(128) __half g_h  [MTOK*DIMN];             // LN out
__device__ __align__(128) __half g_qkv[3L*MTOK*INNER];
__device__ __align__(128) __half g_o  [MTOK*INNER];
__device__ __align__(128) __half g_f  [MTOK*DIMN];
__device__ __align__(128) __half g_wT [24L*DIMN*DIMN];         // K-major weights, fp16

__device__ __forceinline__ uint32_t cvt_h2(float lo, float hi) {
    __half2 h = __floats2half2_rn(lo, hi);
    return *(uint32_t*)&h;
}
__device__ __forceinline__ uint32_t smem_u32(const void* p) {
    uint32_t a;
    asm("{ .reg .u64 t; cvta.to.shared.u64 t, %1; cvt.u32.u64 %0, t; }" : "=r"(a) : "l"(p));
    return a;
}
__device__ __forceinline__ void mma_f16(float* c, const uint32_t* a, const uint32_t* b) {
    asm volatile(
        "mma.sync.aligned.m16n8k16.row.col.f32.f16.f16.f32 "
        "{%0,%1,%2,%3}, {%4,%5,%6,%7}, {%8,%9}, {%0,%1,%2,%3};"
        : "+f"(c[0]), "+f"(c[1]), "+f"(c[2]), "+f"(c[3])
        : "r"(a[0]), "r"(a[1]), "r"(a[2]), "r"(a[3]), "r"(b[0]), "r"(b[1]));
}
__device__ __forceinline__ void ldm_x4(uint32_t* r, uint32_t addr) {
    asm volatile("ldmatrix.sync.aligned.m8n8.x4.shared.b16 {%0,%1,%2,%3}, [%4];"
                 : "=r"(r[0]), "=r"(r[1]), "=r"(r[2]), "=r"(r[3]) : "r"(addr));
}
__device__ __forceinline__ void ldm_x4_t(uint32_t* r, uint32_t addr) {
    asm volatile("ldmatrix.sync.aligned.m8n8.x4.trans.shared.b16 {%0,%1,%2,%3}, [%4];"
                 : "=r"(r[0]), "=r"(r[1]), "=r"(r[2]), "=r"(r[3]) : "r"(addr));
}
__device__ __forceinline__ void ldm_x2_t(uint32_t* r, uint32_t addr) {
    asm volatile("ldmatrix.sync.aligned.m8n8.x2.trans.shared.b16 {%0,%1}, [%2];"
                 : "=r"(r[0]), "=r"(r[1]) : "r"(addr));
}
__device__ __forceinline__ uint32_t ex2_h2(uint32_t a) {
    uint32_t d;
    asm("ex2.approx.f16x2 %0, %1;" : "=r"(d) : "r"(a));
    return d;
}
__device__ __forceinline__ void cp16(uint32_t s, const void* g) {
    asm volatile("cp.async.cg.shared.global [%0], [%1], 16;" :: "r"(s), "l"(g));
}
#define CP_COMMIT() asm volatile("cp.async.commit_group;" ::: "memory")
#define CP_WAIT1()  asm volatile("cp.async.wait_group 1;" ::: "memory")

// ================= elementwise kernels =================
__global__ void layernorm_kernel(const float* __restrict__ x, __half* __restrict__ y,
                                 const float* __restrict__ gamma,
                                 const float* __restrict__ beta,
                                 const float* __restrict__ pos,   // nullptr -> plain LN
                                 float* __restrict__ xout)        // fp32 residual out
{
    __shared__ float ss[8], qq[8];
    int row = blockIdx.x;
    int tid = threadIdx.x;
    const float* xr = x + (long)row * DIMN;
    float v0 = xr[tid], v1 = xr[tid + 256], v2 = xr[tid + 512];
    if (pos) {
        const float* pr = pos + (long)(row % CTX) * DIMN;
        v0 += pr[tid]; v1 += pr[tid + 256]; v2 += pr[tid + 512];
        float* xo = xout + (long)row * DIMN;
        xo[tid] = v0; xo[tid + 256] = v1; xo[tid + 512] = v2;
    }
    float s = v0 + v1 + v2;
    float q = v0*v0 + v1*v1 + v2*v2;
    #pragma unroll
    for (int o = 16; o > 0; o >>= 1) {
        s += __shfl_xor_sync(0xffffffffu, s, o);
        q += __shfl_xor_sync(0xffffffffu, q, o);
    }
    int wid = tid >> 5, lane = tid & 31;
    if (lane == 0) { ss[wid] = s; qq[wid] = q; }
    __syncthreads();
    if (tid == 0) {
        float ts = 0.f, tq = 0.f;
        #pragma unroll
        for (int i = 0; i < 8; i++) { ts += ss[i]; tq += qq[i]; }
        ss[0] = ts; qq[0] = tq;
    }
    __syncthreads();
    float mean = ss[0] * (1.0f / DIMN);
    float var  = qq[0] * (1.0f / DIMN) - mean * mean;
    float inv  = rsqrtf(var + 1e-5f);
    __half* yr = y + (long)row * DIMN;
    yr[tid      ] = __float2half((v0 - mean) * inv * gamma[tid      ] + beta[tid      ]);
    yr[tid + 256] = __float2half((v1 - mean) * inv * gamma[tid + 256] + beta[tid + 256]);
    yr[tid + 512] = __float2half((v2 - mean) * inv * gamma[tid + 512] + beta[tid + 512]);
}

// transpose all 24 weight matrices (768x768) into g_wT (half); z = l*6 + w
__global__ void transpose_w(const float* __restrict__ Wq, const float* __restrict__ Wk,
                            const float* __restrict__ Wv, const float* __restrict__ Wo,
                            const float* __restrict__ W1, const float* __restrict__ W2,
                            __half* __restrict__ dst)
{
    __shared__ float t[32][33];
    int z = blockIdx.z;
    int l = z / 6, w = z - l * 6;
    const float* srcs[6] = {Wq, Wk, Wv, Wo, W1, W2};
    const float* src = srcs[w] + (long)l * WSZ;
    __half* d = dst + (long)z * WSZ;
    int tx = threadIdx.x, ty = threadIdx.y;
    int x = blockIdx.x * 32 + tx;
    int y = blockIdx.y * 32 + ty;
    #pragma unroll
    for (int i = 0; i < 4; i++)
        t[ty + 8*i][tx] = src[(long)(y + 8*i) * DIMN + x];
    __syncthreads();
    int x2 = blockIdx.y * 32 + tx;
    int y2 = blockIdx.x * 32 + ty;
    #pragma unroll
    for (int i = 0; i < 4; i++)
        d[(long)(y2 + 8*i) * DIMN + x2] = __float2half(t[tx][ty + 8*i]);
}

// ================= fused flash attention v5 =================
// grid (16, 48), block 128 = 4 warps x 32 q-rows.
// K/V 3-stage cp.async pipeline; V padding cols 64..71 hold 1.0 so row-sums
// of P come out of the PV mma as a 9th output column (no scalar reduction).
#define FROW 72
#define NIT (CTX / 64)
#define FSTAGE (2 * 64 * FROW)                 // halfs per stage (K then V)
#define FLASH_SMEM (3 * FSTAGE * 2)            // bytes
#define SCL 0.18033688f                        // 0.125 * log2(e)

__global__ void __launch_bounds__(128, 2)
flash_attn(const __half* __restrict__ Q, const __half* __restrict__ Kg,
           const __half* __restrict__ Vg, __half* __restrict__ O)
{
    extern __shared__ __half fsm[];

    const int tid  = threadIdx.x;
    const int wid  = tid >> 5;
    const int lane = tid & 31;
    const int g    = lane >> 2;
    const int tg   = lane & 3;
    const int mwo  = wid * 32;

    const int grp  = lane >> 3;
    const int l7   = lane & 7;
    const int rowo = (grp & 1) * 8 + l7;
    const int colo = (grp >> 1);

    const int bh = blockIdx.y;
    const int b  = bh / HEADS, h = bh - b * HEADS;
    const long qoff  = ((long)b * CTX + blockIdx.x * 128) * INNER + h * HD;
    const long kvoff = (long)b * CTX * INNER + h * HD;

    const uint32_t smbase = smem_u32(fsm);
    const uint32_t lmoff  = (uint32_t)(rowo * FROW + colo * 8) * 2;
    const uint32_t VOFF   = 64 * FROW * 2;                    // bytes
    const uint32_t vloff  = (uint32_t)((lane & 15) * FROW + 64) * 2;  // ones col frag

    // ---- ones into V padding cols 64..71 of all 3 stages ----
    {
        const __half2 one2 = __floats2half2_rn(1.f, 1.f);
        #pragma unroll
        for (int i = 0; i < 6; i++) {
            int idx = tid + 128 * i;                  // 768 = 3*64*4
            int st = idx >> 8, rem = idx & 255;
            int row = rem >> 2, c = rem & 3;
            *(__half2*)(fsm + st * FSTAGE + 64 * FROW + row * FROW + 64 + c * 2) = one2;
        }
    }

    // ---- Q fragments direct from gmem ----
    uint32_t qf[2][4][4];
    #pragma unroll
    for (int mg = 0; mg < 2; mg++) {
        const __half* q0 = Q + qoff + (long)(mwo + mg * 16 + g) * INNER + 2 * tg;
        const __half* q8 = q0 + 8 * INNER;
        #pragma unroll
        for (int kk = 0; kk < 4; kk++) {
            qf[mg][kk][0] = *(const uint32_t*)(q0 + 16 * kk);
            qf[mg][kk][1] = *(const uint32_t*)(q8 + 16 * kk);
            qf[mg][kk][2] = *(const uint32_t*)(q0 + 16 * kk + 8);
            qf[mg][kk][3] = *(const uint32_t*)(q8 + 16 * kk + 8);
        }
    }

    float m_r[2][2], acc_o[2][8][4], acc_l[2][4];
    #pragma unroll
    for (int mg = 0; mg < 2; mg++) {
        m_r[mg][0] = m_r[mg][1] = -1e30f;
        #pragma unroll
        for (int c = 0; c < 4; c++) acc_l[mg][c] = 0.f;
        #pragma unroll
        for (int nt = 0; nt < 8; nt++)
            #pragma unroll
            for (int c = 0; c < 4; c++) acc_o[mg][nt][c] = 0.f;
    }

    const __half* kp[4]; const __half* vp[4]; uint32_t soff[4];
    #pragma unroll
    for (int i = 0; i < 4; i++) {
        int idx = tid + 128 * i;
        int row = idx >> 3, c = idx & 7;
        kp[i] = Kg + kvoff + (long)row * INNER + c * 8;
        vp[i] = Vg + kvoff + (long)row * INNER + c * 8;
        soff[i] = (uint32_t)(row * FROW + c * 8) * 2;
    }

#define FCOPY(ST, IT)                                                       \
    {                                                                       \
        const uint32_t sb = smbase + (uint32_t)(ST) * (FSTAGE * 2);         \
        const long go = (long)(IT) * 64 * INNER;                            \
        _Pragma("unroll")                                                   \
        for (int i = 0; i < 4; i++) {                                       \
            cp16(sb + soff[i], kp[i] + go);                                 \
            cp16(sb + VOFF + soff[i], vp[i] + go);                          \
        }                                                                   \
    }

    FCOPY(0, 0); CP_COMMIT();
    FCOPY(1, 1); CP_COMMIT();

    for (int it = 0; it < NIT; it++) {
        CP_WAIT1();
        __syncthreads();
        const int st = it % 3;
        const uint32_t stb = smbase + (uint32_t)st * (FSTAGE * 2);
        const uint32_t kb = stb + lmoff;
        const uint32_t vb = stb + VOFF + lmoff;
        const uint32_t vl = stb + VOFF + vloff;

        // ---- S = Q @ K^T ----
        float acc_s[2][8][4];
        #pragma unroll
        for (int mg = 0; mg < 2; mg++)
            #pragma unroll
            for (int nt = 0; nt < 8; nt++)
                #pragma unroll
                for (int c = 0; c < 4; c++) acc_s[mg][nt][c] = 0.f;
        #pragma unroll
        for (int kk = 0; kk < 4; kk++) {
            #pragma unroll
            for (int j = 0; j < 4; j++) {
                uint32_t r[4];
                ldm_x4(r, kb + (uint32_t)(j * 16 * FROW) * 2 + kk * 32);
                uint32_t b0[2] = {r[0], r[2]};
                uint32_t b1[2] = {r[1], r[3]};
                mma_f16(acc_s[0][2*j],     qf[0][kk], b0);
                mma_f16(acc_s[0][2*j + 1], qf[0][kk], b1);
                mma_f16(acc_s[1][2*j],     qf[1][kk], b0);
                mma_f16(acc_s[1][2*j + 1], qf[1][kk], b1);
            }
        }

        // ---- online softmax: P frags via f16x2 ex2; no scalar sums ----
        uint32_t pf[2][4][4];
        #pragma unroll
        for (int mg = 0; mg < 2; mg++) {
            #pragma unroll
            for (int r = 0; r < 2; r++) {
                float mx = -1e30f;
                #pragma unroll
                for (int nt = 0; nt < 8; nt++)
                    mx = fmaxf(mx, fmaxf(acc_s[mg][nt][2 * r], acc_s[mg][nt][2 * r + 1]));
                mx = fmaxf(mx, __shfl_xor_sync(0xffffffffu, mx, 1));
                mx = fmaxf(mx, __shfl_xor_sync(0xffffffffu, mx, 2));
                float mn = fmaxf(m_r[mg][r], mx);
                float alpha = exp2f((m_r[mg][r] - mn) * SCL);
                m_r[mg][r] = mn;
                #pragma unroll
                for (int nt = 0; nt < 8; nt++) {
                    float t0 = (acc_s[mg][nt][2 * r]     - mn) * SCL;
                    float t1 = (acc_s[mg][nt][2 * r + 1] - mn) * SCL;
                    pf[mg][nt >> 1][(nt & 1) * 2 + r] = ex2_h2(cvt_h2(t0, t1));
                }
                acc_l[mg][2 * r]     *= alpha;
                acc_l[mg][2 * r + 1] *= alpha;
                #pragma unroll
                for (int nt = 0; nt < 8; nt++) {
                    acc_o[mg][nt][2 * r]     *= alpha;
                    acc_o[mg][nt][2 * r + 1] *= alpha;
                }
            }
        }

        // ---- O += P @ V ; l += P @ ones (V padding col) ----
        #pragma unroll
        for (int kk = 0; kk < 4; kk++) {
            uint32_t bf[8][2];
            #pragma unroll
            for (int j = 0; j < 4; j++) {
                uint32_t r[4];
                ldm_x4_t(r, vb + (uint32_t)(kk * 16 * FROW) * 2 + j * 32);
                bf[2*j][0]     = r[0]; bf[2*j][1]     = r[1];
                bf[2*j + 1][0] = r[2]; bf[2*j + 1][1] = r[3];
            }
            uint32_t bl[2];
            ldm_x2_t(bl, vl + (uint32_t)(kk * 16 * FROW) * 2);
            mma_f16(acc_l[0], pf[0][kk], bl);
            mma_f16(acc_l[1], pf[1][kk], bl);
            #pragma unroll
            for (int mg = 0; mg < 2; mg++)
                #pragma unroll
                for (int nt = 0; nt < 8; nt++)
                    mma_f16(acc_o[mg][nt], pf[mg][kk], bf[nt]);
        }

        if (it + 2 < NIT) FCOPY((it + 2) % 3, it + 2);
        CP_COMMIT();
    }
#undef FCOPY

    // ---- write O = acc / l (fp16); l from mma ones-column ----
    #pragma unroll
    for (int mg = 0; mg < 2; mg++) {
        const float inv0 = 1.0f / acc_l[mg][0];
        const float inv1 = 1.0f / acc_l[mg][2];
        const long r0 = mwo + mg * 16 + g;
        #pragma unroll
        for (int nt = 0; nt < 8; nt++) {
            uint32_t o0 = cvt_h2(acc_o[mg][nt][0] * inv0, acc_o[mg][nt][1] * inv0);
            uint32_t o1 = cvt_h2(acc_o[mg][nt][2] * inv1, acc_o[mg][nt][3] * inv1);
            *(uint32_t*)(O + qoff + r0 * INNER + nt * 8 + 2 * tg) = o0;
            *(uint32_t*)(O + qoff + (r0 + 8) * INNER + nt * 8 + 2 * tg) = o1;
        }
    }
}

// ================= fp16 GEMM, ldmatrix + cp.async 3-stage, BM templated =================
#define BKD 32
#define AROW 40

template<int BMT, bool GELU_, bool HASBIAS, bool HASRES, bool OUTHALF>
__global__ void __launch_bounds__(256, 2)
mma_gemm(const __half* __restrict__ A, const __half* __restrict__ B,
         void* __restrict__ Cv, const float* __restrict__ bias,
         const float* __restrict__ residual,
         long sB1, long sC1, float alpha)
{
    constexpr int MT  = BMT / 32;
    constexpr int ACH = (BMT * 4) / 256;
    constexpr uint32_t DSTG = (uint32_t)(BMT + 128) * AROW * 2;
    constexpr uint32_t BOFF = (uint32_t)BMT * AROW * 2;

    extern __shared__ __half dsm[];

    const int zo = blockIdx.z;
    B += zo * sB1;
    const long coff = (long)zo * sC1;

    const int tid  = threadIdx.x;
    const int wid  = tid >> 5;
    const int lane = tid & 31;
    const int g    = lane >> 2;
    const int tg   = lane & 3;
    const int wm   = wid & 1;
    const int wn   = wid >> 1;
    const int mwo  = wm * (BMT / 2);
    const int nwo  = wn * 32;

    const int grp  = lane >> 3;
    const int l7   = lane & 7;
    const int rowo = (grp & 1) * 8 + l7;
    const int colo = (grp >> 1);

    const int m0 = blockIdx.y * BMT;
    const int n0 = blockIdx.x * 128;

    const uint32_t smbase = smem_u32(dsm);
    const uint32_t lma = (uint32_t)((mwo + rowo) * AROW + colo * 8) * 2;
    const uint32_t lmb = (uint32_t)((nwo + rowo) * AROW + colo * 8) * 2;

    const __half* ap[ACH]; uint32_t soffa[ACH];
    #pragma unroll
    for (int i = 0; i < ACH; i++) {
        int idx = tid + 256 * i;
        int row = idx >> 2, c = idx & 3;
        ap[i] = A + (long)(m0 + row) * DIMN + c * 8;
        soffa[i] = (uint32_t)(row * AROW + c * 8) * 2;
    }
    const __half* bp[2]; uint32_t soffb[2];
    #pragma unroll
    for (int i = 0; i < 2; i++) {
        int idx = tid + 256 * i;
        int row = idx >> 2, c = idx & 3;
        bp[i] = B + (long)(n0 + row) * DIMN + c * 8;
        soffb[i] = (uint32_t)(row * AROW + c * 8) * 2;
    }

#define DCOPY(ST, S)                                                        \
    {                                                                       \
        const uint32_t sb = smbase + (uint32_t)(ST) * DSTG;                 \
        const int ko = (S) * BKD;                                           \
        _Pragma("unroll")                                                   \
        for (int i = 0; i < ACH; i++) cp16(sb + soffa[i], ap[i] + ko);      \
        _Pragma("unroll")                                                   \
        for (int i = 0; i < 2; i++) cp16(sb + BOFF + soffb[i], bp[i] + ko); \
    }

    float acc[MT][4][4];
    #pragma unroll
    for (int i = 0; i < MT; i++)
        #pragma unroll
        for (int j = 0; j < 4; j++)
            #pragma unroll
            for (int k = 0; k < 4; k++) acc[i][j][k] = 0.f;

    DCOPY(0, 0); CP_COMMIT();
    DCOPY(1, 1); CP_COMMIT();

    const int ntiles = DIMN / BKD;             // 24
    for (int s = 0; s < ntiles; s++) {
        CP_WAIT1();
        __syncthreads();
        const int st = s % 3;
        const uint32_t ab = smbase + (uint32_t)st * DSTG + lma;
        const uint32_t bb = smbase + (uint32_t)st * DSTG + BOFF + lmb;

        #pragma unroll
        for (int half = 0; half < 2; half++) {
            const uint32_t koffb = half * 32;
            uint32_t af[MT][4];
            #pragma unroll
            for (int mt = 0; mt < MT; mt++)
                ldm_x4(af[mt], ab + (uint32_t)(mt * 16 * AROW) * 2 + koffb);
            uint32_t bf[4][2];
            #pragma unroll
            for (int j = 0; j < 2; j++) {
                uint32_t r[4];
                ldm_x4(r, bb + (uint32_t)(j * 16 * AROW) * 2 + koffb);
                bf[2*j][0]     = r[0]; bf[2*j][1]     = r[2];
                bf[2*j + 1][0] = r[1]; bf[2*j + 1][1] = r[3];
            }
            #pragma unroll
            for (int mt = 0; mt < MT; mt++)
                #pragma unroll
                for (int nt = 0; nt < 4; nt++)
                    mma_f16(acc[mt][nt], af[mt], bf[nt]);
        }

        if (s + 2 < ntiles) DCOPY((s + 2) % 3, s + 2);
        CP_COMMIT();
    }
#undef DCOPY

    // ---- epilogue ----
    #pragma unroll
    for (int mt = 0; mt < MT; mt++) {
        const long r0 = m0 + mwo + mt * 16 + g;
        const long r1 = r0 + 8;
        #pragma unroll
        for (int nt = 0; nt < 4; nt++) {
            const int cb = n0 + nwo + nt * 8 + 2 * tg;
            float2 v0, v1;
            v0.x = acc[mt][nt][0] * alpha; v0.y = acc[mt][nt][1] * alpha;
            v1.x = acc[mt][nt][2] * alpha; v1.y = acc[mt][nt][3] * alpha;
            if (HASBIAS) {
                float bx = bias[cb], by = bias[cb + 1];
                v0.x += bx; v0.y += by; v1.x += bx; v1.y += by;
            }
            if (GELU_) {
                v0.x = 0.5f * v0.x * (1.0f + erff(v0.x * 0.70710678118654752f));
                v0.y = 0.5f * v0.y * (1.0f + erff(v0.y * 0.70710678118654752f));
                v1.x = 0.5f * v1.x * (1.0f + erff(v1.x * 0.70710678118654752f));
                v1.y = 0.5f * v1.y * (1.0f + erff(v1.y * 0.70710678118654752f));
            }
            if (OUTHALF) {
                __half* Cp = (__half*)Cv + coff;
                *(uint32_t*)(Cp + r0 * DIMN + cb) = cvt_h2(v0.x, v0.y);
                *(uint32_t*)(Cp + r1 * DIMN + cb) = cvt_h2(v1.x, v1.y);
            } else {
                float* Cp = (float*)Cv + coff;
                if (HASRES) {
                    const float* Rp = residual + coff;
                    float2 q0 = *(const float2*)(Rp + r0 * DIMN + cb);
                    float2 q1 = *(const float2*)(Rp + r1 * DIMN + cb);
                    v0.x += q0.x; v0.y += q0.y; v1.x += q1.x; v1.y += q1.y;
                }
                *(float2*)(Cp + r0 * DIMN + cb) = v0;
                *(float2*)(Cp + r1 * DIMN + cb) = v1;
            }
        }
    }
}

template<int BMT, bool GELU_, bool HASBIAS, bool HASRES, bool OUTHALF>
static void launch_mm(const __half* A, const __half* B, void* C,
                      const float* bias, const float* res,
                      long sB1, long sC1, int nz, float alpha)
{
    constexpr int SMEM = 3 * (BMT + 128) * AROW * 2;
    cudaFuncSetAttribute((const void*)mma_gemm<BMT, GELU_, HASBIAS, HASRES, OUTHALF>,
                         cudaFuncAttributeMaxDynamicSharedMemorySize, SMEM);
    dim3 grid(DIMN / 128, MTOK / BMT, nz);
    mma_gemm<BMT, GELU_, HASBIAS, HASRES, OUTHALF><<<grid, 256, SMEM>>>(
        A, B, C, bias, res, sB1, sC1, alpha);
}

extern "C" void kernel_launch(void* const* d_in, const int* in_sizes, int n_in,
                              void* d_out, int out_size)
{
    const float* x     = (const float*)d_in[0];
    const float* pos   = (const float*)d_in[1];
    const float* ln1_g = (const float*)d_in[2];
    const float* ln1_b = (const float*)d_in[3];
    const float* Wq    = (const float*)d_in[4];
    const float* Wk    = (const float*)d_in[5];
    const float* Wv    = (const float*)d_in[6];
    const float* Wo    = (const float*)d_in[7];
    const float* ln2_g = (const float*)d_in[8];
    const float* ln2_b = (const float*)d_in[9];
    const float* W1    = (const float*)d_in[10];
    const float* b1    = (const float*)d_in[11];
    const float* W2    = (const float*)d_in[12];
    const float* b2    = (const float*)d_in[13];

    float  *gx;
    __half *gh, *gqkv, *go, *gf, *gwT;
    cudaGetSymbolAddress((void**)&gx,   g_x);
    cudaGetSymbolAddress((void**)&gh,   g_h);
    cudaGetSymbolAddress((void**)&gqkv, g_qkv);
    cudaGetSymbolAddress((void**)&go,   g_o);
    cudaGetSymbolAddress((void**)&gf,   g_f);
    cudaGetSymbolAddress((void**)&gwT,  g_wT);

    __half* gq = gqkv;
    __half* gk = gqkv + (long)MTOK * INNER;
    __half* gv = gqkv + 2L * MTOK * INNER;

    cudaFuncSetAttribute((const void*)flash_attn,
                         cudaFuncAttributeMaxDynamicSharedMemorySize, FLASH_SMEM);

    {
        dim3 grid(DIMN / 32, DIMN / 32, DEPTH * 6);
        transpose_w<<<grid, dim3(32, 8)>>>(Wq, Wk, Wv, Wo, W1, W2, gwT);
    }

    for (int l = 0; l < DEPTH; l++) {
        const __half* wqT = gwT + (long)(l * 6 + 0) * WSZ;
        const __half* woT = gwT + (long)(l * 6 + 3) * WSZ;
        const __half* w1T = gwT + (long)(l * 6 + 4) * WSZ;
        const __half* w2T = gwT + (long)(l * 6 + 5) * WSZ;
        const float* l1g = ln1_g + l * DIMN, *l1b = ln1_b + l * DIMN;
        const float* l2g = ln2_g + l * DIMN, *l2b = ln2_b + l * DIMN;
        const float* bb1 = b1 + l * DIMN,   *bb2 = b2 + l * DIMN;

        // --- attention
        if (l == 0) {
            layernorm_kernel<<<MTOK, 256>>>(x, gh, l1g, l1b, pos, gx);
        } else {
            layernorm_kernel<<<MTOK, 256>>>(gx, gh, l1g, l1b, nullptr, nullptr);
        }

        launch_mm<128, false, false, false, true>(
            gh, wqT, gqkv, nullptr, nullptr,
            WSZ, (long)MTOK * INNER, 3, 1.0f);

        flash_attn<<<dim3(CTX / 128, BATCH * HEADS), 128, FLASH_SMEM>>>(gq, gk, gv, go);

        launch_mm<64, false, false, true, false>(
            go, woT, gx, nullptr, gx, 0, 0, 1, 1.0f);

        // --- FFN
        layernorm_kernel<<<MTOK, 256>>>(gx, gh, l2g, l2b, nullptr, nullptr);

        launch_mm<64, true, true, false, true>(
            gh, w1T, gf, bb1, nullptr, 0, 0, 1, 1.0f);

        float* cout = (l == DEPTH - 1) ? (float*)d_out : gx;
        launch_mm<64, false, true, true, false>(
            gf, w2T, cout, bb2, gx, 0, 0, 1, 1.0f);
    }
}